// round 6
// baseline (speedup 1.0000x reference)
#include <cuda_runtime.h>
#include <cuda_bf16.h>
#include <cstdint>
#include <math.h>

// ---------------- problem constants ----------------
#define NTOT 4
#define CHN  256
#define HSZ  128
#define WSZ  128
#define HWSZ 16384
#define MTOT 65536
#define KTAP 9
#define EPSV 1e-5f
#define OMSP 128

typedef __nv_bfloat16 bf16;

// ---------------- scratch ----------------
__device__ bf16  g_xhi[MTOT*CHN], g_xlo[MTOT*CHN];
__device__ bf16  g_yhi[MTOT*CHN], g_ylo[MTOT*CHN];
__device__ bf16  g_shi[MTOT*CHN], g_slo[MTOT*CHN];
__device__ float g_v  [MTOT*CHN];
__device__ float g_om [MTOT*OMSP];
__device__ bf16  g_whi[896*CHN],  g_wlo[896*CHN];

// ---------------- helpers ----------------
__device__ __forceinline__ uint32_t smem_u32(const void* p){
    uint32_t a;
    asm("{ .reg .u64 t; cvta.to.shared.u64 t, %1; cvt.u32.u64 %0, t; }" : "=r"(a) : "l"(p));
    return a;
}
__device__ __forceinline__ void cpasync16(uint32_t dst, const void* src){
    asm volatile("cp.async.cg.shared.global [%0], [%1], 16;"
                 :: "r"(dst), "l"(src) : "memory");
}
#define CP_COMMIT()  asm volatile("cp.async.commit_group;" ::: "memory")
#define CP_WAIT(n)   asm volatile("cp.async.wait_group %0;" :: "n"(n) : "memory")

__device__ __forceinline__ void ldsm4(uint32_t& a0, uint32_t& a1, uint32_t& a2,
                                      uint32_t& a3, uint32_t addr){
    asm volatile("ldmatrix.sync.aligned.m8n8.x4.shared.b16 {%0,%1,%2,%3}, [%4];"
                 : "=r"(a0), "=r"(a1), "=r"(a2), "=r"(a3) : "r"(addr));
}
__device__ __forceinline__ void ldsm2(uint32_t& b0, uint32_t& b1, uint32_t addr){
    asm volatile("ldmatrix.sync.aligned.m8n8.x2.shared.b16 {%0,%1}, [%2];"
                 : "=r"(b0), "=r"(b1) : "r"(addr));
}
__device__ __forceinline__ void mma16816(float* c, const uint32_t* a,
                                         const uint32_t* b){
    asm volatile(
        "mma.sync.aligned.m16n8k16.row.col.f32.bf16.bf16.f32 "
        "{%0,%1,%2,%3}, {%4,%5,%6,%7}, {%8,%9}, {%0,%1,%2,%3};"
        : "+f"(c[0]), "+f"(c[1]), "+f"(c[2]), "+f"(c[3])
        : "r"(a[0]), "r"(a[1]), "r"(a[2]), "r"(a[3]), "r"(b[0]), "r"(b[1]));
}
__device__ __forceinline__ uint32_t pack2(bf16 a, bf16 b){
    __nv_bfloat162 h; h.x = a; h.y = b;
    return *reinterpret_cast<uint32_t*>(&h);
}
__device__ __forceinline__ uint32_t swz(int r, int c){
    return (uint32_t)(r * 64 + ((c ^ ((r >> 1) & 3)) * 16));
}

// ---------------------------------------------------------------------------
// Weight split (rows: 0-255 conv | 256-511 value | 512-639 offset | 640-895 out)
// ---------------------------------------------------------------------------
__global__ __launch_bounds__(256)
void w_split(const float* __restrict__ conv_w, const float* __restrict__ value_w,
             const float* __restrict__ offset_w, const float* __restrict__ out_w,
             bf16* __restrict__ whi, bf16* __restrict__ wlo)
{
    int idx = blockIdx.x * 256 + threadIdx.x;
    if (idx >= 896 * 256) return;
    int r = idx >> 8, c = idx & 255;
    float v = 0.f;
    if      (r < 256) v = conv_w[r * 256 + c];
    else if (r < 512) v = value_w[(r - 256) * 256 + c];
    else if (r < 640) { int rr = r - 512; if (rr < 112) v = offset_w[rr * 256 + c]; }
    else              v = out_w[(r - 640) * 256 + c];
    bf16 h = __float2bfloat16_rn(v);
    whi[idx] = h;
    wlo[idx] = __float2bfloat16_rn(v - __bfloat162float(h));
}

// ---------------------------------------------------------------------------
// x prepass: NCHW fp32 -> NHWC bf16 hi/lo
// ---------------------------------------------------------------------------
__global__ __launch_bounds__(256)
void x_split(const float* __restrict__ x, bf16* __restrict__ xhi,
             bf16* __restrict__ xlo)
{
    __shared__ float t[32][129];
    const int tid = threadIdx.x;
    const int n = blockIdx.z, c0 = blockIdx.y * 32, hw0 = blockIdx.x * 128;
    const float* src = x + ((size_t)n * 256 + c0) * HWSZ + hw0;
    #pragma unroll
    for (int i = 0; i < 16; i++) {
        int e = tid + i * 256;
        int c = e >> 7, p = e & 127;
        t[c][p] = src[(size_t)c * HWSZ + p];
    }
    __syncthreads();
    int p = tid >> 1, half = tid & 1;
    size_t base = ((size_t)n * HWSZ + hw0 + p) * 256 + c0 + half * 16;
    bf16 hi[16], lo[16];
    #pragma unroll
    for (int j = 0; j < 16; j++) {
        float a = t[half * 16 + j][p];
        bf16 h = __float2bfloat16_rn(a);
        hi[j] = h;
        lo[j] = __float2bfloat16_rn(a - __bfloat162float(h));
    }
    *reinterpret_cast<uint4*>(&xhi[base])     = *reinterpret_cast<uint4*>(&hi[0]);
    *reinterpret_cast<uint4*>(&xhi[base + 8]) = *reinterpret_cast<uint4*>(&hi[8]);
    *reinterpret_cast<uint4*>(&xlo[base])     = *reinterpret_cast<uint4*>(&lo[0]);
    *reinterpret_cast<uint4*>(&xlo[base + 8]) = *reinterpret_cast<uint4*>(&lo[8]);
}

// ---------------------------------------------------------------------------
// Full-N bf16-split GEMM: BM=128, BN=256 (all outputs), 512 threads, 3-stage.
// A read exactly once from DRAM. Warp grid 4(M)x4(N), warp tile 32x64.
//   EPI 0: +bias -> fp32 NHWC [p*256+o]
//   EPI 1: bn+silu -> bf16 hi/lo NHWC
//   EPI 2: bias+bn+silu -> fp32 NCHW via smem-staged coalesced stores
// smem/stage: A 16KB (hi+lo) + B 32KB = 48KB; 3 stages = 144KB.
// ---------------------------------------------------------------------------
template<int EPI>
__global__ __launch_bounds__(512, 1)
void gemm_full(const bf16* __restrict__ Ahi, const bf16* __restrict__ Alo,
               const bf16* __restrict__ Bhi, const bf16* __restrict__ Blo,
               const float* __restrict__ bias,
               const float* __restrict__ gamma, const float* __restrict__ beta,
               const float* __restrict__ mean,  const float* __restrict__ var,
               float* __restrict__ Co, bf16* __restrict__ CoHi,
               bf16* __restrict__ CoLo)
{
    extern __shared__ __align__(16) char dsm[];
    __shared__ float sSC[256], sSH[256];

    const int tid  = threadIdx.x;
    const int wid  = tid >> 5;
    const int lane = tid & 31;
    const int p0   = blockIdx.x * 128;

    const uint32_t sb = smem_u32(dsm);
    const int STG = 49152;

    if (tid < 256) {
        int o = tid;
        float sc = 1.f, sh = 0.f;
        if (EPI == 0) {
            sh = bias[o];
        } else if (EPI == 1) {
            float s_ = gamma[o] * rsqrtf(var[o] + EPSV);
            sc = s_; sh = beta[o] - mean[o] * s_;
        } else {
            float s_ = gamma[o] * rsqrtf(var[o] + EPSV);
            sc = s_; sh = (beta[o] - mean[o] * s_) + bias[o] * s_;
        }
        sSC[o] = sc; sSH[o] = sh;
    }

    auto load_stage = [&](int kt, int s) {
        const uint32_t st = sb + s * STG;
        {   // A: 128 rows x 4 chunks, hi+lo — 1 op each per thread
            int r = tid >> 2, c = tid & 3;
            size_t ao = (size_t)(p0 + r) * 256 + kt + c * 8;
            uint32_t d = swz(r, c);
            cpasync16(st + d,        Ahi + ao);
            cpasync16(st + 8192 + d, Alo + ao);
        }
        #pragma unroll
        for (int i = 0; i < 2; i++) {  // B: 256 rows x 4 chunks, hi+lo
            int e = tid + i * 512;
            int r = e >> 2, c = e & 3;
            size_t bo = (size_t)r * 256 + kt + c * 8;
            uint32_t d = swz(r, c);
            cpasync16(st + 16384 + d, Bhi + bo);
            cpasync16(st + 32768 + d, Blo + bo);
        }
        CP_COMMIT();
    };

    const int wm = (wid & 3) * 32;        // M offset (4 warps)
    const int wn = (wid >> 2) * 64;       // N offset (4 warps)

    float acc[2][8][4];
    #pragma unroll
    for (int i = 0; i < 2; i++)
        #pragma unroll
        for (int j = 0; j < 8; j++)
            #pragma unroll
            for (int q = 0; q < 4; q++) acc[i][j][q] = 0.f;

    load_stage(0, 0);
    load_stage(32, 1);

    #pragma unroll 1
    for (int st = 0; st < 8; st++) {
        const int s = st % 3;
        const uint32_t bs = sb + s * STG;
        if (st == 7) { CP_WAIT(0); } else { CP_WAIT(1); }
        __syncthreads();

        #pragma unroll
        for (int kk = 0; kk < 2; kk++) {
            const int c0 = kk * 2;
            uint32_t ah[2][4], al[2][4], bh[8][2], bl[8][2];
            #pragma unroll
            for (int mt = 0; mt < 2; mt++) {
                int rr = wm + mt * 16 + (lane & 15);
                int cc = c0 + (lane >> 4);
                uint32_t ad = swz(rr, cc);
                ldsm4(ah[mt][0], ah[mt][1], ah[mt][2], ah[mt][3], bs + ad);
                ldsm4(al[mt][0], al[mt][1], al[mt][2], al[mt][3], bs + 8192 + ad);
            }
            #pragma unroll
            for (int nt = 0; nt < 8; nt++) {
                int rr = wn + nt * 8 + (lane & 7);
                int cc = c0 + ((lane >> 3) & 1);
                uint32_t bd = swz(rr, cc);
                ldsm2(bh[nt][0], bh[nt][1], bs + 16384 + bd);
                ldsm2(bl[nt][0], bl[nt][1], bs + 32768 + bd);
            }
            #pragma unroll
            for (int mt = 0; mt < 2; mt++)
                #pragma unroll
                for (int nt = 0; nt < 8; nt++) {
                    mma16816(acc[mt][nt], ah[mt], bh[nt]);
                    mma16816(acc[mt][nt], ah[mt], bl[nt]);
                    mma16816(acc[mt][nt], al[mt], bh[nt]);
                }
        }
        if (st < 6) load_stage((st + 2) * 32, (st + 2) % 3);
    }

    // ---------------- epilogue ----------------
    const int qr = lane >> 2;
    const int qc = (lane & 3) * 2;

    if (EPI == 2) {
        // staged NCHW store: two rounds of 128 channels each
        float* sf = reinterpret_cast<float*>(dsm);
        const int n = p0 >> 14, hw0 = p0 & 16383;
        const int rsel = wn >> 7;             // which round this warp's cols are in
        const int obase = wn & 127;
        #pragma unroll 1
        for (int r = 0; r < 2; r++) {
            __syncthreads();
            if (rsel == r) {
                #pragma unroll
                for (int mt = 0; mt < 2; mt++)
                    #pragma unroll
                    for (int nt = 0; nt < 8; nt++) {
                        int og = wn + nt * 8 + qc;
                        int ol = obase + nt * 8 + qc;
                        float sc0 = sSC[og], sh0 = sSH[og];
                        float sc1 = sSC[og + 1], sh1 = sSH[og + 1];
                        #pragma unroll
                        for (int half = 0; half < 2; half++) {
                            int pl = wm + mt * 16 + qr + half * 8;
                            float v0 = acc[mt][nt][half * 2 + 0] * sc0 + sh0;
                            float v1 = acc[mt][nt][half * 2 + 1] * sc1 + sh1;
                            v0 = v0 / (1.f + expf(-v0));
                            v1 = v1 / (1.f + expf(-v1));
                            sf[ol * 132 + pl]       = v0;
                            sf[(ol + 1) * 132 + pl] = v1;
                        }
                    }
            }
            __syncthreads();
            #pragma unroll
            for (int i = 0; i < 8; i++) {
                int idx = tid + i * 512;
                int ol = idx >> 5, pq = (idx & 31) * 4;
                float4 t = *reinterpret_cast<float4*>(&sf[ol * 132 + pq]);
                *reinterpret_cast<float4*>(
                    &Co[(((size_t)n * 256 + r * 128 + ol) << 14) + hw0 + pq]) = t;
            }
        }
        return;
    }

    #pragma unroll
    for (int mt = 0; mt < 2; mt++) {
        #pragma unroll
        for (int nt = 0; nt < 8; nt++) {
            int o = wn + nt * 8 + qc;
            float sc0 = sSC[o],     sh0 = sSH[o];
            float sc1 = sSC[o + 1], sh1 = sSH[o + 1];
            #pragma unroll
            for (int half = 0; half < 2; half++) {
                int p = p0 + wm + mt * 16 + qr + half * 8;
                float v0 = acc[mt][nt][half * 2 + 0] * sc0 + sh0;
                float v1 = acc[mt][nt][half * 2 + 1] * sc1 + sh1;
                if (EPI == 1) {
                    v0 = v0 / (1.f + expf(-v0));
                    v1 = v1 / (1.f + expf(-v1));
                    bf16 h0 = __float2bfloat16_rn(v0);
                    bf16 h1 = __float2bfloat16_rn(v1);
                    bf16 l0 = __float2bfloat16_rn(v0 - __bfloat162float(h0));
                    bf16 l1 = __float2bfloat16_rn(v1 - __bfloat162float(h1));
                    size_t ob = (size_t)p * 256 + o;
                    *reinterpret_cast<uint32_t*>(&CoHi[ob]) = pack2(h0, h1);
                    *reinterpret_cast<uint32_t*>(&CoLo[ob]) = pack2(l0, l1);
                } else {
                    *reinterpret_cast<float2*>(&Co[(size_t)p * 256 + o]) =
                        make_float2(v0, v1);
                }
            }
        }
    }
}

// ---------------------------------------------------------------------------
// om GEMM: BM=128, BN=128 (112 real), 256 threads, 3-stage (single n-block).
// ---------------------------------------------------------------------------
__global__ __launch_bounds__(256, 2)
void gemm_om(const bf16* __restrict__ Ahi, const bf16* __restrict__ Alo,
             const bf16* __restrict__ Bhi, const bf16* __restrict__ Blo,
             const float* __restrict__ bias, int biasN,
             float* __restrict__ Co)
{
    extern __shared__ __align__(16) char dsm[];
    __shared__ float sSH[128];

    const int tid  = threadIdx.x;
    const int wid  = tid >> 5;
    const int lane = tid & 31;
    const int p0   = blockIdx.x * 128;

    const uint32_t sb = smem_u32(dsm);
    auto AHI = [&](int s){ return sb + s * 32768 + 0;     };
    auto ALO = [&](int s){ return sb + s * 32768 + 8192;  };
    auto BHI = [&](int s){ return sb + s * 32768 + 16384; };
    auto BLO = [&](int s){ return sb + s * 32768 + 24576; };

    if (tid < 128) sSH[tid] = (tid < biasN) ? bias[tid] : 0.f;

    auto load_stage = [&](int kt, int s) {
        #pragma unroll
        for (int i = 0; i < 2; i++) {
            int e = tid + i * 256;
            int r = e >> 2, c = e & 3;
            size_t ao = (size_t)(p0 + r) * 256 + kt + c * 8;
            size_t bo = (size_t)r * 256 + kt + c * 8;
            uint32_t d = swz(r, c);
            cpasync16(AHI(s) + d, Ahi + ao);
            cpasync16(ALO(s) + d, Alo + ao);
            cpasync16(BHI(s) + d, Bhi + bo);
            cpasync16(BLO(s) + d, Blo + bo);
        }
        CP_COMMIT();
    };

    const int wm = (wid >> 2) * 64;
    const int wn = (wid & 3) * 32;

    float acc[4][4][4];
    #pragma unroll
    for (int i = 0; i < 4; i++)
        #pragma unroll
        for (int j = 0; j < 4; j++)
            #pragma unroll
            for (int q = 0; q < 4; q++) acc[i][j][q] = 0.f;

    load_stage(0, 0);
    load_stage(32, 1);

    #pragma unroll 1
    for (int st = 0; st < 8; st++) {
        const int s = st % 3;
        if (st == 7) { CP_WAIT(0); } else { CP_WAIT(1); }
        __syncthreads();
        #pragma unroll
        for (int kk = 0; kk < 2; kk++) {
            const int c0 = kk * 2;
            uint32_t ah[4][4], al[4][4], bh[4][2], bl[4][2];
            #pragma unroll
            for (int mt = 0; mt < 4; mt++) {
                int rr = wm + mt * 16 + (lane & 15);
                int cc = c0 + (lane >> 4);
                uint32_t ad = swz(rr, cc);
                ldsm4(ah[mt][0], ah[mt][1], ah[mt][2], ah[mt][3], AHI(s) + ad);
                ldsm4(al[mt][0], al[mt][1], al[mt][2], al[mt][3], ALO(s) + ad);
            }
            #pragma unroll
            for (int nt = 0; nt < 4; nt++) {
                int rr = wn + nt * 8 + (lane & 7);
                int cc = c0 + ((lane >> 3) & 1);
                uint32_t bd = swz(rr, cc);
                ldsm2(bh[nt][0], bh[nt][1], BHI(s) + bd);
                ldsm2(bl[nt][0], bl[nt][1], BLO(s) + bd);
            }
            #pragma unroll
            for (int mt = 0; mt < 4; mt++)
                #pragma unroll
                for (int nt = 0; nt < 4; nt++) {
                    mma16816(acc[mt][nt], ah[mt], bh[nt]);
                    mma16816(acc[mt][nt], ah[mt], bl[nt]);
                    mma16816(acc[mt][nt], al[mt], bh[nt]);
                }
        }
        if (st < 6) load_stage((st + 2) * 32, (st + 2) % 3);
    }

    const int qr = lane >> 2;
    const int qc = (lane & 3) * 2;
    #pragma unroll
    for (int mt = 0; mt < 4; mt++) {
        #pragma unroll
        for (int nt = 0; nt < 4; nt++) {
            int o = wn + nt * 8 + qc;
            float sh0 = sSH[o], sh1 = sSH[o + 1];
            #pragma unroll
            for (int half = 0; half < 2; half++) {
                int p = p0 + wm + mt * 16 + qr + half * 8;
                float v0 = acc[mt][nt][half * 2 + 0] + sh0;
                float v1 = acc[mt][nt][half * 2 + 1] + sh1;
                *reinterpret_cast<float2*>(&Co[(size_t)p * OMSP + o]) =
                    make_float2(v0, v1);
            }
        }
    }
}

// ---------------------------------------------------------------------------
// DCNv4 sampling: warp = (pixel, 2 groups); lane -> 4 channels via float4.
// ---------------------------------------------------------------------------
__global__ __launch_bounds__(256)
void dcn_sample(const float* __restrict__ v, const float* __restrict__ om,
                bf16* __restrict__ shi, bf16* __restrict__ slo)
{
    int wrp  = (blockIdx.x * 256 + threadIdx.x) >> 5;
    int lane = threadIdx.x & 31;
    int p = wrp >> 1;
    int g = ((wrp & 1) << 1) + (lane >> 4);
    int laneg = lane & 15;
    int n = p >> 14;
    int hw = p & (HWSZ - 1);
    int h = hw >> 7, w = hw & 127;

    const float* op = om + (size_t)p * OMSP + g * 27;
    const int cb = g * 64 + laneg * 4;
    const int nb = n << 14;

    float a0 = 0.f, a1 = 0.f, a2 = 0.f, a3 = 0.f;
    #pragma unroll
    for (int k = 0; k < KTAP; k++) {
        float ow = op[2 * k];
        float oh = op[2 * k + 1];
        float mk = op[18 + k];
        float lh = (float)(h + k / 3 - 1) + oh;
        float lw = (float)(w + k % 3 - 1) + ow;
        float fh = floorf(lh), fw = floorf(lw);
        int h0 = (int)fh, w0 = (int)fw;
        float dh = lh - fh, dw = lw - fw;
        float w00 = (1.f - dh) * (1.f - dw) * mk;
        float w01 = (1.f - dh) * dw * mk;
        float w10 = dh * (1.f - dw) * mk;
        float w11 = dh * dw * mk;
        bool hv0 = (h0 >= 0)     && (h0 < HSZ);
        bool hv1 = (h0 + 1 >= 0) && (h0 + 1 < HSZ);
        bool wv0 = (w0 >= 0)     && (w0 < WSZ);
        bool wv1 = (w0 + 1 >= 0) && (w0 + 1 < WSZ);
        int r0 = (nb + h0 * WSZ + w0) << 8;
        if (hv0 && wv0) { float4 q = *reinterpret_cast<const float4*>(v + r0 + cb);
                          a0 += w00*q.x; a1 += w00*q.y; a2 += w00*q.z; a3 += w00*q.w; }
        if (hv0 && wv1) { float4 q = *reinterpret_cast<const float4*>(v + r0 + 256 + cb);
                          a0 += w01*q.x; a1 += w01*q.y; a2 += w01*q.z; a3 += w01*q.w; }
        if (hv1 && wv0) { float4 q = *reinterpret_cast<const float4*>(v + r0 + (WSZ << 8) + cb);
                          a0 += w10*q.x; a1 += w10*q.y; a2 += w10*q.z; a3 += w10*q.w; }
        if (hv1 && wv1) { float4 q = *reinterpret_cast<const float4*>(v + r0 + ((WSZ + 1) << 8) + cb);
                          a0 += w11*q.x; a1 += w11*q.y; a2 += w11*q.z; a3 += w11*q.w; }
    }
    bf16 h0 = __float2bfloat16_rn(a0), h1 = __float2bfloat16_rn(a1);
    bf16 h2 = __float2bfloat16_rn(a2), h3 = __float2bfloat16_rn(a3);
    uint2 hv, lv;
    hv.x = pack2(h0, h1); hv.y = pack2(h2, h3);
    lv.x = pack2(__float2bfloat16_rn(a0 - __bfloat162float(h0)),
                 __float2bfloat16_rn(a1 - __bfloat162float(h1)));
    lv.y = pack2(__float2bfloat16_rn(a2 - __bfloat162float(h2)),
                 __float2bfloat16_rn(a3 - __bfloat162float(h3)));
    size_t ob = (size_t)p * 256 + cb;
    *reinterpret_cast<uint2*>(&shi[ob]) = hv;
    *reinterpret_cast<uint2*>(&slo[ob]) = lv;
}

// ---------------------------------------------------------------------------
extern "C" void kernel_launch(void* const* d_in, const int* in_sizes, int n_in,
                              void* d_out, int out_size)
{
    const float* x        = (const float*)d_in[0];
    const float* conv_w   = (const float*)d_in[1];
    const float* bn1_g    = (const float*)d_in[2];
    const float* bn1_b    = (const float*)d_in[3];
    const float* bn1_m    = (const float*)d_in[4];
    const float* bn1_v    = (const float*)d_in[5];
    const float* value_w  = (const float*)d_in[6];
    const float* value_b  = (const float*)d_in[7];
    const float* offset_w = (const float*)d_in[8];
    const float* offset_b = (const float*)d_in[9];
    const float* out_w    = (const float*)d_in[10];
    const float* out_b    = (const float*)d_in[11];
    const float* bn2_g    = (const float*)d_in[12];
    const float* bn2_b    = (const float*)d_in[13];
    const float* bn2_m    = (const float*)d_in[14];
    const float* bn2_v    = (const float*)d_in[15];

    bf16 *xhi, *xlo, *yhi, *ylo, *shi, *slo, *whi, *wlo;
    float *v, *omp;
    cudaGetSymbolAddress((void**)&xhi, g_xhi);
    cudaGetSymbolAddress((void**)&xlo, g_xlo);
    cudaGetSymbolAddress((void**)&yhi, g_yhi);
    cudaGetSymbolAddress((void**)&ylo, g_ylo);
    cudaGetSymbolAddress((void**)&shi, g_shi);
    cudaGetSymbolAddress((void**)&slo, g_slo);
    cudaGetSymbolAddress((void**)&whi, g_whi);
    cudaGetSymbolAddress((void**)&wlo, g_wlo);
    cudaGetSymbolAddress((void**)&v,   g_v);
    cudaGetSymbolAddress((void**)&omp, g_om);

    const int smemF = 3 * 49152;   // 144KB full-N
    const int smemO = 3 * 32768;   // 96KB om
    cudaFuncSetAttribute(gemm_full<0>, cudaFuncAttributeMaxDynamicSharedMemorySize, smemF);
    cudaFuncSetAttribute(gemm_full<1>, cudaFuncAttributeMaxDynamicSharedMemorySize, smemF);
    cudaFuncSetAttribute(gemm_full<2>, cudaFuncAttributeMaxDynamicSharedMemorySize, smemF);
    cudaFuncSetAttribute(gemm_om,      cudaFuncAttributeMaxDynamicSharedMemorySize, smemO);

    // prepasses
    w_split<<<896, 256>>>(conv_w, value_w, offset_w, out_w, whi, wlo);
    x_split<<<dim3(128, 8, 4), 256>>>(x, xhi, xlo);

    const int MT = MTOT / 128;   // 512

    // 1) y = silu(bn1(x @ conv_w^T))     -> y hi/lo
    gemm_full<1><<<MT, 512, smemF>>>(
        xhi, xlo, whi, wlo, nullptr,
        bn1_g, bn1_b, bn1_m, bn1_v, nullptr, yhi, ylo);
    // 2a) v = y @ value_w^T + value_b    -> fp32 NHWC
    gemm_full<0><<<MT, 512, smemF>>>(
        yhi, ylo, whi + 256*256, wlo + 256*256, value_b,
        nullptr, nullptr, nullptr, nullptr, v, nullptr, nullptr);
    // 2b) om = y @ offset_w^T + offset_b
    gemm_om<<<MT, 256, smemO>>>(
        yhi, ylo, whi + 512*256, wlo + 512*256, offset_b, 112, omp);
    // 3) deformable sampling -> s hi/lo
    dcn_sample<<<MTOT / 4, 256>>>(v, omp, shi, slo);
    // 4) out = silu(bn2(s @ out_w^T + out_b)) -> NCHW fp32 (staged stores)
    gemm_full<2><<<MT, 512, smemF>>>(
        shi, slo, whi + 640*256, wlo + 640*256, out_b,
        bn2_g, bn2_b, bn2_m, bn2_v, (float*)d_out, nullptr, nullptr);
}

// round 7
// speedup vs baseline: 1.1260x; 1.1260x over previous
#include <cuda_runtime.h>
#include <cuda_bf16.h>
#include <cstdint>
#include <math.h>

// ---------------- problem constants ----------------
#define NTOT 4
#define CHN  256
#define HSZ  128
#define WSZ  128
#define HWSZ 16384
#define MTOT 65536
#define KTAP 9
#define EPSV 1e-5f
#define OMSP 128

typedef __nv_bfloat16 bf16;

// ---------------- scratch ----------------
__device__ bf16  g_xhi[MTOT*CHN], g_xlo[MTOT*CHN];
__device__ bf16  g_yhi[MTOT*CHN], g_ylo[MTOT*CHN];
__device__ bf16  g_shi[MTOT*CHN], g_slo[MTOT*CHN];
__device__ float g_v  [MTOT*CHN];
__device__ float g_om [MTOT*OMSP];
__device__ bf16  g_whi[896*CHN],  g_wlo[896*CHN];

// ---------------- helpers ----------------
__device__ __forceinline__ uint32_t smem_u32(const void* p){
    uint32_t a;
    asm("{ .reg .u64 t; cvta.to.shared.u64 t, %1; cvt.u32.u64 %0, t; }" : "=r"(a) : "l"(p));
    return a;
}
__device__ __forceinline__ void cpasync16(uint32_t dst, const void* src){
    asm volatile("cp.async.cg.shared.global [%0], [%1], 16;"
                 :: "r"(dst), "l"(src) : "memory");
}
#define CP_COMMIT()  asm volatile("cp.async.commit_group;" ::: "memory")
#define CP_WAIT(n)   asm volatile("cp.async.wait_group %0;" :: "n"(n) : "memory")

__device__ __forceinline__ void ldsm4(uint32_t& a0, uint32_t& a1, uint32_t& a2,
                                      uint32_t& a3, uint32_t addr){
    asm volatile("ldmatrix.sync.aligned.m8n8.x4.shared.b16 {%0,%1,%2,%3}, [%4];"
                 : "=r"(a0), "=r"(a1), "=r"(a2), "=r"(a3) : "r"(addr));
}
__device__ __forceinline__ void ldsm2(uint32_t& b0, uint32_t& b1, uint32_t addr){
    asm volatile("ldmatrix.sync.aligned.m8n8.x2.shared.b16 {%0,%1}, [%2];"
                 : "=r"(b0), "=r"(b1) : "r"(addr));
}
__device__ __forceinline__ void mma16816(float* c, const uint32_t* a,
                                         const uint32_t* b){
    asm volatile(
        "mma.sync.aligned.m16n8k16.row.col.f32.bf16.bf16.f32 "
        "{%0,%1,%2,%3}, {%4,%5,%6,%7}, {%8,%9}, {%0,%1,%2,%3};"
        : "+f"(c[0]), "+f"(c[1]), "+f"(c[2]), "+f"(c[3])
        : "r"(a[0]), "r"(a[1]), "r"(a[2]), "r"(a[3]), "r"(b[0]), "r"(b[1]));
}
__device__ __forceinline__ uint32_t pack2(bf16 a, bf16 b){
    __nv_bfloat162 h; h.x = a; h.y = b;
    return *reinterpret_cast<uint32_t*>(&h);
}
__device__ __forceinline__ uint32_t swz(int r, int c){
    return (uint32_t)(r * 64 + ((c ^ ((r >> 1) & 3)) * 16));
}

// ---------------------------------------------------------------------------
// Weight split (rows: 0-255 conv | 256-511 value | 512-639 offset | 640-895 out)
// ---------------------------------------------------------------------------
__global__ __launch_bounds__(256)
void w_split(const float* __restrict__ conv_w, const float* __restrict__ value_w,
             const float* __restrict__ offset_w, const float* __restrict__ out_w,
             bf16* __restrict__ whi, bf16* __restrict__ wlo)
{
    int idx = blockIdx.x * 256 + threadIdx.x;
    if (idx >= 896 * 256) return;
    int r = idx >> 8, c = idx & 255;
    float v = 0.f;
    if      (r < 256) v = conv_w[r * 256 + c];
    else if (r < 512) v = value_w[(r - 256) * 256 + c];
    else if (r < 640) { int rr = r - 512; if (rr < 112) v = offset_w[rr * 256 + c]; }
    else              v = out_w[(r - 640) * 256 + c];
    bf16 h = __float2bfloat16_rn(v);
    whi[idx] = h;
    wlo[idx] = __float2bfloat16_rn(v - __bfloat162float(h));
}

// ---------------------------------------------------------------------------
// x prepass: NCHW fp32 -> NHWC bf16 hi/lo
// ---------------------------------------------------------------------------
__global__ __launch_bounds__(256)
void x_split(const float* __restrict__ x, bf16* __restrict__ xhi,
             bf16* __restrict__ xlo)
{
    __shared__ float t[32][129];
    const int tid = threadIdx.x;
    const int n = blockIdx.z, c0 = blockIdx.y * 32, hw0 = blockIdx.x * 128;
    const float* src = x + ((size_t)n * 256 + c0) * HWSZ + hw0;
    #pragma unroll
    for (int i = 0; i < 16; i++) {
        int e = tid + i * 256;
        int c = e >> 7, p = e & 127;
        t[c][p] = src[(size_t)c * HWSZ + p];
    }
    __syncthreads();
    int p = tid >> 1, half = tid & 1;
    size_t base = ((size_t)n * HWSZ + hw0 + p) * 256 + c0 + half * 16;
    bf16 hi[16], lo[16];
    #pragma unroll
    for (int j = 0; j < 16; j++) {
        float a = t[half * 16 + j][p];
        bf16 h = __float2bfloat16_rn(a);
        hi[j] = h;
        lo[j] = __float2bfloat16_rn(a - __bfloat162float(h));
    }
    *reinterpret_cast<uint4*>(&xhi[base])     = *reinterpret_cast<uint4*>(&hi[0]);
    *reinterpret_cast<uint4*>(&xhi[base + 8]) = *reinterpret_cast<uint4*>(&hi[8]);
    *reinterpret_cast<uint4*>(&xlo[base])     = *reinterpret_cast<uint4*>(&lo[0]);
    *reinterpret_cast<uint4*>(&xlo[base + 8]) = *reinterpret_cast<uint4*>(&lo[8]);
}

// ---------------------------------------------------------------------------
// bf16-split HMMA GEMM, 3-stage cp.async pipeline; loads issued right after
// the stage barrier (max latency cover).
//   EPI 1: bn+silu -> bf16 hi/lo NHWC (y)
//   EPI 2: bias+bn+silu -> fp32 NCHW via smem-staged coalesced stores
//   EPI 3: fused v+om: o<256 -> +value_b into Co(v); o>=256 -> +offset_b Co2(om)
// Tile BM=128, BN=128, 8 warps (2x4), warp 64x32, 2 CTAs/SM.
// ---------------------------------------------------------------------------
template<int EPI>
__global__ __launch_bounds__(256, 2)
void gemm_bf16(const bf16* __restrict__ Ahi, const bf16* __restrict__ Alo,
               const bf16* __restrict__ Bhi, const bf16* __restrict__ Blo,
               const float* __restrict__ bias, const float* __restrict__ bias2,
               const float* __restrict__ gamma, const float* __restrict__ beta,
               const float* __restrict__ mean,  const float* __restrict__ var,
               float* __restrict__ Co, float* __restrict__ Co2,
               bf16* __restrict__ CoHi, bf16* __restrict__ CoLo)
{
    extern __shared__ __align__(16) char dsm[];
    __shared__ float sSC[128], sSH[128];

    const int tid  = threadIdx.x;
    const int wid  = tid >> 5;
    const int lane = tid & 31;
    const int p0   = blockIdx.x * 128;
    const int n0   = blockIdx.y * 128;

    const uint32_t sb = smem_u32(dsm);
    auto AHI = [&](int s){ return sb + s * 32768 + 0;     };
    auto ALO = [&](int s){ return sb + s * 32768 + 8192;  };
    auto BHI = [&](int s){ return sb + s * 32768 + 16384; };
    auto BLO = [&](int s){ return sb + s * 32768 + 24576; };

    if (tid < 128) {
        int o = n0 + tid;
        float sc = 1.f, sh = 0.f;
        if (EPI == 1) {
            float s_ = gamma[o] * rsqrtf(var[o] + EPSV);
            sc = s_; sh = beta[o] - mean[o] * s_;
        } else if (EPI == 2) {
            float s_ = gamma[o] * rsqrtf(var[o] + EPSV);
            sc = s_; sh = (beta[o] - mean[o] * s_) + bias[o] * s_;
        } else { // EPI 3
            if (o < 256)            sh = bias[o];
            else if (o - 256 < 112) sh = bias2[o - 256];
        }
        sSC[tid] = sc; sSH[tid] = sh;
    }

    auto load_stage = [&](int kt, int s) {
        #pragma unroll
        for (int i = 0; i < 2; i++) {
            int e = tid + i * 256;
            int r = e >> 2, c = e & 3;
            size_t ao = (size_t)(p0 + r) * 256 + kt + c * 8;
            size_t bo = (size_t)(n0 + r) * 256 + kt + c * 8;
            uint32_t d = swz(r, c);
            cpasync16(AHI(s) + d, Ahi + ao);
            cpasync16(ALO(s) + d, Alo + ao);
            cpasync16(BHI(s) + d, Bhi + bo);
            cpasync16(BLO(s) + d, Blo + bo);
        }
        CP_COMMIT();
    };

    const int wm = (wid >> 2) * 64;
    const int wn = (wid & 3) * 32;

    float acc[4][4][4];
    #pragma unroll
    for (int i = 0; i < 4; i++)
        #pragma unroll
        for (int j = 0; j < 4; j++)
            #pragma unroll
            for (int q = 0; q < 4; q++) acc[i][j][q] = 0.f;

    load_stage(0, 0);
    load_stage(32, 1);

    #pragma unroll 1
    for (int st = 0; st < 8; st++) {
        const int s = st % 3;
        if (st == 7) { CP_WAIT(0); } else { CP_WAIT(1); }
        __syncthreads();
        if (st < 6) load_stage((st + 2) * 32, (st + 2) % 3);   // early issue

        #pragma unroll
        for (int kk = 0; kk < 2; kk++) {
            const int c0 = kk * 2;
            uint32_t ah[4][4], al[4][4], bh[4][2], bl[4][2];
            #pragma unroll
            for (int mt = 0; mt < 4; mt++) {
                int rr = wm + mt * 16 + (lane & 15);
                int cc = c0 + (lane >> 4);
                uint32_t ad = swz(rr, cc);
                ldsm4(ah[mt][0], ah[mt][1], ah[mt][2], ah[mt][3], AHI(s) + ad);
                ldsm4(al[mt][0], al[mt][1], al[mt][2], al[mt][3], ALO(s) + ad);
            }
            #pragma unroll
            for (int nt = 0; nt < 4; nt++) {
                int rr = wn + nt * 8 + (lane & 7);
                int cc = c0 + ((lane >> 3) & 1);
                uint32_t bd = swz(rr, cc);
                ldsm2(bh[nt][0], bh[nt][1], BHI(s) + bd);
                ldsm2(bl[nt][0], bl[nt][1], BLO(s) + bd);
            }
            #pragma unroll
            for (int mt = 0; mt < 4; mt++)
                #pragma unroll
                for (int nt = 0; nt < 4; nt++) {
                    mma16816(acc[mt][nt], ah[mt], bh[nt]);
                    mma16816(acc[mt][nt], ah[mt], bl[nt]);
                    mma16816(acc[mt][nt], al[mt], bh[nt]);
                }
        }
    }

    // ---------------- epilogue ----------------
    const int qr = lane >> 2;
    const int qc = (lane & 3) * 2;

    if (EPI == 2) {
        // Stage the 128ch x 128px tile in smem, then coalesced NCHW stores.
        __syncthreads();                  // all LDSM of stage buffers done
        float* sf = reinterpret_cast<float*>(dsm);   // 128*132 floats = 67.6KB
        const int n = p0 >> 14, hw0 = p0 & 16383;
        #pragma unroll
        for (int mt = 0; mt < 4; mt++)
            #pragma unroll
            for (int nt = 0; nt < 4; nt++) {
                int ol = wn + nt * 8 + qc;
                float sc0 = sSC[ol],     sh0 = sSH[ol];
                float sc1 = sSC[ol + 1], sh1 = sSH[ol + 1];
                #pragma unroll
                for (int half = 0; half < 2; half++) {
                    int pl = wm + mt * 16 + qr + half * 8;
                    float v0 = acc[mt][nt][half * 2 + 0] * sc0 + sh0;
                    float v1 = acc[mt][nt][half * 2 + 1] * sc1 + sh1;
                    v0 = v0 / (1.f + expf(-v0));
                    v1 = v1 / (1.f + expf(-v1));
                    sf[ol * 132 + pl]       = v0;
                    sf[(ol + 1) * 132 + pl] = v1;
                }
            }
        __syncthreads();
        #pragma unroll
        for (int i = 0; i < 16; i++) {
            int idx = tid + i * 256;          // 0..4095
            int ol = idx >> 5, pq = (idx & 31) * 4;
            float4 t = *reinterpret_cast<float4*>(&sf[ol * 132 + pq]);
            *reinterpret_cast<float4*>(
                &Co[(((size_t)n * 256 + n0 + ol) << 14) + hw0 + pq]) = t;
        }
        return;
    }

    #pragma unroll
    for (int mt = 0; mt < 4; mt++) {
        #pragma unroll
        for (int nt = 0; nt < 4; nt++) {
            int ocl = wn + nt * 8 + qc;
            int o   = n0 + ocl;
            float sc0 = sSC[ocl],     sh0 = sSH[ocl];
            float sc1 = sSC[ocl + 1], sh1 = sSH[ocl + 1];
            #pragma unroll
            for (int half = 0; half < 2; half++) {
                int p  = p0 + wm + mt * 16 + qr + half * 8;
                float v0 = acc[mt][nt][half * 2 + 0] * sc0 + sh0;
                float v1 = acc[mt][nt][half * 2 + 1] * sc1 + sh1;
                if (EPI == 1) {
                    v0 = v0 / (1.f + expf(-v0));
                    v1 = v1 / (1.f + expf(-v1));
                    bf16 h0 = __float2bfloat16_rn(v0);
                    bf16 h1 = __float2bfloat16_rn(v1);
                    bf16 l0 = __float2bfloat16_rn(v0 - __bfloat162float(h0));
                    bf16 l1 = __float2bfloat16_rn(v1 - __bfloat162float(h1));
                    size_t ob = (size_t)p * 256 + o;
                    *reinterpret_cast<uint32_t*>(&CoHi[ob]) = pack2(h0, h1);
                    *reinterpret_cast<uint32_t*>(&CoLo[ob]) = pack2(l0, l1);
                } else { // EPI 3
                    if (o < 256) {
                        *reinterpret_cast<float2*>(&Co[(size_t)p * 256 + o]) =
                            make_float2(v0, v1);
                    } else {
                        *reinterpret_cast<float2*>(&Co2[(size_t)p * OMSP + (o - 256)]) =
                            make_float2(v0, v1);
                    }
                }
            }
        }
    }
}

// ---------------------------------------------------------------------------
// DCNv4 sampling, branchless: clamp addresses, fold validity into weights.
// warp = (pixel, 2 groups); lane -> 4 channels via float4.
// ---------------------------------------------------------------------------
__global__ __launch_bounds__(256)
void dcn_sample(const float* __restrict__ v, const float* __restrict__ om,
                bf16* __restrict__ shi, bf16* __restrict__ slo)
{
    int wrp  = (blockIdx.x * 256 + threadIdx.x) >> 5;
    int lane = threadIdx.x & 31;
    int p = wrp >> 1;
    int g = ((wrp & 1) << 1) + (lane >> 4);
    int laneg = lane & 15;
    int n = p >> 14;
    int hw = p & (HWSZ - 1);
    int h = hw >> 7, w = hw & 127;

    const float* op = om + (size_t)p * OMSP + g * 27;
    const int cb = g * 64 + laneg * 4;
    const float* vb = v + ((size_t)n << 22) + cb;   // n*HWSZ*256 + cb

    float a0 = 0.f, a1 = 0.f, a2 = 0.f, a3 = 0.f;
    #pragma unroll
    for (int k = 0; k < KTAP; k++) {
        float ow = op[2 * k];
        float oh = op[2 * k + 1];
        float mk = op[18 + k];
        float lh = (float)(h + k / 3 - 1) + oh;
        float lw = (float)(w + k % 3 - 1) + ow;
        float fh = floorf(lh), fw = floorf(lw);
        int h0 = (int)fh, w0 = (int)fw;
        float dh = lh - fh, dw = lw - fw;
        float w00 = (1.f - dh) * (1.f - dw) * mk;
        float w01 = (1.f - dh) * dw * mk;
        float w10 = dh * (1.f - dw) * mk;
        float w11 = dh * dw * mk;
        // validity (unsigned-compare trick) folded into weights
        bool hv0 = (unsigned)h0 < HSZ;
        bool hv1 = (unsigned)(h0 + 1) < HSZ;
        bool wv0 = (unsigned)w0 < WSZ;
        bool wv1 = (unsigned)(w0 + 1) < WSZ;
        w00 = (hv0 && wv0) ? w00 : 0.f;
        w01 = (hv0 && wv1) ? w01 : 0.f;
        w10 = (hv1 && wv0) ? w10 : 0.f;
        w11 = (hv1 && wv1) ? w11 : 0.f;
        // clamped coordinates -> always-valid addresses
        int h0c = min(max(h0, 0), HSZ - 1);
        int h1c = min(max(h0 + 1, 0), HSZ - 1);
        int w0c = min(max(w0, 0), WSZ - 1);
        int w1c = min(max(w0 + 1, 0), WSZ - 1);
        int r00 = (h0c * WSZ + w0c) << 8;
        int r01 = (h0c * WSZ + w1c) << 8;
        int r10 = (h1c * WSZ + w0c) << 8;
        int r11 = (h1c * WSZ + w1c) << 8;
        float4 q00 = *reinterpret_cast<const float4*>(vb + r00);
        float4 q01 = *reinterpret_cast<const float4*>(vb + r01);
        float4 q10 = *reinterpret_cast<const float4*>(vb + r10);
        float4 q11 = *reinterpret_cast<const float4*>(vb + r11);
        a0 += w00*q00.x + w01*q01.x + w10*q10.x + w11*q11.x;
        a1 += w00*q00.y + w01*q01.y + w10*q10.y + w11*q11.y;
        a2 += w00*q00.z + w01*q01.z + w10*q10.z + w11*q11.z;
        a3 += w00*q00.w + w01*q01.w + w10*q10.w + w11*q11.w;
    }
    bf16 h0 = __float2bfloat16_rn(a0), h1 = __float2bfloat16_rn(a1);
    bf16 h2 = __float2bfloat16_rn(a2), h3 = __float2bfloat16_rn(a3);
    uint2 hv, lv;
    hv.x = pack2(h0, h1); hv.y = pack2(h2, h3);
    lv.x = pack2(__float2bfloat16_rn(a0 - __bfloat162float(h0)),
                 __float2bfloat16_rn(a1 - __bfloat162float(h1)));
    lv.y = pack2(__float2bfloat16_rn(a2 - __bfloat162float(h2)),
                 __float2bfloat16_rn(a3 - __bfloat162float(h3)));
    size_t ob = (size_t)p * 256 + cb;
    *reinterpret_cast<uint2*>(&shi[ob]) = hv;
    *reinterpret_cast<uint2*>(&slo[ob]) = lv;
}

// ---------------------------------------------------------------------------
extern "C" void kernel_launch(void* const* d_in, const int* in_sizes, int n_in,
                              void* d_out, int out_size)
{
    const float* x        = (const float*)d_in[0];
    const float* conv_w   = (const float*)d_in[1];
    const float* bn1_g    = (const float*)d_in[2];
    const float* bn1_b    = (const float*)d_in[3];
    const float* bn1_m    = (const float*)d_in[4];
    const float* bn1_v    = (const float*)d_in[5];
    const float* value_w  = (const float*)d_in[6];
    const float* value_b  = (const float*)d_in[7];
    const float* offset_w = (const float*)d_in[8];
    const float* offset_b = (const float*)d_in[9];
    const float* out_w    = (const float*)d_in[10];
    const float* out_b    = (const float*)d_in[11];
    const float* bn2_g    = (const float*)d_in[12];
    const float* bn2_b    = (const float*)d_in[13];
    const float* bn2_m    = (const float*)d_in[14];
    const float* bn2_v    = (const float*)d_in[15];

    bf16 *xhi, *xlo, *yhi, *ylo, *shi, *slo, *whi, *wlo;
    float *v, *omp;
    cudaGetSymbolAddress((void**)&xhi, g_xhi);
    cudaGetSymbolAddress((void**)&xlo, g_xlo);
    cudaGetSymbolAddress((void**)&yhi, g_yhi);
    cudaGetSymbolAddress((void**)&ylo, g_ylo);
    cudaGetSymbolAddress((void**)&shi, g_shi);
    cudaGetSymbolAddress((void**)&slo, g_slo);
    cudaGetSymbolAddress((void**)&whi, g_whi);
    cudaGetSymbolAddress((void**)&wlo, g_wlo);
    cudaGetSymbolAddress((void**)&v,   g_v);
    cudaGetSymbolAddress((void**)&omp, g_om);

    const int smem = 3 * 32768;   // 96KB (also covers EPI2 staging 67.6KB)
    cudaFuncSetAttribute(gemm_bf16<1>, cudaFuncAttributeMaxDynamicSharedMemorySize, smem);
    cudaFuncSetAttribute(gemm_bf16<2>, cudaFuncAttributeMaxDynamicSharedMemorySize, smem);
    cudaFuncSetAttribute(gemm_bf16<3>, cudaFuncAttributeMaxDynamicSharedMemorySize, smem);

    // prepasses
    w_split<<<896, 256>>>(conv_w, value_w, offset_w, out_w, whi, wlo);
    x_split<<<dim3(128, 8, 4), 256>>>(x, xhi, xlo);

    const int MT = MTOT / 128;   // 512

    // 1) y = silu(bn1(x @ conv_w^T))           -> y hi/lo
    gemm_bf16<1><<<dim3(MT,2), 256, smem>>>(
        xhi, xlo, whi, wlo, nullptr, nullptr,
        bn1_g, bn1_b, bn1_m, bn1_v, nullptr, nullptr, yhi, ylo);
    // 2) fused: v = y@value_w^T + value_b ; om = y@offset_w^T + offset_b
    gemm_bf16<3><<<dim3(MT,3), 256, smem>>>(
        yhi, ylo, whi + 256*256, wlo + 256*256, value_b, offset_b,
        nullptr, nullptr, nullptr, nullptr, v, omp, nullptr, nullptr);
    // 3) deformable sampling -> s hi/lo
    dcn_sample<<<MTOT / 4, 256>>>(v, omp, shi, slo);
    // 4) out = silu(bn2(s @ out_w^T + out_b))  -> NCHW fp32 (staged stores)
    gemm_bf16<2><<<dim3(MT,2), 256, smem>>>(
        shi, slo, whi + 640*256, wlo + 640*256, out_b, nullptr,
        bn2_g, bn2_b, bn2_m, bn2_v, (float*)d_out, nullptr, nullptr, nullptr);
}

// round 8
// speedup vs baseline: 1.1860x; 1.0533x over previous
#include <cuda_runtime.h>
#include <cuda_bf16.h>
#include <cstdint>
#include <math.h>

// ---------------- problem constants ----------------
#define NTOT 4
#define CHN  256
#define HSZ  128
#define WSZ  128
#define HWSZ 16384
#define MTOT 65536
#define KTAP 9
#define EPSV 1e-5f
#define OMSP 128

typedef __nv_bfloat16 bf16;

// ---------------- scratch ----------------
__device__ bf16  g_xhi[MTOT*CHN], g_xlo[MTOT*CHN];
__device__ bf16  g_yhi[MTOT*CHN], g_ylo[MTOT*CHN];
__device__ bf16  g_shi[MTOT*CHN], g_slo[MTOT*CHN];
__device__ float g_v  [MTOT*CHN];
__device__ float g_om [MTOT*OMSP];
__device__ bf16  g_whi[896*CHN],  g_wlo[896*CHN];

// ---------------- helpers ----------------
__device__ __forceinline__ uint32_t smem_u32(const void* p){
    uint32_t a;
    asm("{ .reg .u64 t; cvta.to.shared.u64 t, %1; cvt.u32.u64 %0, t; }" : "=r"(a) : "l"(p));
    return a;
}
__device__ __forceinline__ void cpasync16(uint32_t dst, const void* src){
    asm volatile("cp.async.cg.shared.global [%0], [%1], 16;"
                 :: "r"(dst), "l"(src) : "memory");
}
#define CP_COMMIT()  asm volatile("cp.async.commit_group;" ::: "memory")
#define CP_WAIT(n)   asm volatile("cp.async.wait_group %0;" :: "n"(n) : "memory")

__device__ __forceinline__ void ldsm4(uint32_t& a0, uint32_t& a1, uint32_t& a2,
                                      uint32_t& a3, uint32_t addr){
    asm volatile("ldmatrix.sync.aligned.m8n8.x4.shared.b16 {%0,%1,%2,%3}, [%4];"
                 : "=r"(a0), "=r"(a1), "=r"(a2), "=r"(a3) : "r"(addr));
}
__device__ __forceinline__ void ldsm2(uint32_t& b0, uint32_t& b1, uint32_t addr){
    asm volatile("ldmatrix.sync.aligned.m8n8.x2.shared.b16 {%0,%1}, [%2];"
                 : "=r"(b0), "=r"(b1) : "r"(addr));
}
__device__ __forceinline__ void mma16816(float* c, const uint32_t* a,
                                         const uint32_t* b){
    asm volatile(
        "mma.sync.aligned.m16n8k16.row.col.f32.bf16.bf16.f32 "
        "{%0,%1,%2,%3}, {%4,%5,%6,%7}, {%8,%9}, {%0,%1,%2,%3};"
        : "+f"(c[0]), "+f"(c[1]), "+f"(c[2]), "+f"(c[3])
        : "r"(a[0]), "r"(a[1]), "r"(a[2]), "r"(a[3]), "r"(b[0]), "r"(b[1]));
}
__device__ __forceinline__ uint32_t pack2(bf16 a, bf16 b){
    __nv_bfloat162 h; h.x = a; h.y = b;
    return *reinterpret_cast<uint32_t*>(&h);
}
__device__ __forceinline__ uint32_t swz(int r, int c){
    return (uint32_t)(r * 64 + ((c ^ ((r >> 1) & 3)) * 16));
}

// ---------------------------------------------------------------------------
// Weight split (rows: 0-255 conv | 256-511 value | 512-639 offset | 640-895 out)
// ---------------------------------------------------------------------------
__global__ __launch_bounds__(256)
void w_split(const float* __restrict__ conv_w, const float* __restrict__ value_w,
             const float* __restrict__ offset_w, const float* __restrict__ out_w,
             bf16* __restrict__ whi, bf16* __restrict__ wlo)
{
    int idx = blockIdx.x * 256 + threadIdx.x;
    if (idx >= 896 * 256) return;
    int r = idx >> 8, c = idx & 255;
    float v = 0.f;
    if      (r < 256) v = conv_w[r * 256 + c];
    else if (r < 512) v = value_w[(r - 256) * 256 + c];
    else if (r < 640) { int rr = r - 512; if (rr < 112) v = offset_w[rr * 256 + c]; }
    else              v = out_w[(r - 640) * 256 + c];
    bf16 h = __float2bfloat16_rn(v);
    whi[idx] = h;
    wlo[idx] = __float2bfloat16_rn(v - __bfloat162float(h));
}

// ---------------------------------------------------------------------------
// x prepass: NCHW fp32 -> NHWC bf16 hi/lo
// ---------------------------------------------------------------------------
__global__ __launch_bounds__(256)
void x_split(const float* __restrict__ x, bf16* __restrict__ xhi,
             bf16* __restrict__ xlo)
{
    __shared__ float t[32][129];
    const int tid = threadIdx.x;
    const int n = blockIdx.z, c0 = blockIdx.y * 32, hw0 = blockIdx.x * 128;
    const float* src = x + ((size_t)n * 256 + c0) * HWSZ + hw0;
    #pragma unroll
    for (int i = 0; i < 16; i++) {
        int e = tid + i * 256;
        int c = e >> 7, p = e & 127;
        t[c][p] = src[(size_t)c * HWSZ + p];
    }
    __syncthreads();
    int p = tid >> 1, half = tid & 1;
    size_t base = ((size_t)n * HWSZ + hw0 + p) * 256 + c0 + half * 16;
    bf16 hi[16], lo[16];
    #pragma unroll
    for (int j = 0; j < 16; j++) {
        float a = t[half * 16 + j][p];
        bf16 h = __float2bfloat16_rn(a);
        hi[j] = h;
        lo[j] = __float2bfloat16_rn(a - __bfloat162float(h));
    }
    *reinterpret_cast<uint4*>(&xhi[base])     = *reinterpret_cast<uint4*>(&hi[0]);
    *reinterpret_cast<uint4*>(&xhi[base + 8]) = *reinterpret_cast<uint4*>(&hi[8]);
    *reinterpret_cast<uint4*>(&xlo[base])     = *reinterpret_cast<uint4*>(&lo[0]);
    *reinterpret_cast<uint4*>(&xlo[base + 8]) = *reinterpret_cast<uint4*>(&lo[8]);
}

// ---------------------------------------------------------------------------
// bf16-split HMMA GEMM, 3-stage cp.async pipeline (exact R5 structure).
//   EPI 1: bn+silu -> bf16 hi/lo NHWC (y)
//   EPI 2: bias+bn+silu -> fp32 NCHW (direct stores, sector-efficient)
//   EPI 3: fused v+om
// Tile BM=128, BN=128, 8 warps (2x4), warp 64x32, 2 CTAs/SM.
// ---------------------------------------------------------------------------
template<int EPI>
__global__ __launch_bounds__(256, 2)
void gemm_bf16(const bf16* __restrict__ Ahi, const bf16* __restrict__ Alo,
               const bf16* __restrict__ Bhi, const bf16* __restrict__ Blo,
               const float* __restrict__ bias, const float* __restrict__ bias2,
               const float* __restrict__ gamma, const float* __restrict__ beta,
               const float* __restrict__ mean,  const float* __restrict__ var,
               float* __restrict__ Co, float* __restrict__ Co2,
               bf16* __restrict__ CoHi, bf16* __restrict__ CoLo)
{
    extern __shared__ __align__(16) char dsm[];
    __shared__ float sSC[128], sSH[128];

    const int tid  = threadIdx.x;
    const int wid  = tid >> 5;
    const int lane = tid & 31;
    const int p0   = blockIdx.x * 128;
    const int n0   = blockIdx.y * 128;

    const uint32_t sb = smem_u32(dsm);
    auto AHI = [&](int s){ return sb + s * 32768 + 0;     };
    auto ALO = [&](int s){ return sb + s * 32768 + 8192;  };
    auto BHI = [&](int s){ return sb + s * 32768 + 16384; };
    auto BLO = [&](int s){ return sb + s * 32768 + 24576; };

    if (tid < 128) {
        int o = n0 + tid;
        float sc = 1.f, sh = 0.f;
        if (EPI == 1) {
            float s_ = gamma[o] * rsqrtf(var[o] + EPSV);
            sc = s_; sh = beta[o] - mean[o] * s_;
        } else if (EPI == 2) {
            float s_ = gamma[o] * rsqrtf(var[o] + EPSV);
            sc = s_; sh = (beta[o] - mean[o] * s_) + bias[o] * s_;
        } else { // EPI 3
            if (o < 256)            sh = bias[o];
            else if (o - 256 < 112) sh = bias2[o - 256];
        }
        sSC[tid] = sc; sSH[tid] = sh;
    }

    auto load_stage = [&](int kt, int s) {
        #pragma unroll
        for (int i = 0; i < 2; i++) {
            int e = tid + i * 256;
            int r = e >> 2, c = e & 3;
            size_t ao = (size_t)(p0 + r) * 256 + kt + c * 8;
            size_t bo = (size_t)(n0 + r) * 256 + kt + c * 8;
            uint32_t d = swz(r, c);
            cpasync16(AHI(s) + d, Ahi + ao);
            cpasync16(ALO(s) + d, Alo + ao);
            cpasync16(BHI(s) + d, Bhi + bo);
            cpasync16(BLO(s) + d, Blo + bo);
        }
        CP_COMMIT();
    };

    const int wm = (wid >> 2) * 64;
    const int wn = (wid & 3) * 32;

    float acc[4][4][4];
    #pragma unroll
    for (int i = 0; i < 4; i++)
        #pragma unroll
        for (int j = 0; j < 4; j++)
            #pragma unroll
            for (int q = 0; q < 4; q++) acc[i][j][q] = 0.f;

    load_stage(0, 0);
    load_stage(32, 1);

    #pragma unroll 1
    for (int st = 0; st < 8; st++) {
        const int s = st % 3;
        if (st == 7) { CP_WAIT(0); } else { CP_WAIT(1); }
        __syncthreads();

        #pragma unroll
        for (int kk = 0; kk < 2; kk++) {
            const int c0 = kk * 2;
            uint32_t ah[4][4], al[4][4], bh[4][2], bl[4][2];
            #pragma unroll
            for (int mt = 0; mt < 4; mt++) {
                int rr = wm + mt * 16 + (lane & 15);
                int cc = c0 + (lane >> 4);
                uint32_t ad = swz(rr, cc);
                ldsm4(ah[mt][0], ah[mt][1], ah[mt][2], ah[mt][3], AHI(s) + ad);
                ldsm4(al[mt][0], al[mt][1], al[mt][2], al[mt][3], ALO(s) + ad);
            }
            #pragma unroll
            for (int nt = 0; nt < 4; nt++) {
                int rr = wn + nt * 8 + (lane & 7);
                int cc = c0 + ((lane >> 3) & 1);
                uint32_t bd = swz(rr, cc);
                ldsm2(bh[nt][0], bh[nt][1], BHI(s) + bd);
                ldsm2(bl[nt][0], bl[nt][1], BLO(s) + bd);
            }
            #pragma unroll
            for (int mt = 0; mt < 4; mt++)
                #pragma unroll
                for (int nt = 0; nt < 4; nt++) {
                    mma16816(acc[mt][nt], ah[mt], bh[nt]);
                    mma16816(acc[mt][nt], ah[mt], bl[nt]);
                    mma16816(acc[mt][nt], al[mt], bh[nt]);
                }
        }
        if (st < 6) load_stage((st + 2) * 32, (st + 2) % 3);
    }

    // ---------------- epilogue ----------------
    const int qr = lane >> 2;
    const int qc = (lane & 3) * 2;
    #pragma unroll
    for (int mt = 0; mt < 4; mt++) {
        #pragma unroll
        for (int nt = 0; nt < 4; nt++) {
            int ocl = wn + nt * 8 + qc;
            int o   = n0 + ocl;
            float sc0 = sSC[ocl],     sh0 = sSH[ocl];
            float sc1 = sSC[ocl + 1], sh1 = sSH[ocl + 1];
            #pragma unroll
            for (int half = 0; half < 2; half++) {
                int p  = p0 + wm + mt * 16 + qr + half * 8;
                float v0 = acc[mt][nt][half * 2 + 0] * sc0 + sh0;
                float v1 = acc[mt][nt][half * 2 + 1] * sc1 + sh1;
                if (EPI == 1 || EPI == 2) {
                    v0 = v0 / (1.f + expf(-v0));
                    v1 = v1 / (1.f + expf(-v1));
                }
                if (EPI == 1) {
                    bf16 h0 = __float2bfloat16_rn(v0);
                    bf16 h1 = __float2bfloat16_rn(v1);
                    bf16 l0 = __float2bfloat16_rn(v0 - __bfloat162float(h0));
                    bf16 l1 = __float2bfloat16_rn(v1 - __bfloat162float(h1));
                    size_t ob = (size_t)p * 256 + o;
                    *reinterpret_cast<uint32_t*>(&CoHi[ob]) = pack2(h0, h1);
                    *reinterpret_cast<uint32_t*>(&CoLo[ob]) = pack2(l0, l1);
                } else if (EPI == 2) {
                    int n = p >> 14, hw = p & 16383;
                    Co[(((size_t)n * 256 + o)     << 14) + hw] = v0;
                    Co[(((size_t)n * 256 + o + 1) << 14) + hw] = v1;
                } else { // EPI 3
                    if (o < 256) {
                        *reinterpret_cast<float2*>(&Co[(size_t)p * 256 + o]) =
                            make_float2(v0, v1);
                    } else {
                        *reinterpret_cast<float2*>(&Co2[(size_t)p * OMSP + (o - 256)]) =
                            make_float2(v0, v1);
                    }
                }
            }
        }
    }
}

// ---------------------------------------------------------------------------
// DCNv4 sampling v3: two-phase.
//  Phase 1: 144 threads/block compute per-(pixel,group,tap) params into smem
//           (4 bilinear weights + 4 clamped row offsets) — no per-lane
//           duplication of the weight/address math.
//  Phase 2: warp = (pixel, 2 groups); lane -> 4 channels; 4 float4 gathers
//           + 16 FMA per tap, params broadcast from smem.
// Block = 256 threads = 4 pixels x 4 groups.
// ---------------------------------------------------------------------------
__global__ __launch_bounds__(256)
void dcn_sample(const float* __restrict__ v, const float* __restrict__ om,
                bf16* __restrict__ shi, bf16* __restrict__ slo)
{
    __shared__ float4 sW[144];
    __shared__ int4   sR[144];
    const int tid   = threadIdx.x;
    const int pbase = blockIdx.x * 4;

    if (tid < 144) {
        int pg = tid / 9;              // 0..15: (pixel_idx, group)
        int k  = tid - pg * 9;
        int pi = pg >> 2, g = pg & 3;
        int p  = pbase + pi;
        int hw = p & (HWSZ - 1);
        int h = hw >> 7, w = hw & 127;
        const float* op = om + (size_t)p * OMSP + g * 27;
        float ow = op[2 * k];
        float oh = op[2 * k + 1];
        float mk = op[18 + k];
        float lh = (float)(h + k / 3 - 1) + oh;
        float lw = (float)(w + k % 3 - 1) + ow;
        float fh = floorf(lh), fw = floorf(lw);
        int h0 = (int)fh, w0 = (int)fw;
        float dh = lh - fh, dw = lw - fw;
        float w00 = (1.f - dh) * (1.f - dw) * mk;
        float w01 = (1.f - dh) * dw * mk;
        float w10 = dh * (1.f - dw) * mk;
        float w11 = dh * dw * mk;
        bool hv0 = (unsigned)h0 < HSZ;
        bool hv1 = (unsigned)(h0 + 1) < HSZ;
        bool wv0 = (unsigned)w0 < WSZ;
        bool wv1 = (unsigned)(w0 + 1) < WSZ;
        w00 = (hv0 && wv0) ? w00 : 0.f;
        w01 = (hv0 && wv1) ? w01 : 0.f;
        w10 = (hv1 && wv0) ? w10 : 0.f;
        w11 = (hv1 && wv1) ? w11 : 0.f;
        int h0c = min(max(h0, 0), HSZ - 1);
        int h1c = min(max(h0 + 1, 0), HSZ - 1);
        int w0c = min(max(w0, 0), WSZ - 1);
        int w1c = min(max(w0 + 1, 0), WSZ - 1);
        sW[tid] = make_float4(w00, w01, w10, w11);
        sR[tid] = make_int4((h0c * WSZ + w0c) << 8, (h0c * WSZ + w1c) << 8,
                            (h1c * WSZ + w0c) << 8, (h1c * WSZ + w1c) << 8);
    }
    __syncthreads();

    const int wid   = tid >> 5;
    const int lane  = tid & 31;
    const int pi    = wid >> 1;
    const int g     = ((wid & 1) << 1) + (lane >> 4);
    const int laneg = lane & 15;
    const int p     = pbase + pi;
    const int n     = p >> 14;
    const int cb    = g * 64 + laneg * 4;
    const float* vb = v + ((size_t)n << 22) + cb;
    const int base  = (pi * 4 + g) * 9;

    float a0 = 0.f, a1 = 0.f, a2 = 0.f, a3 = 0.f;
    #pragma unroll
    for (int k = 0; k < KTAP; k++) {
        float4 wv = sW[base + k];
        int4   rv = sR[base + k];
        float4 q00 = *reinterpret_cast<const float4*>(vb + rv.x);
        float4 q01 = *reinterpret_cast<const float4*>(vb + rv.y);
        float4 q10 = *reinterpret_cast<const float4*>(vb + rv.z);
        float4 q11 = *reinterpret_cast<const float4*>(vb + rv.w);
        a0 += wv.x*q00.x + wv.y*q01.x + wv.z*q10.x + wv.w*q11.x;
        a1 += wv.x*q00.y + wv.y*q01.y + wv.z*q10.y + wv.w*q11.y;
        a2 += wv.x*q00.z + wv.y*q01.z + wv.z*q10.z + wv.w*q11.z;
        a3 += wv.x*q00.w + wv.y*q01.w + wv.z*q10.w + wv.w*q11.w;
    }
    bf16 h0 = __float2bfloat16_rn(a0), h1 = __float2bfloat16_rn(a1);
    bf16 h2 = __float2bfloat16_rn(a2), h3 = __float2bfloat16_rn(a3);
    uint2 hv, lv;
    hv.x = pack2(h0, h1); hv.y = pack2(h2, h3);
    lv.x = pack2(__float2bfloat16_rn(a0 - __bfloat162float(h0)),
                 __float2bfloat16_rn(a1 - __bfloat162float(h1)));
    lv.y = pack2(__float2bfloat16_rn(a2 - __bfloat162float(h2)),
                 __float2bfloat16_rn(a3 - __bfloat162float(h3)));
    size_t ob = (size_t)p * 256 + cb;
    *reinterpret_cast<uint2*>(&shi[ob]) = hv;
    *reinterpret_cast<uint2*>(&slo[ob]) = lv;
}

// ---------------------------------------------------------------------------
extern "C" void kernel_launch(void* const* d_in, const int* in_sizes, int n_in,
                              void* d_out, int out_size)
{
    const float* x        = (const float*)d_in[0];
    const float* conv_w   = (const float*)d_in[1];
    const float* bn1_g    = (const float*)d_in[2];
    const float* bn1_b    = (const float*)d_in[3];
    const float* bn1_m    = (const float*)d_in[4];
    const float* bn1_v    = (const float*)d_in[5];
    const float* value_w  = (const float*)d_in[6];
    const float* value_b  = (const float*)d_in[7];
    const float* offset_w = (const float*)d_in[8];
    const float* offset_b = (const float*)d_in[9];
    const float* out_w    = (const float*)d_in[10];
    const float* out_b    = (const float*)d_in[11];
    const float* bn2_g    = (const float*)d_in[12];
    const float* bn2_b    = (const float*)d_in[13];
    const float* bn2_m    = (const float*)d_in[14];
    const float* bn2_v    = (const float*)d_in[15];

    bf16 *xhi, *xlo, *yhi, *ylo, *shi, *slo, *whi, *wlo;
    float *v, *omp;
    cudaGetSymbolAddress((void**)&xhi, g_xhi);
    cudaGetSymbolAddress((void**)&xlo, g_xlo);
    cudaGetSymbolAddress((void**)&yhi, g_yhi);
    cudaGetSymbolAddress((void**)&ylo, g_ylo);
    cudaGetSymbolAddress((void**)&shi, g_shi);
    cudaGetSymbolAddress((void**)&slo, g_slo);
    cudaGetSymbolAddress((void**)&whi, g_whi);
    cudaGetSymbolAddress((void**)&wlo, g_wlo);
    cudaGetSymbolAddress((void**)&v,   g_v);
    cudaGetSymbolAddress((void**)&omp, g_om);

    const int smem = 3 * 32768;   // 96KB, 3 stages
    cudaFuncSetAttribute(gemm_bf16<1>, cudaFuncAttributeMaxDynamicSharedMemorySize, smem);
    cudaFuncSetAttribute(gemm_bf16<2>, cudaFuncAttributeMaxDynamicSharedMemorySize, smem);
    cudaFuncSetAttribute(gemm_bf16<3>, cudaFuncAttributeMaxDynamicSharedMemorySize, smem);

    // prepasses
    w_split<<<896, 256>>>(conv_w, value_w, offset_w, out_w, whi, wlo);
    x_split<<<dim3(128, 8, 4), 256>>>(x, xhi, xlo);

    const int MT = MTOT / 128;   // 512

    // 1) y = silu(bn1(x @ conv_w^T))           -> y hi/lo
    gemm_bf16<1><<<dim3(MT,2), 256, smem>>>(
        xhi, xlo, whi, wlo, nullptr, nullptr,
        bn1_g, bn1_b, bn1_m, bn1_v, nullptr, nullptr, yhi, ylo);
    // 2) fused: v = y@value_w^T + value_b ; om = y@offset_w^T + offset_b
    gemm_bf16<3><<<dim3(MT,3), 256, smem>>>(
        yhi, ylo, whi + 256*256, wlo + 256*256, value_b, offset_b,
        nullptr, nullptr, nullptr, nullptr, v, omp, nullptr, nullptr);
    // 3) deformable sampling -> s hi/lo (two-phase, block = 4 pixels)
    dcn_sample<<<MTOT / 4, 256>>>(v, omp, shi, slo);
    // 4) out = silu(bn2(s @ out_w^T + out_b))  -> NCHW fp32
    gemm_bf16<2><<<dim3(MT,2), 256, smem>>>(
        shi, slo, whi + 640*256, wlo + 640*256, out_b, nullptr,
        bn2_g, bn2_b, bn2_m, bn2_v, (float*)d_out, nullptr, nullptr, nullptr);
}

// round 9
// speedup vs baseline: 1.2179x; 1.0268x over previous
#include <cuda_runtime.h>
#include <cuda_bf16.h>
#include <cstdint>
#include <math.h>

// ---------------- problem constants ----------------
#define NTOT 4
#define CHN  256
#define HSZ  128
#define WSZ  128
#define HWSZ 16384
#define MTOT 65536
#define KTAP 9
#define EPSV 1e-5f
#define OMSP 128

typedef __nv_bfloat16 bf16;

// ---------------- scratch ----------------
__device__ bf16  g_xhi[MTOT*CHN], g_xlo[MTOT*CHN];
__device__ bf16  g_yhi[MTOT*CHN], g_ylo[MTOT*CHN];
__device__ bf16  g_shi[MTOT*CHN], g_slo[MTOT*CHN];
__device__ float g_v  [MTOT*CHN];
__device__ float g_om [MTOT*OMSP];
__device__ bf16  g_whi[896*CHN],  g_wlo[896*CHN];

// ---------------- helpers ----------------
__device__ __forceinline__ uint32_t smem_u32(const void* p){
    uint32_t a;
    asm("{ .reg .u64 t; cvta.to.shared.u64 t, %1; cvt.u32.u64 %0, t; }" : "=r"(a) : "l"(p));
    return a;
}
__device__ __forceinline__ void cpasync16(uint32_t dst, const void* src){
    asm volatile("cp.async.cg.shared.global [%0], [%1], 16;"
                 :: "r"(dst), "l"(src) : "memory");
}
#define CP_COMMIT()  asm volatile("cp.async.commit_group;" ::: "memory")
#define CP_WAIT(n)   asm volatile("cp.async.wait_group %0;" :: "n"(n) : "memory")

__device__ __forceinline__ void ldsm4(uint32_t& a0, uint32_t& a1, uint32_t& a2,
                                      uint32_t& a3, uint32_t addr){
    asm volatile("ldmatrix.sync.aligned.m8n8.x4.shared.b16 {%0,%1,%2,%3}, [%4];"
                 : "=r"(a0), "=r"(a1), "=r"(a2), "=r"(a3) : "r"(addr));
}
__device__ __forceinline__ void ldsm2(uint32_t& b0, uint32_t& b1, uint32_t addr){
    asm volatile("ldmatrix.sync.aligned.m8n8.x2.shared.b16 {%0,%1}, [%2];"
                 : "=r"(b0), "=r"(b1) : "r"(addr));
}
__device__ __forceinline__ void mma16816(float* c, const uint32_t* a,
                                         const uint32_t* b){
    asm volatile(
        "mma.sync.aligned.m16n8k16.row.col.f32.bf16.bf16.f32 "
        "{%0,%1,%2,%3}, {%4,%5,%6,%7}, {%8,%9}, {%0,%1,%2,%3};"
        : "+f"(c[0]), "+f"(c[1]), "+f"(c[2]), "+f"(c[3])
        : "r"(a[0]), "r"(a[1]), "r"(a[2]), "r"(a[3]), "r"(b[0]), "r"(b[1]));
}
__device__ __forceinline__ uint32_t pack2(bf16 a, bf16 b){
    __nv_bfloat162 h; h.x = a; h.y = b;
    return *reinterpret_cast<uint32_t*>(&h);
}
__device__ __forceinline__ uint32_t swz(int r, int c){
    return (uint32_t)(r * 64 + ((c ^ ((r >> 1) & 3)) * 16));
}
__device__ __forceinline__ float silu_f(float x){
    return x / (1.f + __expf(-x));
}

// ---------------------------------------------------------------------------
// Weight split (rows: 0-255 conv | 256-511 value | 512-639 offset | 640-895 out)
// ---------------------------------------------------------------------------
__global__ __launch_bounds__(256)
void w_split(const float* __restrict__ conv_w, const float* __restrict__ value_w,
             const float* __restrict__ offset_w, const float* __restrict__ out_w,
             bf16* __restrict__ whi, bf16* __restrict__ wlo)
{
    int idx = blockIdx.x * 256 + threadIdx.x;
    if (idx >= 896 * 256) return;
    int r = idx >> 8, c = idx & 255;
    float v = 0.f;
    if      (r < 256) v = conv_w[r * 256 + c];
    else if (r < 512) v = value_w[(r - 256) * 256 + c];
    else if (r < 640) { int rr = r - 512; if (rr < 112) v = offset_w[rr * 256 + c]; }
    else              v = out_w[(r - 640) * 256 + c];
    bf16 h = __float2bfloat16_rn(v);
    whi[idx] = h;
    wlo[idx] = __float2bfloat16_rn(v - __bfloat162float(h));
}

// ---------------------------------------------------------------------------
// x prepass: NCHW fp32 -> NHWC bf16 hi/lo
// ---------------------------------------------------------------------------
__global__ __launch_bounds__(256)
void x_split(const float* __restrict__ x, bf16* __restrict__ xhi,
             bf16* __restrict__ xlo)
{
    __shared__ float t[32][129];
    const int tid = threadIdx.x;
    const int n = blockIdx.z, c0 = blockIdx.y * 32, hw0 = blockIdx.x * 128;
    const float* src = x + ((size_t)n * 256 + c0) * HWSZ + hw0;
    #pragma unroll
    for (int i = 0; i < 16; i++) {
        int e = tid + i * 256;
        int c = e >> 7, p = e & 127;
        t[c][p] = src[(size_t)c * HWSZ + p];
    }
    __syncthreads();
    int p = tid >> 1, half = tid & 1;
    size_t base = ((size_t)n * HWSZ + hw0 + p) * 256 + c0 + half * 16;
    bf16 hi[16], lo[16];
    #pragma unroll
    for (int j = 0; j < 16; j++) {
        float a = t[half * 16 + j][p];
        bf16 h = __float2bfloat16_rn(a);
        hi[j] = h;
        lo[j] = __float2bfloat16_rn(a - __bfloat162float(h));
    }
    *reinterpret_cast<uint4*>(&xhi[base])     = *reinterpret_cast<uint4*>(&hi[0]);
    *reinterpret_cast<uint4*>(&xhi[base + 8]) = *reinterpret_cast<uint4*>(&hi[8]);
    *reinterpret_cast<uint4*>(&xlo[base])     = *reinterpret_cast<uint4*>(&lo[0]);
    *reinterpret_cast<uint4*>(&xlo[base + 8]) = *reinterpret_cast<uint4*>(&lo[8]);
}

// ---------------------------------------------------------------------------
// bf16-split HMMA GEMM, 3-stage cp.async pipeline (R5 structure).
// GRID SWAP: blockIdx.x = n-block (fast-varying -> L2 A-tile reuse),
//            blockIdx.y = pixel tile.
//   EPI 1: bn+silu -> bf16 hi/lo NHWC (y)
//   EPI 2: bias+bn+silu -> fp32 NCHW (direct stores)
//   EPI 3: fused v+om
// Tile BM=128, BN=128, 8 warps (2x4), warp 64x32, 2 CTAs/SM.
// ---------------------------------------------------------------------------
template<int EPI>
__global__ __launch_bounds__(256, 2)
void gemm_bf16(const bf16* __restrict__ Ahi, const bf16* __restrict__ Alo,
               const bf16* __restrict__ Bhi, const bf16* __restrict__ Blo,
               const float* __restrict__ bias, const float* __restrict__ bias2,
               const float* __restrict__ gamma, const float* __restrict__ beta,
               const float* __restrict__ mean,  const float* __restrict__ var,
               float* __restrict__ Co, float* __restrict__ Co2,
               bf16* __restrict__ CoHi, bf16* __restrict__ CoLo)
{
    extern __shared__ __align__(16) char dsm[];
    __shared__ float sSC[128], sSH[128];

    const int tid  = threadIdx.x;
    const int wid  = tid >> 5;
    const int lane = tid & 31;
    const int p0   = blockIdx.y * 128;     // pixel tile (slow)
    const int n0   = blockIdx.x * 128;     // n-block  (fast -> L2 reuse of A)

    const uint32_t sb = smem_u32(dsm);
    auto AHI = [&](int s){ return sb + s * 32768 + 0;     };
    auto ALO = [&](int s){ return sb + s * 32768 + 8192;  };
    auto BHI = [&](int s){ return sb + s * 32768 + 16384; };
    auto BLO = [&](int s){ return sb + s * 32768 + 24576; };

    if (tid < 128) {
        int o = n0 + tid;
        float sc = 1.f, sh = 0.f;
        if (EPI == 1) {
            float s_ = gamma[o] * rsqrtf(var[o] + EPSV);
            sc = s_; sh = beta[o] - mean[o] * s_;
        } else if (EPI == 2) {
            float s_ = gamma[o] * rsqrtf(var[o] + EPSV);
            sc = s_; sh = (beta[o] - mean[o] * s_) + bias[o] * s_;
        } else { // EPI 3
            if (o < 256)            sh = bias[o];
            else if (o - 256 < 112) sh = bias2[o - 256];
        }
        sSC[tid] = sc; sSH[tid] = sh;
    }

    auto load_stage = [&](int kt, int s) {
        #pragma unroll
        for (int i = 0; i < 2; i++) {
            int e = tid + i * 256;
            int r = e >> 2, c = e & 3;
            size_t ao = (size_t)(p0 + r) * 256 + kt + c * 8;
            size_t bo = (size_t)(n0 + r) * 256 + kt + c * 8;
            uint32_t d = swz(r, c);
            cpasync16(AHI(s) + d, Ahi + ao);
            cpasync16(ALO(s) + d, Alo + ao);
            cpasync16(BHI(s) + d, Bhi + bo);
            cpasync16(BLO(s) + d, Blo + bo);
        }
        CP_COMMIT();
    };

    const int wm = (wid >> 2) * 64;
    const int wn = (wid & 3) * 32;

    float acc[4][4][4];
    #pragma unroll
    for (int i = 0; i < 4; i++)
        #pragma unroll
        for (int j = 0; j < 4; j++)
            #pragma unroll
            for (int q = 0; q < 4; q++) acc[i][j][q] = 0.f;

    load_stage(0, 0);
    load_stage(32, 1);

    #pragma unroll 1
    for (int st = 0; st < 8; st++) {
        const int s = st % 3;
        if (st == 7) { CP_WAIT(0); } else { CP_WAIT(1); }
        __syncthreads();

        #pragma unroll
        for (int kk = 0; kk < 2; kk++) {
            const int c0 = kk * 2;
            uint32_t ah[4][4], al[4][4], bh[4][2], bl[4][2];
            #pragma unroll
            for (int mt = 0; mt < 4; mt++) {
                int rr = wm + mt * 16 + (lane & 15);
                int cc = c0 + (lane >> 4);
                uint32_t ad = swz(rr, cc);
                ldsm4(ah[mt][0], ah[mt][1], ah[mt][2], ah[mt][3], AHI(s) + ad);
                ldsm4(al[mt][0], al[mt][1], al[mt][2], al[mt][3], ALO(s) + ad);
            }
            #pragma unroll
            for (int nt = 0; nt < 4; nt++) {
                int rr = wn + nt * 8 + (lane & 7);
                int cc = c0 + ((lane >> 3) & 1);
                uint32_t bd = swz(rr, cc);
                ldsm2(bh[nt][0], bh[nt][1], BHI(s) + bd);
                ldsm2(bl[nt][0], bl[nt][1], BLO(s) + bd);
            }
            #pragma unroll
            for (int mt = 0; mt < 4; mt++)
                #pragma unroll
                for (int nt = 0; nt < 4; nt++) {
                    mma16816(acc[mt][nt], ah[mt], bh[nt]);
                    mma16816(acc[mt][nt], ah[mt], bl[nt]);
                    mma16816(acc[mt][nt], al[mt], bh[nt]);
                }
        }
        if (st < 6) load_stage((st + 2) * 32, (st + 2) % 3);
    }

    // ---------------- epilogue ----------------
    const int qr = lane >> 2;
    const int qc = (lane & 3) * 2;
    #pragma unroll
    for (int mt = 0; mt < 4; mt++) {
        #pragma unroll
        for (int nt = 0; nt < 4; nt++) {
            int ocl = wn + nt * 8 + qc;
            int o   = n0 + ocl;
            float sc0 = sSC[ocl],     sh0 = sSH[ocl];
            float sc1 = sSC[ocl + 1], sh1 = sSH[ocl + 1];
            #pragma unroll
            for (int half = 0; half < 2; half++) {
                int p  = p0 + wm + mt * 16 + qr + half * 8;
                float v0 = acc[mt][nt][half * 2 + 0] * sc0 + sh0;
                float v1 = acc[mt][nt][half * 2 + 1] * sc1 + sh1;
                if (EPI == 1 || EPI == 2) {
                    v0 = silu_f(v0);
                    v1 = silu_f(v1);
                }
                if (EPI == 1) {
                    bf16 h0 = __float2bfloat16_rn(v0);
                    bf16 h1 = __float2bfloat16_rn(v1);
                    bf16 l0 = __float2bfloat16_rn(v0 - __bfloat162float(h0));
                    bf16 l1 = __float2bfloat16_rn(v1 - __bfloat162float(h1));
                    size_t ob = (size_t)p * 256 + o;
                    *reinterpret_cast<uint32_t*>(&CoHi[ob]) = pack2(h0, h1);
                    *reinterpret_cast<uint32_t*>(&CoLo[ob]) = pack2(l0, l1);
                } else if (EPI == 2) {
                    int n = p >> 14, hw = p & 16383;
                    Co[(((size_t)n * 256 + o)     << 14) + hw] = v0;
                    Co[(((size_t)n * 256 + o + 1) << 14) + hw] = v1;
                } else { // EPI 3
                    if (o < 256) {
                        *reinterpret_cast<float2*>(&Co[(size_t)p * 256 + o]) =
                            make_float2(v0, v1);
                    } else {
                        *reinterpret_cast<float2*>(&Co2[(size_t)p * OMSP + (o - 256)]) =
                            make_float2(v0, v1);
                    }
                }
            }
        }
    }
}

// ---------------------------------------------------------------------------
// DCNv4 sampling (R5's best-measured version): warp = (pixel, 2 groups);
// lane -> 4 channels via float4; branchy validity tests.
// ---------------------------------------------------------------------------
__global__ __launch_bounds__(256)
void dcn_sample(const float* __restrict__ v, const float* __restrict__ om,
                bf16* __restrict__ shi, bf16* __restrict__ slo)
{
    int wrp  = (blockIdx.x * 256 + threadIdx.x) >> 5;
    int lane = threadIdx.x & 31;
    int p = wrp >> 1;
    int g = ((wrp & 1) << 1) + (lane >> 4);
    int laneg = lane & 15;
    int n = p >> 14;
    int hw = p & (HWSZ - 1);
    int h = hw >> 7, w = hw & 127;

    const float* op = om + (size_t)p * OMSP + g * 27;
    const int cb = g * 64 + laneg * 4;
    const int nb = n << 14;

    float a0 = 0.f, a1 = 0.f, a2 = 0.f, a3 = 0.f;
    #pragma unroll
    for (int k = 0; k < KTAP; k++) {
        float ow = op[2 * k];
        float oh = op[2 * k + 1];
        float mk = op[18 + k];
        float lh = (float)(h + k / 3 - 1) + oh;
        float lw = (float)(w + k % 3 - 1) + ow;
        float fh = floorf(lh), fw = floorf(lw);
        int h0 = (int)fh, w0 = (int)fw;
        float dh = lh - fh, dw = lw - fw;
        float w00 = (1.f - dh) * (1.f - dw) * mk;
        float w01 = (1.f - dh) * dw * mk;
        float w10 = dh * (1.f - dw) * mk;
        float w11 = dh * dw * mk;
        bool hv0 = (unsigned)h0 < HSZ;
        bool hv1 = (unsigned)(h0 + 1) < HSZ;
        bool wv0 = (unsigned)w0 < WSZ;
        bool wv1 = (unsigned)(w0 + 1) < WSZ;
        int r0 = (nb + h0 * WSZ + w0) << 8;
        if (hv0 && wv0) { float4 q = *reinterpret_cast<const float4*>(v + r0 + cb);
                          a0 += w00*q.x; a1 += w00*q.y; a2 += w00*q.z; a3 += w00*q.w; }
        if (hv0 && wv1) { float4 q = *reinterpret_cast<const float4*>(v + r0 + 256 + cb);
                          a0 += w01*q.x; a1 += w01*q.y; a2 += w01*q.z; a3 += w01*q.w; }
        if (hv1 && wv0) { float4 q = *reinterpret_cast<const float4*>(v + r0 + (WSZ << 8) + cb);
                          a0 += w10*q.x; a1 += w10*q.y; a2 += w10*q.z; a3 += w10*q.w; }
        if (hv1 && wv1) { float4 q = *reinterpret_cast<const float4*>(v + r0 + ((WSZ + 1) << 8) + cb);
                          a0 += w11*q.x; a1 += w11*q.y; a2 += w11*q.z; a3 += w11*q.w; }
    }
    bf16 h0 = __float2bfloat16_rn(a0), h1 = __float2bfloat16_rn(a1);
    bf16 h2 = __float2bfloat16_rn(a2), h3 = __float2bfloat16_rn(a3);
    uint2 hv, lv;
    hv.x = pack2(h0, h1); hv.y = pack2(h2, h3);
    lv.x = pack2(__float2bfloat16_rn(a0 - __bfloat162float(h0)),
                 __float2bfloat16_rn(a1 - __bfloat162float(h1)));
    lv.y = pack2(__float2bfloat16_rn(a2 - __bfloat162float(h2)),
                 __float2bfloat16_rn(a3 - __bfloat162float(h3)));
    size_t ob = (size_t)p * 256 + cb;
    *reinterpret_cast<uint2*>(&shi[ob]) = hv;
    *reinterpret_cast<uint2*>(&slo[ob]) = lv;
}

// ---------------------------------------------------------------------------
extern "C" void kernel_launch(void* const* d_in, const int* in_sizes, int n_in,
                              void* d_out, int out_size)
{
    const float* x        = (const float*)d_in[0];
    const float* conv_w   = (const float*)d_in[1];
    const float* bn1_g    = (const float*)d_in[2];
    const float* bn1_b    = (const float*)d_in[3];
    const float* bn1_m    = (const float*)d_in[4];
    const float* bn1_v    = (const float*)d_in[5];
    const float* value_w  = (const float*)d_in[6];
    const float* value_b  = (const float*)d_in[7];
    const float* offset_w = (const float*)d_in[8];
    const float* offset_b = (const float*)d_in[9];
    const float* out_w    = (const float*)d_in[10];
    const float* out_b    = (const float*)d_in[11];
    const float* bn2_g    = (const float*)d_in[12];
    const float* bn2_b    = (const float*)d_in[13];
    const float* bn2_m    = (const float*)d_in[14];
    const float* bn2_v    = (const float*)d_in[15];

    bf16 *xhi, *xlo, *yhi, *ylo, *shi, *slo, *whi, *wlo;
    float *v, *omp;
    cudaGetSymbolAddress((void**)&xhi, g_xhi);
    cudaGetSymbolAddress((void**)&xlo, g_xlo);
    cudaGetSymbolAddress((void**)&yhi, g_yhi);
    cudaGetSymbolAddress((void**)&ylo, g_ylo);
    cudaGetSymbolAddress((void**)&shi, g_shi);
    cudaGetSymbolAddress((void**)&slo, g_slo);
    cudaGetSymbolAddress((void**)&whi, g_whi);
    cudaGetSymbolAddress((void**)&wlo, g_wlo);
    cudaGetSymbolAddress((void**)&v,   g_v);
    cudaGetSymbolAddress((void**)&omp, g_om);

    const int smem = 3 * 32768;   // 96KB, 3 stages
    cudaFuncSetAttribute(gemm_bf16<1>, cudaFuncAttributeMaxDynamicSharedMemorySize, smem);
    cudaFuncSetAttribute(gemm_bf16<2>, cudaFuncAttributeMaxDynamicSharedMemorySize, smem);
    cudaFuncSetAttribute(gemm_bf16<3>, cudaFuncAttributeMaxDynamicSharedMemorySize, smem);

    // prepasses
    w_split<<<896, 256>>>(conv_w, value_w, offset_w, out_w, whi, wlo);
    x_split<<<dim3(128, 8, 4), 256>>>(x, xhi, xlo);

    const int MT = MTOT / 128;   // 512 pixel tiles

    // NOTE: grid = (n-blocks, pixel-tiles) — x fastest for L2 A-tile reuse.
    // 1) y = silu(bn1(x @ conv_w^T))           -> y hi/lo
    gemm_bf16<1><<<dim3(2, MT), 256, smem>>>(
        xhi, xlo, whi, wlo, nullptr, nullptr,
        bn1_g, bn1_b, bn1_m, bn1_v, nullptr, nullptr, yhi, ylo);
    // 2) fused: v = y@value_w^T + value_b ; om = y@offset_w^T + offset_b
    gemm_bf16<3><<<dim3(3, MT), 256, smem>>>(
        yhi, ylo, whi + 256*256, wlo + 256*256, value_b, offset_b,
        nullptr, nullptr, nullptr, nullptr, v, omp, nullptr, nullptr);
    // 3) deformable sampling -> s hi/lo
    dcn_sample<<<MTOT / 4, 256>>>(v, omp, shi, slo);
    // 4) out = silu(bn2(s @ out_w^T + out_b))  -> NCHW fp32
    gemm_bf16<2><<<dim3(2, MT), 256, smem>>>(
        shi, slo, whi + 640*256, wlo + 640*256, out_b, nullptr,
        bn2_g, bn2_b, bn2_m, bn2_v, (float*)d_out, nullptr, nullptr, nullptr);
}

// round 10
// speedup vs baseline: 1.4898x; 1.2233x over previous
#include <cuda_runtime.h>
#include <cuda_fp16.h>
#include <cstdint>
#include <math.h>

// ---------------- problem constants ----------------
#define NTOT 4
#define CHN  256
#define HSZ  128
#define WSZ  128
#define HWSZ 16384
#define MTOT 65536
#define KTAP 9
#define EPSV 1e-5f
#define OMSP 128

typedef __half fp16;

// ---------------- scratch ----------------
__device__ fp16  g_xh[MTOT*CHN];                     // x transposed, fp16
__device__ fp16  g_yh[MTOT*CHN];                     // y fp16
__device__ fp16  g_sh[MTOT*CHN];                     // sampled fp16
__device__ float g_v [MTOT*CHN];                     // value proj fp32
__device__ float g_om[MTOT*OMSP];                    // offsets+masks
__device__ fp16  g_whi[896*CHN], g_wlo[896*CHN];     // weights hi/lo fp16

// ---------------- helpers ----------------
__device__ __forceinline__ uint32_t smem_u32(const void* p){
    uint32_t a;
    asm("{ .reg .u64 t; cvta.to.shared.u64 t, %1; cvt.u32.u64 %0, t; }" : "=r"(a) : "l"(p));
    return a;
}
__device__ __forceinline__ void cpasync16(uint32_t dst, const void* src){
    asm volatile("cp.async.cg.shared.global [%0], [%1], 16;"
                 :: "r"(dst), "l"(src) : "memory");
}
#define CP_COMMIT()  asm volatile("cp.async.commit_group;" ::: "memory")
#define CP_WAIT(n)   asm volatile("cp.async.wait_group %0;" :: "n"(n) : "memory")

__device__ __forceinline__ void ldsm4(uint32_t& a0, uint32_t& a1, uint32_t& a2,
                                      uint32_t& a3, uint32_t addr){
    asm volatile("ldmatrix.sync.aligned.m8n8.x4.shared.b16 {%0,%1,%2,%3}, [%4];"
                 : "=r"(a0), "=r"(a1), "=r"(a2), "=r"(a3) : "r"(addr));
}
__device__ __forceinline__ void ldsm2(uint32_t& b0, uint32_t& b1, uint32_t addr){
    asm volatile("ldmatrix.sync.aligned.m8n8.x2.shared.b16 {%0,%1}, [%2];"
                 : "=r"(b0), "=r"(b1) : "r"(addr));
}
__device__ __forceinline__ void mma16816(float* c, const uint32_t* a,
                                         const uint32_t* b){
    asm volatile(
        "mma.sync.aligned.m16n8k16.row.col.f32.f16.f16.f32 "
        "{%0,%1,%2,%3}, {%4,%5,%6,%7}, {%8,%9}, {%0,%1,%2,%3};"
        : "+f"(c[0]), "+f"(c[1]), "+f"(c[2]), "+f"(c[3])
        : "r"(a[0]), "r"(a[1]), "r"(a[2]), "r"(a[3]), "r"(b[0]), "r"(b[1]));
}
__device__ __forceinline__ uint32_t pack2h(fp16 a, fp16 b){
    __half2 h; h.x = a; h.y = b;
    return *reinterpret_cast<uint32_t*>(&h);
}
__device__ __forceinline__ uint32_t swz(int r, int c){
    return (uint32_t)(r * 64 + ((c ^ ((r >> 1) & 3)) * 16));
}
__device__ __forceinline__ float silu_f(float x){
    return x / (1.f + __expf(-x));
}

// ---------------------------------------------------------------------------
// Weight split (rows: 0-255 conv | 256-511 value | 512-639 offset | 640-895 out)
// fp16 hi + fp16 residual lo.
// ---------------------------------------------------------------------------
__global__ __launch_bounds__(256)
void w_split(const float* __restrict__ conv_w, const float* __restrict__ value_w,
             const float* __restrict__ offset_w, const float* __restrict__ out_w,
             fp16* __restrict__ whi, fp16* __restrict__ wlo)
{
    int idx = blockIdx.x * 256 + threadIdx.x;
    if (idx >= 896 * 256) return;
    int r = idx >> 8, c = idx & 255;
    float v = 0.f;
    if      (r < 256) v = conv_w[r * 256 + c];
    else if (r < 512) v = value_w[(r - 256) * 256 + c];
    else if (r < 640) { int rr = r - 512; if (rr < 112) v = offset_w[rr * 256 + c]; }
    else              v = out_w[(r - 640) * 256 + c];
    fp16 h = __float2half_rn(v);
    whi[idx] = h;
    wlo[idx] = __float2half_rn(v - __half2float(h));
}

// ---------------------------------------------------------------------------
// x prepass: NCHW fp32 -> NHWC fp16
// ---------------------------------------------------------------------------
__global__ __launch_bounds__(256)
void x_split(const float* __restrict__ x, fp16* __restrict__ xh)
{
    __shared__ float t[32][129];
    const int tid = threadIdx.x;
    const int n = blockIdx.z, c0 = blockIdx.y * 32, hw0 = blockIdx.x * 128;
    const float* src = x + ((size_t)n * 256 + c0) * HWSZ + hw0;
    #pragma unroll
    for (int i = 0; i < 16; i++) {
        int e = tid + i * 256;
        int c = e >> 7, p = e & 127;
        t[c][p] = src[(size_t)c * HWSZ + p];
    }
    __syncthreads();
    int p = tid >> 1, half = tid & 1;
    size_t base = ((size_t)n * HWSZ + hw0 + p) * 256 + c0 + half * 16;
    fp16 hi[16];
    #pragma unroll
    for (int j = 0; j < 16; j++)
        hi[j] = __float2half_rn(t[half * 16 + j][p]);
    *reinterpret_cast<uint4*>(&xh[base])     = *reinterpret_cast<uint4*>(&hi[0]);
    *reinterpret_cast<uint4*>(&xh[base + 8]) = *reinterpret_cast<uint4*>(&hi[8]);
}

// ---------------------------------------------------------------------------
// fp16 HMMA GEMM: A single-fp16, W hi/lo fp16 -> 2 MMA products per k-step.
// 4-stage cp.async pipeline, 24KB/stage. Grid: x = n-block (L2 A reuse).
//   EPI 1: bn+silu -> fp16 NHWC (y)
//   EPI 2: bias+bn+silu -> fp32 NCHW (final)
//   EPI 3: fused v+om (fp32)
// Tile BM=128, BN=128, 8 warps (2x4), warp 64x32, 2 CTAs/SM.
// ---------------------------------------------------------------------------
template<int EPI>
__global__ __launch_bounds__(256, 2)
void gemm_fp16(const fp16* __restrict__ Ah,
               const fp16* __restrict__ Bhi, const fp16* __restrict__ Blo,
               const float* __restrict__ bias, const float* __restrict__ bias2,
               const float* __restrict__ gamma, const float* __restrict__ beta,
               const float* __restrict__ mean,  const float* __restrict__ var,
               float* __restrict__ Co, float* __restrict__ Co2,
               fp16* __restrict__ CoH)
{
    extern __shared__ __align__(16) char dsm[];
    __shared__ float sSC[128], sSH[128];

    const int tid  = threadIdx.x;
    const int wid  = tid >> 5;
    const int lane = tid & 31;
    const int p0   = blockIdx.y * 128;     // pixel tile (slow)
    const int n0   = blockIdx.x * 128;     // n-block  (fast -> L2 A reuse)

    const uint32_t sb = smem_u32(dsm);
    const int STG = 24576;
    auto AH = [&](int s){ return sb + s * STG + 0;     };
    auto BH = [&](int s){ return sb + s * STG + 8192;  };
    auto BL = [&](int s){ return sb + s * STG + 16384; };

    if (tid < 128) {
        int o = n0 + tid;
        float sc = 1.f, sh = 0.f;
        if (EPI == 1) {
            float s_ = gamma[o] * rsqrtf(var[o] + EPSV);
            sc = s_; sh = beta[o] - mean[o] * s_;
        } else if (EPI == 2) {
            float s_ = gamma[o] * rsqrtf(var[o] + EPSV);
            sc = s_; sh = (beta[o] - mean[o] * s_) + bias[o] * s_;
        } else { // EPI 3
            if (o < 256)            sh = bias[o];
            else if (o - 256 < 112) sh = bias2[o - 256];
        }
        sSC[tid] = sc; sSH[tid] = sh;
    }

    auto load_stage = [&](int kt, int s) {
        #pragma unroll
        for (int i = 0; i < 2; i++) {
            int e = tid + i * 256;
            int r = e >> 2, c = e & 3;
            size_t ao = (size_t)(p0 + r) * 256 + kt + c * 8;
            size_t bo = (size_t)(n0 + r) * 256 + kt + c * 8;
            uint32_t d = swz(r, c);
            cpasync16(AH(s) + d, Ah  + ao);
            cpasync16(BH(s) + d, Bhi + bo);
            cpasync16(BL(s) + d, Blo + bo);
        }
        CP_COMMIT();
    };

    const int wm = (wid >> 2) * 64;
    const int wn = (wid & 3) * 32;

    float acc[4][4][4];
    #pragma unroll
    for (int i = 0; i < 4; i++)
        #pragma unroll
        for (int j = 0; j < 4; j++)
            #pragma unroll
            for (int q = 0; q < 4; q++) acc[i][j][q] = 0.f;

    load_stage(0, 0);
    load_stage(32, 1);
    load_stage(64, 2);

    #pragma unroll 1
    for (int st = 0; st < 8; st++) {
        const int s = st & 3;
        if (st < 6) { CP_WAIT(2); }
        else if (st == 6) { CP_WAIT(1); }
        else { CP_WAIT(0); }
        __syncthreads();

        #pragma unroll
        for (int kk = 0; kk < 2; kk++) {
            const int c0 = kk * 2;
            uint32_t ah[4][4], bh[4][2], bl[4][2];
            #pragma unroll
            for (int mt = 0; mt < 4; mt++) {
                int rr = wm + mt * 16 + (lane & 15);
                int cc = c0 + (lane >> 4);
                ldsm4(ah[mt][0], ah[mt][1], ah[mt][2], ah[mt][3],
                      AH(s) + swz(rr, cc));
            }
            #pragma unroll
            for (int nt = 0; nt < 4; nt++) {
                int rr = wn + nt * 8 + (lane & 7);
                int cc = c0 + ((lane >> 3) & 1);
                uint32_t bd = swz(rr, cc);
                ldsm2(bh[nt][0], bh[nt][1], BH(s) + bd);
                ldsm2(bl[nt][0], bl[nt][1], BL(s) + bd);
            }
            #pragma unroll
            for (int mt = 0; mt < 4; mt++)
                #pragma unroll
                for (int nt = 0; nt < 4; nt++) {
                    mma16816(acc[mt][nt], ah[mt], bh[nt]);
                    mma16816(acc[mt][nt], ah[mt], bl[nt]);
                }
        }
        if (st < 5) load_stage((st + 3) * 32, (st + 3) & 3);
    }

    // ---------------- epilogue ----------------
    const int qr = lane >> 2;
    const int qc = (lane & 3) * 2;
    #pragma unroll
    for (int mt = 0; mt < 4; mt++) {
        #pragma unroll
        for (int nt = 0; nt < 4; nt++) {
            int ocl = wn + nt * 8 + qc;
            int o   = n0 + ocl;
            float sc0 = sSC[ocl],     sh0 = sSH[ocl];
            float sc1 = sSC[ocl + 1], sh1 = sSH[ocl + 1];
            #pragma unroll
            for (int half = 0; half < 2; half++) {
                int p  = p0 + wm + mt * 16 + qr + half * 8;
                float v0 = acc[mt][nt][half * 2 + 0] * sc0 + sh0;
                float v1 = acc[mt][nt][half * 2 + 1] * sc1 + sh1;
                if (EPI == 1 || EPI == 2) {
                    v0 = silu_f(v0);
                    v1 = silu_f(v1);
                }
                if (EPI == 1) {
                    *reinterpret_cast<uint32_t*>(&CoH[(size_t)p * 256 + o]) =
                        pack2h(__float2half_rn(v0), __float2half_rn(v1));
                } else if (EPI == 2) {
                    int n = p >> 14, hw = p & 16383;
                    Co[(((size_t)n * 256 + o)     << 14) + hw] = v0;
                    Co[(((size_t)n * 256 + o + 1) << 14) + hw] = v1;
                } else { // EPI 3
                    if (o < 256) {
                        *reinterpret_cast<float2*>(&Co[(size_t)p * 256 + o]) =
                            make_float2(v0, v1);
                    } else {
                        *reinterpret_cast<float2*>(&Co2[(size_t)p * OMSP + (o - 256)]) =
                            make_float2(v0, v1);
                    }
                }
            }
        }
    }
}

// ---------------------------------------------------------------------------
// DCNv4 sampling (R5 structure): warp = (pixel, 2 groups); lane -> 4 channels.
// Output s as single fp16.
// ---------------------------------------------------------------------------
__global__ __launch_bounds__(256)
void dcn_sample(const float* __restrict__ v, const float* __restrict__ om,
                fp16* __restrict__ sh)
{
    int wrp  = (blockIdx.x * 256 + threadIdx.x) >> 5;
    int lane = threadIdx.x & 31;
    int p = wrp >> 1;
    int g = ((wrp & 1) << 1) + (lane >> 4);
    int laneg = lane & 15;
    int n = p >> 14;
    int hw = p & (HWSZ - 1);
    int h = hw >> 7, w = hw & 127;

    const float* op = om + (size_t)p * OMSP + g * 27;
    const int cb = g * 64 + laneg * 4;
    const int nb = n << 14;

    float a0 = 0.f, a1 = 0.f, a2 = 0.f, a3 = 0.f;
    #pragma unroll
    for (int k = 0; k < KTAP; k++) {
        float ow = op[2 * k];
        float oh = op[2 * k + 1];
        float mk = op[18 + k];
        float lh = (float)(h + k / 3 - 1) + oh;
        float lw = (float)(w + k % 3 - 1) + ow;
        float fh = floorf(lh), fw = floorf(lw);
        int h0 = (int)fh, w0 = (int)fw;
        float dh = lh - fh, dw = lw - fw;
        float w00 = (1.f - dh) * (1.f - dw) * mk;
        float w01 = (1.f - dh) * dw * mk;
        float w10 = dh * (1.f - dw) * mk;
        float w11 = dh * dw * mk;
        bool hv0 = (unsigned)h0 < HSZ;
        bool hv1 = (unsigned)(h0 + 1) < HSZ;
        bool wv0 = (unsigned)w0 < WSZ;
        bool wv1 = (unsigned)(w0 + 1) < WSZ;
        int r0 = (nb + h0 * WSZ + w0) << 8;
        if (hv0 && wv0) { float4 q = *reinterpret_cast<const float4*>(v + r0 + cb);
                          a0 += w00*q.x; a1 += w00*q.y; a2 += w00*q.z; a3 += w00*q.w; }
        if (hv0 && wv1) { float4 q = *reinterpret_cast<const float4*>(v + r0 + 256 + cb);
                          a0 += w01*q.x; a1 += w01*q.y; a2 += w01*q.z; a3 += w01*q.w; }
        if (hv1 && wv0) { float4 q = *reinterpret_cast<const float4*>(v + r0 + (WSZ << 8) + cb);
                          a0 += w10*q.x; a1 += w10*q.y; a2 += w10*q.z; a3 += w10*q.w; }
        if (hv1 && wv1) { float4 q = *reinterpret_cast<const float4*>(v + r0 + ((WSZ + 1) << 8) + cb);
                          a0 += w11*q.x; a1 += w11*q.y; a2 += w11*q.z; a3 += w11*q.w; }
    }
    uint2 hv;
    hv.x = pack2h(__float2half_rn(a0), __float2half_rn(a1));
    hv.y = pack2h(__float2half_rn(a2), __float2half_rn(a3));
    *reinterpret_cast<uint2*>(&sh[(size_t)p * 256 + cb]) = hv;
}

// ---------------------------------------------------------------------------
extern "C" void kernel_launch(void* const* d_in, const int* in_sizes, int n_in,
                              void* d_out, int out_size)
{
    const float* x        = (const float*)d_in[0];
    const float* conv_w   = (const float*)d_in[1];
    const float* bn1_g    = (const float*)d_in[2];
    const float* bn1_b    = (const float*)d_in[3];
    const float* bn1_m    = (const float*)d_in[4];
    const float* bn1_v    = (const float*)d_in[5];
    const float* value_w  = (const float*)d_in[6];
    const float* value_b  = (const float*)d_in[7];
    const float* offset_w = (const float*)d_in[8];
    const float* offset_b = (const float*)d_in[9];
    const float* out_w    = (const float*)d_in[10];
    const float* out_b    = (const float*)d_in[11];
    const float* bn2_g    = (const float*)d_in[12];
    const float* bn2_b    = (const float*)d_in[13];
    const float* bn2_m    = (const float*)d_in[14];
    const float* bn2_v    = (const float*)d_in[15];

    fp16 *xh, *yh, *sh, *whi, *wlo;
    float *v, *omp;
    cudaGetSymbolAddress((void**)&xh,  g_xh);
    cudaGetSymbolAddress((void**)&yh,  g_yh);
    cudaGetSymbolAddress((void**)&sh,  g_sh);
    cudaGetSymbolAddress((void**)&whi, g_whi);
    cudaGetSymbolAddress((void**)&wlo, g_wlo);
    cudaGetSymbolAddress((void**)&v,   g_v);
    cudaGetSymbolAddress((void**)&omp, g_om);

    const int smem = 4 * 24576;   // 96KB, 4 stages
    cudaFuncSetAttribute(gemm_fp16<1>, cudaFuncAttributeMaxDynamicSharedMemorySize, smem);
    cudaFuncSetAttribute(gemm_fp16<2>, cudaFuncAttributeMaxDynamicSharedMemorySize, smem);
    cudaFuncSetAttribute(gemm_fp16<3>, cudaFuncAttributeMaxDynamicSharedMemorySize, smem);

    // prepasses
    w_split<<<896, 256>>>(conv_w, value_w, offset_w, out_w, whi, wlo);
    x_split<<<dim3(128, 8, 4), 256>>>(x, xh);

    const int MT = MTOT / 128;   // 512 pixel tiles

    // grid = (n-blocks, pixel-tiles) — x fastest for L2 A-tile reuse.
    // 1) y = silu(bn1(x @ conv_w^T))           -> y fp16
    gemm_fp16<1><<<dim3(2, MT), 256, smem>>>(
        xh, whi, wlo, nullptr, nullptr,
        bn1_g, bn1_b, bn1_m, bn1_v, nullptr, nullptr, yh);
    // 2) fused: v = y@value_w^T + value_b ; om = y@offset_w^T + offset_b
    gemm_fp16<3><<<dim3(3, MT), 256, smem>>>(
        yh, whi + 256*256, wlo + 256*256, value_b, offset_b,
        nullptr, nullptr, nullptr, nullptr, v, omp, nullptr);
    // 3) deformable sampling -> s fp16
    dcn_sample<<<MTOT / 4, 256>>>(v, omp, sh);
    // 4) out = silu(bn2(s @ out_w^T + out_b))  -> NCHW fp32
    gemm_fp16<2><<<dim3(2, MT), 256, smem>>>(
        sh, whi + 640*256, wlo + 640*256, out_b, nullptr,
        bn2_g, bn2_b, bn2_m, bn2_v, (float*)d_out, nullptr, nullptr);
}

// round 11
// speedup vs baseline: 1.5585x; 1.0461x over previous
#include <cuda_runtime.h>
#include <cuda_fp16.h>
#include <cstdint>
#include <math.h>

// ---------------- problem constants ----------------
#define NTOT 4
#define CHN  256
#define HSZ  128
#define WSZ  128
#define HWSZ 16384
#define MTOT 65536
#define KTAP 9
#define EPSV 1e-5f
#define OMSP 128

typedef __half fp16;

// ---------------- scratch ----------------
__device__ fp16  g_xh[MTOT*CHN];                     // x transposed, fp16
__device__ fp16  g_yh[MTOT*CHN];                     // y fp16
__device__ fp16  g_sh[MTOT*CHN];                     // sampled fp16
__device__ fp16  g_v [MTOT*CHN];                     // value proj fp16
__device__ float g_om[MTOT*OMSP];                    // offsets+masks
__device__ fp16  g_whi[896*CHN], g_wlo[896*CHN];     // weights hi/lo fp16

// ---------------- helpers ----------------
__device__ __forceinline__ uint32_t smem_u32(const void* p){
    uint32_t a;
    asm("{ .reg .u64 t; cvta.to.shared.u64 t, %1; cvt.u32.u64 %0, t; }" : "=r"(a) : "l"(p));
    return a;
}
__device__ __forceinline__ void cpasync16(uint32_t dst, const void* src){
    asm volatile("cp.async.cg.shared.global [%0], [%1], 16;"
                 :: "r"(dst), "l"(src) : "memory");
}
#define CP_COMMIT()  asm volatile("cp.async.commit_group;" ::: "memory")
#define CP_WAIT(n)   asm volatile("cp.async.wait_group %0;" :: "n"(n) : "memory")

__device__ __forceinline__ void ldsm4(uint32_t& a0, uint32_t& a1, uint32_t& a2,
                                      uint32_t& a3, uint32_t addr){
    asm volatile("ldmatrix.sync.aligned.m8n8.x4.shared.b16 {%0,%1,%2,%3}, [%4];"
                 : "=r"(a0), "=r"(a1), "=r"(a2), "=r"(a3) : "r"(addr));
}
__device__ __forceinline__ void ldsm2(uint32_t& b0, uint32_t& b1, uint32_t addr){
    asm volatile("ldmatrix.sync.aligned.m8n8.x2.shared.b16 {%0,%1}, [%2];"
                 : "=r"(b0), "=r"(b1) : "r"(addr));
}
__device__ __forceinline__ void mma16816(float* c, const uint32_t* a,
                                         const uint32_t* b){
    asm volatile(
        "mma.sync.aligned.m16n8k16.row.col.f32.f16.f16.f32 "
        "{%0,%1,%2,%3}, {%4,%5,%6,%7}, {%8,%9}, {%0,%1,%2,%3};"
        : "+f"(c[0]), "+f"(c[1]), "+f"(c[2]), "+f"(c[3])
        : "r"(a[0]), "r"(a[1]), "r"(a[2]), "r"(a[3]), "r"(b[0]), "r"(b[1]));
}
__device__ __forceinline__ uint32_t pack2h(fp16 a, fp16 b){
    __half2 h; h.x = a; h.y = b;
    return *reinterpret_cast<uint32_t*>(&h);
}
__device__ __forceinline__ uint32_t swz(int r, int c){
    return (uint32_t)(r * 64 + ((c ^ ((r >> 1) & 3)) * 16));
}
__device__ __forceinline__ float silu_f(float x){
    return x / (1.f + __expf(-x));
}

// ---------------------------------------------------------------------------
// Weight split (rows: 0-255 conv | 256-511 value | 512-639 offset | 640-895 out)
// ---------------------------------------------------------------------------
__global__ __launch_bounds__(256)
void w_split(const float* __restrict__ conv_w, const float* __restrict__ value_w,
             const float* __restrict__ offset_w, const float* __restrict__ out_w,
             fp16* __restrict__ whi, fp16* __restrict__ wlo)
{
    int idx = blockIdx.x * 256 + threadIdx.x;
    if (idx >= 896 * 256) return;
    int r = idx >> 8, c = idx & 255;
    float v = 0.f;
    if      (r < 256) v = conv_w[r * 256 + c];
    else if (r < 512) v = value_w[(r - 256) * 256 + c];
    else if (r < 640) { int rr = r - 512; if (rr < 112) v = offset_w[rr * 256 + c]; }
    else              v = out_w[(r - 640) * 256 + c];
    fp16 h = __float2half_rn(v);
    whi[idx] = h;
    wlo[idx] = __float2half_rn(v - __half2float(h));
}

// ---------------------------------------------------------------------------
// x prepass: NCHW fp32 -> NHWC fp16
// ---------------------------------------------------------------------------
__global__ __launch_bounds__(256)
void x_split(const float* __restrict__ x, fp16* __restrict__ xh)
{
    __shared__ float t[32][129];
    const int tid = threadIdx.x;
    const int n = blockIdx.z, c0 = blockIdx.y * 32, hw0 = blockIdx.x * 128;
    const float* src = x + ((size_t)n * 256 + c0) * HWSZ + hw0;
    #pragma unroll
    for (int i = 0; i < 16; i++) {
        int e = tid + i * 256;
        int c = e >> 7, p = e & 127;
        t[c][p] = src[(size_t)c * HWSZ + p];
    }
    __syncthreads();
    int p = tid >> 1, half = tid & 1;
    size_t base = ((size_t)n * HWSZ + hw0 + p) * 256 + c0 + half * 16;
    fp16 hi[16];
    #pragma unroll
    for (int j = 0; j < 16; j++)
        hi[j] = __float2half_rn(t[half * 16 + j][p]);
    *reinterpret_cast<uint4*>(&xh[base])     = *reinterpret_cast<uint4*>(&hi[0]);
    *reinterpret_cast<uint4*>(&xh[base + 8]) = *reinterpret_cast<uint4*>(&hi[8]);
}

// ---------------------------------------------------------------------------
// fp16 HMMA GEMM: A single-fp16, W hi/lo fp16 -> 2 MMA products per k-step.
// 4-stage cp.async pipeline. Grid: x = n-block (L2 A reuse).
//   EPI 1: bn+silu -> fp16 NHWC (y)
//   EPI 2: bias+bn+silu -> fp32 NCHW (final)
//   EPI 3: fused: o<256 -> v fp16 (CoH); o>=256 -> om fp32 (Co2)
// ---------------------------------------------------------------------------
template<int EPI>
__global__ __launch_bounds__(256, 2)
void gemm_fp16(const fp16* __restrict__ Ah,
               const fp16* __restrict__ Bhi, const fp16* __restrict__ Blo,
               const float* __restrict__ bias, const float* __restrict__ bias2,
               const float* __restrict__ gamma, const float* __restrict__ beta,
               const float* __restrict__ mean,  const float* __restrict__ var,
               float* __restrict__ Co, float* __restrict__ Co2,
               fp16* __restrict__ CoH)
{
    extern __shared__ __align__(16) char dsm[];
    __shared__ float sSC[128], sSH[128];

    const int tid  = threadIdx.x;
    const int wid  = tid >> 5;
    const int lane = tid & 31;
    const int p0   = blockIdx.y * 128;
    const int n0   = blockIdx.x * 128;

    const uint32_t sb = smem_u32(dsm);
    const int STG = 24576;
    auto AH = [&](int s){ return sb + s * STG + 0;     };
    auto BH = [&](int s){ return sb + s * STG + 8192;  };
    auto BL = [&](int s){ return sb + s * STG + 16384; };

    if (tid < 128) {
        int o = n0 + tid;
        float sc = 1.f, sh = 0.f;
        if (EPI == 1) {
            float s_ = gamma[o] * rsqrtf(var[o] + EPSV);
            sc = s_; sh = beta[o] - mean[o] * s_;
        } else if (EPI == 2) {
            float s_ = gamma[o] * rsqrtf(var[o] + EPSV);
            sc = s_; sh = (beta[o] - mean[o] * s_) + bias[o] * s_;
        } else { // EPI 3
            if (o < 256)            sh = bias[o];
            else if (o - 256 < 112) sh = bias2[o - 256];
        }
        sSC[tid] = sc; sSH[tid] = sh;
    }

    auto load_stage = [&](int kt, int s) {
        #pragma unroll
        for (int i = 0; i < 2; i++) {
            int e = tid + i * 256;
            int r = e >> 2, c = e & 3;
            size_t ao = (size_t)(p0 + r) * 256 + kt + c * 8;
            size_t bo = (size_t)(n0 + r) * 256 + kt + c * 8;
            uint32_t d = swz(r, c);
            cpasync16(AH(s) + d, Ah  + ao);
            cpasync16(BH(s) + d, Bhi + bo);
            cpasync16(BL(s) + d, Blo + bo);
        }
        CP_COMMIT();
    };

    const int wm = (wid >> 2) * 64;
    const int wn = (wid & 3) * 32;

    float acc[4][4][4];
    #pragma unroll
    for (int i = 0; i < 4; i++)
        #pragma unroll
        for (int j = 0; j < 4; j++)
            #pragma unroll
            for (int q = 0; q < 4; q++) acc[i][j][q] = 0.f;

    load_stage(0, 0);
    load_stage(32, 1);
    load_stage(64, 2);

    #pragma unroll 1
    for (int st = 0; st < 8; st++) {
        const int s = st & 3;
        if (st < 6) { CP_WAIT(2); }
        else if (st == 6) { CP_WAIT(1); }
        else { CP_WAIT(0); }
        __syncthreads();

        #pragma unroll
        for (int kk = 0; kk < 2; kk++) {
            const int c0 = kk * 2;
            uint32_t ah[4][4], bh[4][2], bl[4][2];
            #pragma unroll
            for (int mt = 0; mt < 4; mt++) {
                int rr = wm + mt * 16 + (lane & 15);
                int cc = c0 + (lane >> 4);
                ldsm4(ah[mt][0], ah[mt][1], ah[mt][2], ah[mt][3],
                      AH(s) + swz(rr, cc));
            }
            #pragma unroll
            for (int nt = 0; nt < 4; nt++) {
                int rr = wn + nt * 8 + (lane & 7);
                int cc = c0 + ((lane >> 3) & 1);
                uint32_t bd = swz(rr, cc);
                ldsm2(bh[nt][0], bh[nt][1], BH(s) + bd);
                ldsm2(bl[nt][0], bl[nt][1], BL(s) + bd);
            }
            #pragma unroll
            for (int mt = 0; mt < 4; mt++)
                #pragma unroll
                for (int nt = 0; nt < 4; nt++) {
                    mma16816(acc[mt][nt], ah[mt], bh[nt]);
                    mma16816(acc[mt][nt], ah[mt], bl[nt]);
                }
        }
        if (st < 5) load_stage((st + 3) * 32, (st + 3) & 3);
    }

    // ---------------- epilogue ----------------
    const int qr = lane >> 2;
    const int qc = (lane & 3) * 2;
    #pragma unroll
    for (int mt = 0; mt < 4; mt++) {
        #pragma unroll
        for (int nt = 0; nt < 4; nt++) {
            int ocl = wn + nt * 8 + qc;
            int o   = n0 + ocl;
            float sc0 = sSC[ocl],     sh0 = sSH[ocl];
            float sc1 = sSC[ocl + 1], sh1 = sSH[ocl + 1];
            #pragma unroll
            for (int half = 0; half < 2; half++) {
                int p  = p0 + wm + mt * 16 + qr + half * 8;
                float v0 = acc[mt][nt][half * 2 + 0] * sc0 + sh0;
                float v1 = acc[mt][nt][half * 2 + 1] * sc1 + sh1;
                if (EPI == 1 || EPI == 2) {
                    v0 = silu_f(v0);
                    v1 = silu_f(v1);
                }
                if (EPI == 1) {
                    *reinterpret_cast<uint32_t*>(&CoH[(size_t)p * 256 + o]) =
                        pack2h(__float2half_rn(v0), __float2half_rn(v1));
                } else if (EPI == 2) {
                    int n = p >> 14, hw = p & 16383;
                    Co[(((size_t)n * 256 + o)     << 14) + hw] = v0;
                    Co[(((size_t)n * 256 + o + 1) << 14) + hw] = v1;
                } else { // EPI 3
                    if (o < 256) {
                        *reinterpret_cast<uint32_t*>(&CoH[(size_t)p * 256 + o]) =
                            pack2h(__float2half_rn(v0), __float2half_rn(v1));
                    } else {
                        *reinterpret_cast<float2*>(&Co2[(size_t)p * OMSP + (o - 256)]) =
                            make_float2(v0, v1);
                    }
                }
            }
        }
    }
}

// ---------------------------------------------------------------------------
// DCNv4 sampling on fp16 v: warp = (pixel, 2 groups); lane -> 4 channels
// (8B loads). fp32 accumulation, fp16 output.
// ---------------------------------------------------------------------------
__global__ __launch_bounds__(256)
void dcn_sample(const fp16* __restrict__ v, const float* __restrict__ om,
                fp16* __restrict__ sh)
{
    int wrp  = (blockIdx.x * 256 + threadIdx.x) >> 5;
    int lane = threadIdx.x & 31;
    int p = wrp >> 1;
    int g = ((wrp & 1) << 1) + (lane >> 4);
    int laneg = lane & 15;
    int n = p >> 14;
    int hw = p & (HWSZ - 1);
    int h = hw >> 7, w = hw & 127;

    const float* op = om + (size_t)p * OMSP + g * 27;
    const int cb = g * 64 + laneg * 4;
    const fp16* vb = v + ((size_t)n << 22) + cb;

    float a0 = 0.f, a1 = 0.f, a2 = 0.f, a3 = 0.f;
    #pragma unroll
    for (int k = 0; k < KTAP; k++) {
        float ow = op[2 * k];
        float oh = op[2 * k + 1];
        float mk = op[18 + k];
        float lh = (float)(h + k / 3 - 1) + oh;
        float lw = (float)(w + k % 3 - 1) + ow;
        float fh = floorf(lh), fw = floorf(lw);
        int h0 = (int)fh, w0 = (int)fw;
        float dh = lh - fh, dw = lw - fw;
        float w00 = (1.f - dh) * (1.f - dw) * mk;
        float w01 = (1.f - dh) * dw * mk;
        float w10 = dh * (1.f - dw) * mk;
        float w11 = dh * dw * mk;
        bool hv0 = (unsigned)h0 < HSZ;
        bool hv1 = (unsigned)(h0 + 1) < HSZ;
        bool wv0 = (unsigned)w0 < WSZ;
        bool wv1 = (unsigned)(w0 + 1) < WSZ;
        int r0 = (h0 * WSZ + w0) << 8;
        if (hv0 && wv0) {
            uint2 raw = *reinterpret_cast<const uint2*>(vb + r0);
            float2 f01 = __half22float2(*reinterpret_cast<__half2*>(&raw.x));
            float2 f23 = __half22float2(*reinterpret_cast<__half2*>(&raw.y));
            a0 += w00*f01.x; a1 += w00*f01.y; a2 += w00*f23.x; a3 += w00*f23.y;
        }
        if (hv0 && wv1) {
            uint2 raw = *reinterpret_cast<const uint2*>(vb + r0 + 256);
            float2 f01 = __half22float2(*reinterpret_cast<__half2*>(&raw.x));
            float2 f23 = __half22float2(*reinterpret_cast<__half2*>(&raw.y));
            a0 += w01*f01.x; a1 += w01*f01.y; a2 += w01*f23.x; a3 += w01*f23.y;
        }
        if (hv1 && wv0) {
            uint2 raw = *reinterpret_cast<const uint2*>(vb + r0 + (WSZ << 8));
            float2 f01 = __half22float2(*reinterpret_cast<__half2*>(&raw.x));
            float2 f23 = __half22float2(*reinterpret_cast<__half2*>(&raw.y));
            a0 += w10*f01.x; a1 += w10*f01.y; a2 += w10*f23.x; a3 += w10*f23.y;
        }
        if (hv1 && wv1) {
            uint2 raw = *reinterpret_cast<const uint2*>(vb + r0 + ((WSZ + 1) << 8));
            float2 f01 = __half22float2(*reinterpret_cast<__half2*>(&raw.x));
            float2 f23 = __half22float2(*reinterpret_cast<__half2*>(&raw.y));
            a0 += w11*f01.x; a1 += w11*f01.y; a2 += w11*f23.x; a3 += w11*f23.y;
        }
    }
    uint2 hv;
    hv.x = pack2h(__float2half_rn(a0), __float2half_rn(a1));
    hv.y = pack2h(__float2half_rn(a2), __float2half_rn(a3));
    *reinterpret_cast<uint2*>(&sh[(size_t)p * 256 + cb]) = hv;
}

// ---------------------------------------------------------------------------
extern "C" void kernel_launch(void* const* d_in, const int* in_sizes, int n_in,
                              void* d_out, int out_size)
{
    const float* x        = (const float*)d_in[0];
    const float* conv_w   = (const float*)d_in[1];
    const float* bn1_g    = (const float*)d_in[2];
    const float* bn1_b    = (const float*)d_in[3];
    const float* bn1_m    = (const float*)d_in[4];
    const float* bn1_v    = (const float*)d_in[5];
    const float* value_w  = (const float*)d_in[6];
    const float* value_b  = (const float*)d_in[7];
    const float* offset_w = (const float*)d_in[8];
    const float* offset_b = (const float*)d_in[9];
    const float* out_w    = (const float*)d_in[10];
    const float* out_b    = (const float*)d_in[11];
    const float* bn2_g    = (const float*)d_in[12];
    const float* bn2_b    = (const float*)d_in[13];
    const float* bn2_m    = (const float*)d_in[14];
    const float* bn2_v    = (const float*)d_in[15];

    fp16 *xh, *yh, *sh, *vv, *whi, *wlo;
    float *omp;
    cudaGetSymbolAddress((void**)&xh,  g_xh);
    cudaGetSymbolAddress((void**)&yh,  g_yh);
    cudaGetSymbolAddress((void**)&sh,  g_sh);
    cudaGetSymbolAddress((void**)&vv,  g_v);
    cudaGetSymbolAddress((void**)&whi, g_whi);
    cudaGetSymbolAddress((void**)&wlo, g_wlo);
    cudaGetSymbolAddress((void**)&omp, g_om);

    const int smem = 4 * 24576;   // 96KB, 4 stages
    cudaFuncSetAttribute(gemm_fp16<1>, cudaFuncAttributeMaxDynamicSharedMemorySize, smem);
    cudaFuncSetAttribute(gemm_fp16<2>, cudaFuncAttributeMaxDynamicSharedMemorySize, smem);
    cudaFuncSetAttribute(gemm_fp16<3>, cudaFuncAttributeMaxDynamicSharedMemorySize, smem);

    // prepasses
    w_split<<<896, 256>>>(conv_w, value_w, offset_w, out_w, whi, wlo);
    x_split<<<dim3(128, 8, 4), 256>>>(x, xh);

    const int MT = MTOT / 128;   // 512 pixel tiles

    // 1) y = silu(bn1(x @ conv_w^T))           -> y fp16
    gemm_fp16<1><<<dim3(2, MT), 256, smem>>>(
        xh, whi, wlo, nullptr, nullptr,
        bn1_g, bn1_b, bn1_m, bn1_v, nullptr, nullptr, yh);
    // 2) fused: v (fp16) = y@value_w^T + value_b ; om (fp32) = y@offset_w^T + offset_b
    gemm_fp16<3><<<dim3(3, MT), 256, smem>>>(
        yh, whi + 256*256, wlo + 256*256, value_b, offset_b,
        nullptr, nullptr, nullptr, nullptr, nullptr, omp, vv);
    // 3) deformable sampling (fp16 v) -> s fp16
    dcn_sample<<<MTOT / 4, 256>>>(vv, omp, sh);
    // 4) out = silu(bn2(s @ out_w^T + out_b))  -> NCHW fp32
    gemm_fp16<2><<<dim3(2, MT), 256, smem>>>(
        sh, whi + 640*256, wlo + 640*256, out_b, nullptr,
        bn2_g, bn2_b, bn2_m, bn2_v, (float*)d_out, nullptr, nullptr);
}

// round 12
// speedup vs baseline: 1.6812x; 1.0787x over previous
#include <cuda_runtime.h>
#include <cuda_fp16.h>
#include <cstdint>
#include <math.h>

// ---------------- problem constants ----------------
#define NTOT 4
#define CHN  256
#define HSZ  128
#define WSZ  128
#define HWSZ 16384
#define MTOT 65536
#define KTAP 9
#define EPSV 1e-5f
#define OMSP 128

typedef __half fp16;

// ---------------- scratch ----------------
__device__ fp16  g_xh[MTOT*CHN];                     // x transposed, fp16
__device__ fp16  g_yh[MTOT*CHN];                     // y fp16
__device__ fp16  g_sh[MTOT*CHN];                     // sampled fp16
__device__ fp16  g_v [MTOT*CHN];                     // value proj fp16
__device__ float g_om[MTOT*OMSP];                    // offsets+masks
__device__ fp16  g_whi[896*CHN], g_wlo[896*CHN];     // weights hi/lo fp16

// ---------------- helpers ----------------
__device__ __forceinline__ uint32_t smem_u32(const void* p){
    uint32_t a;
    asm("{ .reg .u64 t; cvta.to.shared.u64 t, %1; cvt.u32.u64 %0, t; }" : "=r"(a) : "l"(p));
    return a;
}
__device__ __forceinline__ void cpasync16(uint32_t dst, const void* src){
    asm volatile("cp.async.cg.shared.global [%0], [%1], 16;"
                 :: "r"(dst), "l"(src) : "memory");
}
#define CP_COMMIT()  asm volatile("cp.async.commit_group;" ::: "memory")
#define CP_WAIT(n)   asm volatile("cp.async.wait_group %0;" :: "n"(n) : "memory")

__device__ __forceinline__ void ldsm4(uint32_t& a0, uint32_t& a1, uint32_t& a2,
                                      uint32_t& a3, uint32_t addr){
    asm volatile("ldmatrix.sync.aligned.m8n8.x4.shared.b16 {%0,%1,%2,%3}, [%4];"
                 : "=r"(a0), "=r"(a1), "=r"(a2), "=r"(a3) : "r"(addr));
}
__device__ __forceinline__ void ldsm2(uint32_t& b0, uint32_t& b1, uint32_t addr){
    asm volatile("ldmatrix.sync.aligned.m8n8.x2.shared.b16 {%0,%1}, [%2];"
                 : "=r"(b0), "=r"(b1) : "r"(addr));
}
__device__ __forceinline__ void mma16816(float* c, const uint32_t* a,
                                         const uint32_t* b){
    asm volatile(
        "mma.sync.aligned.m16n8k16.row.col.f32.f16.f16.f32 "
        "{%0,%1,%2,%3}, {%4,%5,%6,%7}, {%8,%9}, {%0,%1,%2,%3};"
        : "+f"(c[0]), "+f"(c[1]), "+f"(c[2]), "+f"(c[3])
        : "r"(a[0]), "r"(a[1]), "r"(a[2]), "r"(a[3]), "r"(b[0]), "r"(b[1]));
}
__device__ __forceinline__ uint32_t pack2h(fp16 a, fp16 b){
    __half2 h; h.x = a; h.y = b;
    return *reinterpret_cast<uint32_t*>(&h);
}
__device__ __forceinline__ uint32_t swz(int r, int c){
    return (uint32_t)(r * 64 + ((c ^ ((r >> 1) & 3)) * 16));
}
__device__ __forceinline__ float silu_f(float x){
    return x / (1.f + __expf(-x));
}

// ---------------------------------------------------------------------------
// Weight split (rows: 0-255 conv | 256-511 value | 512-639 offset | 640-895 out)
// ---------------------------------------------------------------------------
__global__ __launch_bounds__(256)
void w_split(const float* __restrict__ conv_w, const float* __restrict__ value_w,
             const float* __restrict__ offset_w, const float* __restrict__ out_w,
             fp16* __restrict__ whi, fp16* __restrict__ wlo)
{
    int idx = blockIdx.x * 256 + threadIdx.x;
    if (idx >= 896 * 256) return;
    int r = idx >> 8, c = idx & 255;
    float v = 0.f;
    if      (r < 256) v = conv_w[r * 256 + c];
    else if (r < 512) v = value_w[(r - 256) * 256 + c];
    else if (r < 640) { int rr = r - 512; if (rr < 112) v = offset_w[rr * 256 + c]; }
    else              v = out_w[(r - 640) * 256 + c];
    fp16 h = __float2half_rn(v);
    whi[idx] = h;
    wlo[idx] = __float2half_rn(v - __half2float(h));
}

// ---------------------------------------------------------------------------
// x prepass: NCHW fp32 -> NHWC fp16
// ---------------------------------------------------------------------------
__global__ __launch_bounds__(256)
void x_split(const float* __restrict__ x, fp16* __restrict__ xh)
{
    __shared__ float t[32][129];
    const int tid = threadIdx.x;
    const int n = blockIdx.z, c0 = blockIdx.y * 32, hw0 = blockIdx.x * 128;
    const float* src = x + ((size_t)n * 256 + c0) * HWSZ + hw0;
    #pragma unroll
    for (int i = 0; i < 16; i++) {
        int e = tid + i * 256;
        int c = e >> 7, p = e & 127;
        t[c][p] = src[(size_t)c * HWSZ + p];
    }
    __syncthreads();
    int p = tid >> 1, half = tid & 1;
    size_t base = ((size_t)n * HWSZ + hw0 + p) * 256 + c0 + half * 16;
    fp16 hi[16];
    #pragma unroll
    for (int j = 0; j < 16; j++)
        hi[j] = __float2half_rn(t[half * 16 + j][p]);
    *reinterpret_cast<uint4*>(&xh[base])     = *reinterpret_cast<uint4*>(&hi[0]);
    *reinterpret_cast<uint4*>(&xh[base + 8]) = *reinterpret_cast<uint4*>(&hi[8]);
}

// ---------------------------------------------------------------------------
// fp16 HMMA GEMM: A single-fp16, W hi(+lo) fp16 -> NP MMA products per k-step.
// 4-stage cp.async pipeline. Grid: x = n-block (L2 A reuse).
//   EPI 1: bn+silu -> fp16 NHWC (y)
//   EPI 2: bias+bn+silu -> fp32 NCHW (final)
//   EPI 3: fused: o<256 -> v fp16 (CoH); o>=256 -> om fp32 (Co2)
//   NP  : 2 = hi+lo weight products, 1 = hi only (gemm<3>: v is fp16-rounded
//         anyway and om error is second-order, so lo adds nothing there)
// ---------------------------------------------------------------------------
template<int EPI, int NP>
__global__ __launch_bounds__(256, 2)
void gemm_fp16(const fp16* __restrict__ Ah,
               const fp16* __restrict__ Bhi, const fp16* __restrict__ Blo,
               const float* __restrict__ bias, const float* __restrict__ bias2,
               const float* __restrict__ gamma, const float* __restrict__ beta,
               const float* __restrict__ mean,  const float* __restrict__ var,
               float* __restrict__ Co, float* __restrict__ Co2,
               fp16* __restrict__ CoH)
{
    extern __shared__ __align__(16) char dsm[];
    __shared__ float sSC[128], sSH[128];

    const int tid  = threadIdx.x;
    const int wid  = tid >> 5;
    const int lane = tid & 31;
    const int p0   = blockIdx.y * 128;
    const int n0   = blockIdx.x * 128;

    const uint32_t sb = smem_u32(dsm);
    constexpr int STG = (NP == 2) ? 24576 : 16384;
    auto AH = [&](int s){ return sb + s * STG + 0;     };
    auto BH = [&](int s){ return sb + s * STG + 8192;  };
    auto BL = [&](int s){ return sb + s * STG + 16384; };

    if (tid < 128) {
        int o = n0 + tid;
        float sc = 1.f, sh = 0.f;
        if (EPI == 1) {
            float s_ = gamma[o] * rsqrtf(var[o] + EPSV);
            sc = s_; sh = beta[o] - mean[o] * s_;
        } else if (EPI == 2) {
            float s_ = gamma[o] * rsqrtf(var[o] + EPSV);
            sc = s_; sh = (beta[o] - mean[o] * s_) + bias[o] * s_;
        } else { // EPI 3
            if (o < 256)            sh = bias[o];
            else if (o - 256 < 112) sh = bias2[o - 256];
        }
        sSC[tid] = sc; sSH[tid] = sh;
    }

    auto load_stage = [&](int kt, int s) {
        #pragma unroll
        for (int i = 0; i < 2; i++) {
            int e = tid + i * 256;
            int r = e >> 2, c = e & 3;
            size_t ao = (size_t)(p0 + r) * 256 + kt + c * 8;
            size_t bo = (size_t)(n0 + r) * 256 + kt + c * 8;
            uint32_t d = swz(r, c);
            cpasync16(AH(s) + d, Ah  + ao);
            cpasync16(BH(s) + d, Bhi + bo);
            if (NP == 2) cpasync16(BL(s) + d, Blo + bo);
        }
        CP_COMMIT();
    };

    const int wm = (wid >> 2) * 64;
    const int wn = (wid & 3) * 32;

    float acc[4][4][4];
    #pragma unroll
    for (int i = 0; i < 4; i++)
        #pragma unroll
        for (int j = 0; j < 4; j++)
            #pragma unroll
            for (int q = 0; q < 4; q++) acc[i][j][q] = 0.f;

    load_stage(0, 0);
    load_stage(32, 1);
    load_stage(64, 2);

    #pragma unroll 1
    for (int st = 0; st < 8; st++) {
        const int s = st & 3;
        if (st < 6) { CP_WAIT(2); }
        else if (st == 6) { CP_WAIT(1); }
        else { CP_WAIT(0); }
        __syncthreads();

        #pragma unroll
        for (int kk = 0; kk < 2; kk++) {
            const int c0 = kk * 2;
            uint32_t ah[4][4], bh[4][2], bl[4][2];
            #pragma unroll
            for (int mt = 0; mt < 4; mt++) {
                int rr = wm + mt * 16 + (lane & 15);
                int cc = c0 + (lane >> 4);
                ldsm4(ah[mt][0], ah[mt][1], ah[mt][2], ah[mt][3],
                      AH(s) + swz(rr, cc));
            }
            #pragma unroll
            for (int nt = 0; nt < 4; nt++) {
                int rr = wn + nt * 8 + (lane & 7);
                int cc = c0 + ((lane >> 3) & 1);
                uint32_t bd = swz(rr, cc);
                ldsm2(bh[nt][0], bh[nt][1], BH(s) + bd);
                if (NP == 2) ldsm2(bl[nt][0], bl[nt][1], BL(s) + bd);
            }
            #pragma unroll
            for (int mt = 0; mt < 4; mt++)
                #pragma unroll
                for (int nt = 0; nt < 4; nt++) {
                    mma16816(acc[mt][nt], ah[mt], bh[nt]);
                    if (NP == 2) mma16816(acc[mt][nt], ah[mt], bl[nt]);
                }
        }
        if (st < 5) load_stage((st + 3) * 32, (st + 3) & 3);
    }

    // ---------------- epilogue ----------------
    const int qr = lane >> 2;
    const int qc = (lane & 3) * 2;
    #pragma unroll
    for (int mt = 0; mt < 4; mt++) {
        #pragma unroll
        for (int nt = 0; nt < 4; nt++) {
            int ocl = wn + nt * 8 + qc;
            int o   = n0 + ocl;
            float sc0 = sSC[ocl],     sh0 = sSH[ocl];
            float sc1 = sSC[ocl + 1], sh1 = sSH[ocl + 1];
            #pragma unroll
            for (int half = 0; half < 2; half++) {
                int p  = p0 + wm + mt * 16 + qr + half * 8;
                float v0 = acc[mt][nt][half * 2 + 0] * sc0 + sh0;
                float v1 = acc[mt][nt][half * 2 + 1] * sc1 + sh1;
                if (EPI == 1 || EPI == 2) {
                    v0 = silu_f(v0);
                    v1 = silu_f(v1);
                }
                if (EPI == 1) {
                    *reinterpret_cast<uint32_t*>(&CoH[(size_t)p * 256 + o]) =
                        pack2h(__float2half_rn(v0), __float2half_rn(v1));
                } else if (EPI == 2) {
                    int n = p >> 14, hw = p & 16383;
                    Co[(((size_t)n * 256 + o)     << 14) + hw] = v0;
                    Co[(((size_t)n * 256 + o + 1) << 14) + hw] = v1;
                } else { // EPI 3
                    if (o < 256) {
                        *reinterpret_cast<uint32_t*>(&CoH[(size_t)p * 256 + o]) =
                            pack2h(__float2half_rn(v0), __float2half_rn(v1));
                    } else {
                        *reinterpret_cast<float2*>(&Co2[(size_t)p * OMSP + (o - 256)]) =
                            make_float2(v0, v1);
                    }
                }
            }
        }
    }
}

// ---------------------------------------------------------------------------
// DCNv4 sampling on fp16 v: warp = (pixel, 2 groups); lane -> 4 channels
// (8B loads). fp32 accumulation, fp16 output. (Best-measured variant.)
// ---------------------------------------------------------------------------
__global__ __launch_bounds__(256)
void dcn_sample(const fp16* __restrict__ v, const float* __restrict__ om,
                fp16* __restrict__ sh)
{
    int wrp  = (blockIdx.x * 256 + threadIdx.x) >> 5;
    int lane = threadIdx.x & 31;
    int p = wrp >> 1;
    int g = ((wrp & 1) << 1) + (lane >> 4);
    int laneg = lane & 15;
    int n = p >> 14;
    int hw = p & (HWSZ - 1);
    int h = hw >> 7, w = hw & 127;

    const float* op = om + (size_t)p * OMSP + g * 27;
    const int cb = g * 64 + laneg * 4;
    const fp16* vb = v + ((size_t)n << 22) + cb;

    float a0 = 0.f, a1 = 0.f, a2 = 0.f, a3 = 0.f;
    #pragma unroll
    for (int k = 0; k < KTAP; k++) {
        float ow = op[2 * k];
        float oh = op[2 * k + 1];
        float mk = op[18 + k];
        float lh = (float)(h + k / 3 - 1) + oh;
        float lw = (float)(w + k % 3 - 1) + ow;
        float fh = floorf(lh), fw = floorf(lw);
        int h0 = (int)fh, w0 = (int)fw;
        float dh = lh - fh, dw = lw - fw;
        float w00 = (1.f - dh) * (1.f - dw) * mk;
        float w01 = (1.f - dh) * dw * mk;
        float w10 = dh * (1.f - dw) * mk;
        float w11 = dh * dw * mk;
        bool hv0 = (unsigned)h0 < HSZ;
        bool hv1 = (unsigned)(h0 + 1) < HSZ;
        bool wv0 = (unsigned)w0 < WSZ;
        bool wv1 = (unsigned)(w0 + 1) < WSZ;
        int r0 = (h0 * WSZ + w0) << 8;
        if (hv0 && wv0) {
            uint2 raw = *reinterpret_cast<const uint2*>(vb + r0);
            float2 f01 = __half22float2(*reinterpret_cast<__half2*>(&raw.x));
            float2 f23 = __half22float2(*reinterpret_cast<__half2*>(&raw.y));
            a0 += w00*f01.x; a1 += w00*f01.y; a2 += w00*f23.x; a3 += w00*f23.y;
        }
        if (hv0 && wv1) {
            uint2 raw = *reinterpret_cast<const uint2*>(vb + r0 + 256);
            float2 f01 = __half22float2(*reinterpret_cast<__half2*>(&raw.x));
            float2 f23 = __half22float2(*reinterpret_cast<__half2*>(&raw.y));
            a0 += w01*f01.x; a1 += w01*f01.y; a2 += w01*f23.x; a3 += w01*f23.y;
        }
        if (hv1 && wv0) {
            uint2 raw = *reinterpret_cast<const uint2*>(vb + r0 + (WSZ << 8));
            float2 f01 = __half22float2(*reinterpret_cast<__half2*>(&raw.x));
            float2 f23 = __half22float2(*reinterpret_cast<__half2*>(&raw.y));
            a0 += w10*f01.x; a1 += w10*f01.y; a2 += w10*f23.x; a3 += w10*f23.y;
        }
        if (hv1 && wv1) {
            uint2 raw = *reinterpret_cast<const uint2*>(vb + r0 + ((WSZ + 1) << 8));
            float2 f01 = __half22float2(*reinterpret_cast<__half2*>(&raw.x));
            float2 f23 = __half22float2(*reinterpret_cast<__half2*>(&raw.y));
            a0 += w11*f01.x; a1 += w11*f01.y; a2 += w11*f23.x; a3 += w11*f23.y;
        }
    }
    uint2 hv;
    hv.x = pack2h(__float2half_rn(a0), __float2half_rn(a1));
    hv.y = pack2h(__float2half_rn(a2), __float2half_rn(a3));
    *reinterpret_cast<uint2*>(&sh[(size_t)p * 256 + cb]) = hv;
}

// ---------------------------------------------------------------------------
extern "C" void kernel_launch(void* const* d_in, const int* in_sizes, int n_in,
                              void* d_out, int out_size)
{
    const float* x        = (const float*)d_in[0];
    const float* conv_w   = (const float*)d_in[1];
    const float* bn1_g    = (const float*)d_in[2];
    const float* bn1_b    = (const float*)d_in[3];
    const float* bn1_m    = (const float*)d_in[4];
    const float* bn1_v    = (const float*)d_in[5];
    const float* value_w  = (const float*)d_in[6];
    const float* value_b  = (const float*)d_in[7];
    const float* offset_w = (const float*)d_in[8];
    const float* offset_b = (const float*)d_in[9];
    const float* out_w    = (const float*)d_in[10];
    const float* out_b    = (const float*)d_in[11];
    const float* bn2_g    = (const float*)d_in[12];
    const float* bn2_b    = (const float*)d_in[13];
    const float* bn2_m    = (const float*)d_in[14];
    const float* bn2_v    = (const float*)d_in[15];

    fp16 *xh, *yh, *sh, *vv, *whi, *wlo;
    float *omp;
    cudaGetSymbolAddress((void**)&xh,  g_xh);
    cudaGetSymbolAddress((void**)&yh,  g_yh);
    cudaGetSymbolAddress((void**)&sh,  g_sh);
    cudaGetSymbolAddress((void**)&vv,  g_v);
    cudaGetSymbolAddress((void**)&whi, g_whi);
    cudaGetSymbolAddress((void**)&wlo, g_wlo);
    cudaGetSymbolAddress((void**)&omp, g_om);

    const int smem2 = 4 * 24576;   // 96KB, NP=2
    const int smem1 = 4 * 16384;   // 64KB, NP=1
    cudaFuncSetAttribute(gemm_fp16<1,2>, cudaFuncAttributeMaxDynamicSharedMemorySize, smem2);
    cudaFuncSetAttribute(gemm_fp16<2,2>, cudaFuncAttributeMaxDynamicSharedMemorySize, smem2);
    cudaFuncSetAttribute(gemm_fp16<3,1>, cudaFuncAttributeMaxDynamicSharedMemorySize, smem1);

    // prepasses
    w_split<<<896, 256>>>(conv_w, value_w, offset_w, out_w, whi, wlo);
    x_split<<<dim3(128, 8, 4), 256>>>(x, xh);

    const int MT = MTOT / 128;   // 512 pixel tiles

    // 1) y = silu(bn1(x @ conv_w^T))           -> y fp16   (hi+lo)
    gemm_fp16<1,2><<<dim3(2, MT), 256, smem2>>>(
        xh, whi, wlo, nullptr, nullptr,
        bn1_g, bn1_b, bn1_m, bn1_v, nullptr, nullptr, yh);
    // 2) fused: v (fp16) = y@value_w^T + b ; om (fp32) = y@offset_w^T + b  (hi only)
    gemm_fp16<3,1><<<dim3(3, MT), 256, smem1>>>(
        yh, whi + 256*256, nullptr, value_b, offset_b,
        nullptr, nullptr, nullptr, nullptr, nullptr, omp, vv);
    // 3) deformable sampling (fp16 v) -> s fp16
    dcn_sample<<<MTOT / 4, 256>>>(vv, omp, sh);
    // 4) out = silu(bn2(s @ out_w^T + out_b))  -> NCHW fp32   (hi+lo)
    gemm_fp16<2,2><<<dim3(2, MT), 256, smem2>>>(
        sh, whi + 640*256, wlo + 640*256, out_b, nullptr,
        bn2_g, bn2_b, bn2_m, bn2_v, (float*)d_out, nullptr, nullptr);
}

// round 13
// speedup vs baseline: 1.9162x; 1.1398x over previous
#include <cuda_runtime.h>
#include <cuda_fp16.h>
#include <cstdint>
#include <math.h>

// ---------------- problem constants ----------------
#define NTOT 4
#define CHN  256
#define HSZ  128
#define WSZ  128
#define HWSZ 16384
#define MTOT 65536
#define KTAP 9
#define EPSV 1e-5f
#define OMSP 128

typedef __half fp16;

// ---------------- scratch ----------------
__device__ fp16  g_xh[MTOT*CHN];                     // x transposed, fp16
__device__ fp16  g_yh[MTOT*CHN];                     // y fp16
__device__ fp16  g_sh[MTOT*CHN];                     // sampled fp16
__device__ fp16  g_v [MTOT*CHN];                     // value proj fp16
__device__ float g_om[MTOT*OMSP];                    // offsets+masks
__device__ fp16  g_whi[896*CHN], g_wlo[896*CHN];     // weights hi/lo fp16

// ---------------- helpers ----------------
__device__ __forceinline__ uint32_t smem_u32(const void* p){
    uint32_t a;
    asm("{ .reg .u64 t; cvta.to.shared.u64 t, %1; cvt.u32.u64 %0, t; }" : "=r"(a) : "l"(p));
    return a;
}
__device__ __forceinline__ void cpasync16(uint32_t dst, const void* src){
    asm volatile("cp.async.cg.shared.global [%0], [%1], 16;"
                 :: "r"(dst), "l"(src) : "memory");
}
#define CP_COMMIT()  asm volatile("cp.async.commit_group;" ::: "memory")
#define CP_WAIT(n)   asm volatile("cp.async.wait_group %0;" :: "n"(n) : "memory")

__device__ __forceinline__ void ldsm4(uint32_t& a0, uint32_t& a1, uint32_t& a2,
                                      uint32_t& a3, uint32_t addr){
    asm volatile("ldmatrix.sync.aligned.m8n8.x4.shared.b16 {%0,%1,%2,%3}, [%4];"
                 : "=r"(a0), "=r"(a1), "=r"(a2), "=r"(a3) : "r"(addr));
}
__device__ __forceinline__ void ldsm2(uint32_t& b0, uint32_t& b1, uint32_t addr){
    asm volatile("ldmatrix.sync.aligned.m8n8.x2.shared.b16 {%0,%1}, [%2];"
                 : "=r"(b0), "=r"(b1) : "r"(addr));
}
__device__ __forceinline__ void mma16816(float* c, const uint32_t* a,
                                         const uint32_t* b){
    asm volatile(
        "mma.sync.aligned.m16n8k16.row.col.f32.f16.f16.f32 "
        "{%0,%1,%2,%3}, {%4,%5,%6,%7}, {%8,%9}, {%0,%1,%2,%3};"
        : "+f"(c[0]), "+f"(c[1]), "+f"(c[2]), "+f"(c[3])
        : "r"(a[0]), "r"(a[1]), "r"(a[2]), "r"(a[3]), "r"(b[0]), "r"(b[1]));
}
__device__ __forceinline__ uint32_t pack2h(fp16 a, fp16 b){
    __half2 h; h.x = a; h.y = b;
    return *reinterpret_cast<uint32_t*>(&h);
}
__device__ __forceinline__ uint32_t swz(int r, int c){
    return (uint32_t)(r * 64 + ((c ^ ((r >> 1) & 3)) * 16));
}
__device__ __forceinline__ float silu_f(float x){
    return x / (1.f + __expf(-x));
}

// ---------------------------------------------------------------------------
// Weight split (rows: 0-255 conv | 256-511 value | 512-639 offset | 640-895 out)
// ---------------------------------------------------------------------------
__global__ __launch_bounds__(256)
void w_split(const float* __restrict__ conv_w, const float* __restrict__ value_w,
             const float* __restrict__ offset_w, const float* __restrict__ out_w,
             fp16* __restrict__ whi, fp16* __restrict__ wlo)
{
    int idx = blockIdx.x * 256 + threadIdx.x;
    if (idx >= 896 * 256) return;
    int r = idx >> 8, c = idx & 255;
    float v = 0.f;
    if      (r < 256) v = conv_w[r * 256 + c];
    else if (r < 512) v = value_w[(r - 256) * 256 + c];
    else if (r < 640) { int rr = r - 512; if (rr < 112) v = offset_w[rr * 256 + c]; }
    else              v = out_w[(r - 640) * 256 + c];
    fp16 h = __float2half_rn(v);
    whi[idx] = h;
    wlo[idx] = __float2half_rn(v - __half2float(h));
}

// ---------------------------------------------------------------------------
// x prepass: NCHW fp32 -> NHWC fp16
// ---------------------------------------------------------------------------
__global__ __launch_bounds__(256)
void x_split(const float* __restrict__ x, fp16* __restrict__ xh)
{
    __shared__ float t[32][129];
    const int tid = threadIdx.x;
    const int n = blockIdx.z, c0 = blockIdx.y * 32, hw0 = blockIdx.x * 128;
    const float* src = x + ((size_t)n * 256 + c0) * HWSZ + hw0;
    #pragma unroll
    for (int i = 0; i < 16; i++) {
        int e = tid + i * 256;
        int c = e >> 7, p = e & 127;
        t[c][p] = src[(size_t)c * HWSZ + p];
    }
    __syncthreads();
    int p = tid >> 1, half = tid & 1;
    size_t base = ((size_t)n * HWSZ + hw0 + p) * 256 + c0 + half * 16;
    fp16 hi[16];
    #pragma unroll
    for (int j = 0; j < 16; j++)
        hi[j] = __float2half_rn(t[half * 16 + j][p]);
    *reinterpret_cast<uint4*>(&xh[base])     = *reinterpret_cast<uint4*>(&hi[0]);
    *reinterpret_cast<uint4*>(&xh[base + 8]) = *reinterpret_cast<uint4*>(&hi[8]);
}

// ---------------------------------------------------------------------------
// fp16 HMMA GEMM: A single-fp16, W hi(+lo) fp16 -> NP MMA products per k-step.
// 4-stage cp.async pipeline. Grid: x = n-block (L2 A reuse).
//   EPI 1: bn+silu -> fp16 NHWC (y)
//   EPI 2: bias+bn+silu -> fp32 NCHW (final)
//   EPI 3: fused: o<256 -> v fp16 (CoH); o>=256 -> om fp32 (Co2)
// ---------------------------------------------------------------------------
template<int EPI, int NP>
__global__ __launch_bounds__(256, 2)
void gemm_fp16(const fp16* __restrict__ Ah,
               const fp16* __restrict__ Bhi, const fp16* __restrict__ Blo,
               const float* __restrict__ bias, const float* __restrict__ bias2,
               const float* __restrict__ gamma, const float* __restrict__ beta,
               const float* __restrict__ mean,  const float* __restrict__ var,
               float* __restrict__ Co, float* __restrict__ Co2,
               fp16* __restrict__ CoH)
{
    extern __shared__ __align__(16) char dsm[];
    __shared__ float sSC[128], sSH[128];

    const int tid  = threadIdx.x;
    const int wid  = tid >> 5;
    const int lane = tid & 31;
    const int p0   = blockIdx.y * 128;
    const int n0   = blockIdx.x * 128;

    const uint32_t sb = smem_u32(dsm);
    constexpr int STG = (NP == 2) ? 24576 : 16384;
    auto AH = [&](int s){ return sb + s * STG + 0;     };
    auto BH = [&](int s){ return sb + s * STG + 8192;  };
    auto BL = [&](int s){ return sb + s * STG + 16384; };

    if (tid < 128) {
        int o = n0 + tid;
        float sc = 1.f, sh = 0.f;
        if (EPI == 1) {
            float s_ = gamma[o] * rsqrtf(var[o] + EPSV);
            sc = s_; sh = beta[o] - mean[o] * s_;
        } else if (EPI == 2) {
            float s_ = gamma[o] * rsqrtf(var[o] + EPSV);
            sc = s_; sh = (beta[o] - mean[o] * s_) + bias[o] * s_;
        } else { // EPI 3
            if (o < 256)            sh = bias[o];
            else if (o - 256 < 112) sh = bias2[o - 256];
        }
        sSC[tid] = sc; sSH[tid] = sh;
    }

    auto load_stage = [&](int kt, int s) {
        #pragma unroll
        for (int i = 0; i < 2; i++) {
            int e = tid + i * 256;
            int r = e >> 2, c = e & 3;
            size_t ao = (size_t)(p0 + r) * 256 + kt + c * 8;
            size_t bo = (size_t)(n0 + r) * 256 + kt + c * 8;
            uint32_t d = swz(r, c);
            cpasync16(AH(s) + d, Ah  + ao);
            cpasync16(BH(s) + d, Bhi + bo);
            if (NP == 2) cpasync16(BL(s) + d, Blo + bo);
        }
        CP_COMMIT();
    };

    const int wm = (wid >> 2) * 64;
    const int wn = (wid & 3) * 32;

    float acc[4][4][4];
    #pragma unroll
    for (int i = 0; i < 4; i++)
        #pragma unroll
        for (int j = 0; j < 4; j++)
            #pragma unroll
            for (int q = 0; q < 4; q++) acc[i][j][q] = 0.f;

    load_stage(0, 0);
    load_stage(32, 1);
    load_stage(64, 2);

    #pragma unroll 1
    for (int st = 0; st < 8; st++) {
        const int s = st & 3;
        if (st < 6) { CP_WAIT(2); }
        else if (st == 6) { CP_WAIT(1); }
        else { CP_WAIT(0); }
        __syncthreads();

        #pragma unroll
        for (int kk = 0; kk < 2; kk++) {
            const int c0 = kk * 2;
            uint32_t ah[4][4], bh[4][2], bl[4][2];
            #pragma unroll
            for (int mt = 0; mt < 4; mt++) {
                int rr = wm + mt * 16 + (lane & 15);
                int cc = c0 + (lane >> 4);
                ldsm4(ah[mt][0], ah[mt][1], ah[mt][2], ah[mt][3],
                      AH(s) + swz(rr, cc));
            }
            #pragma unroll
            for (int nt = 0; nt < 4; nt++) {
                int rr = wn + nt * 8 + (lane & 7);
                int cc = c0 + ((lane >> 3) & 1);
                uint32_t bd = swz(rr, cc);
                ldsm2(bh[nt][0], bh[nt][1], BH(s) + bd);
                if (NP == 2) ldsm2(bl[nt][0], bl[nt][1], BL(s) + bd);
            }
            #pragma unroll
            for (int mt = 0; mt < 4; mt++)
                #pragma unroll
                for (int nt = 0; nt < 4; nt++) {
                    mma16816(acc[mt][nt], ah[mt], bh[nt]);
                    if (NP == 2) mma16816(acc[mt][nt], ah[mt], bl[nt]);
                }
        }
        if (st < 5) load_stage((st + 3) * 32, (st + 3) & 3);
    }

    // ---------------- epilogue ----------------
    const int qr = lane >> 2;
    const int qc = (lane & 3) * 2;
    #pragma unroll
    for (int mt = 0; mt < 4; mt++) {
        #pragma unroll
        for (int nt = 0; nt < 4; nt++) {
            int ocl = wn + nt * 8 + qc;
            int o   = n0 + ocl;
            float sc0 = sSC[ocl],     sh0 = sSH[ocl];
            float sc1 = sSC[ocl + 1], sh1 = sSH[ocl + 1];
            #pragma unroll
            for (int half = 0; half < 2; half++) {
                int p  = p0 + wm + mt * 16 + qr + half * 8;
                float v0 = acc[mt][nt][half * 2 + 0] * sc0 + sh0;
                float v1 = acc[mt][nt][half * 2 + 1] * sc1 + sh1;
                if (EPI == 1 || EPI == 2) {
                    v0 = silu_f(v0);
                    v1 = silu_f(v1);
                }
                if (EPI == 1) {
                    *reinterpret_cast<uint32_t*>(&CoH[(size_t)p * 256 + o]) =
                        pack2h(__float2half_rn(v0), __float2half_rn(v1));
                } else if (EPI == 2) {
                    int n = p >> 14, hw = p & 16383;
                    Co[(((size_t)n * 256 + o)     << 14) + hw] = v0;
                    Co[(((size_t)n * 256 + o + 1) << 14) + hw] = v1;
                } else { // EPI 3
                    if (o < 256) {
                        *reinterpret_cast<uint32_t*>(&CoH[(size_t)p * 256 + o]) =
                            pack2h(__float2half_rn(v0), __float2half_rn(v1));
                    } else {
                        *reinterpret_cast<float2*>(&Co2[(size_t)p * OMSP + (o - 256)]) =
                            make_float2(v0, v1);
                    }
                }
            }
        }
    }
}

// ---------------------------------------------------------------------------
// DCNv4 sampling v4: warp = 1 pixel (all 4 groups); lane = (group = lane>>3,
// 8 channels via one 16B uint4 load per corner). Halves warp count and
// per-sample instruction count vs v3; identical per-channel arithmetic.
// ---------------------------------------------------------------------------
__global__ __launch_bounds__(256)
void dcn_sample(const fp16* __restrict__ v, const float* __restrict__ om,
                fp16* __restrict__ sh)
{
    const int p    = (blockIdx.x * 256 + threadIdx.x) >> 5;   // pixel
    const int lane = threadIdx.x & 31;
    const int g    = lane >> 3;
    const int c8   = (lane & 7) * 8;
    const int n  = p >> 14;
    const int hw = p & (HWSZ - 1);
    const int h = hw >> 7, w = hw & 127;

    const float* op = om + (size_t)p * OMSP + g * 27;
    const int cb = g * 64 + c8;
    const fp16* vb = v + ((size_t)n << 22) + cb;

    float a[8] = {};
    #pragma unroll
    for (int k = 0; k < KTAP; k++) {
        float ow = op[2 * k];
        float oh = op[2 * k + 1];
        float mk = op[18 + k];
        float lh = (float)(h + k / 3 - 1) + oh;
        float lw = (float)(w + k % 3 - 1) + ow;
        float fh = floorf(lh), fw = floorf(lw);
        int h0 = (int)fh, w0 = (int)fw;
        float dh = lh - fh, dw = lw - fw;
        float w00 = (1.f - dh) * (1.f - dw) * mk;
        float w01 = (1.f - dh) * dw * mk;
        float w10 = dh * (1.f - dw) * mk;
        float w11 = dh * dw * mk;
        bool hv0 = (unsigned)h0 < HSZ;
        bool hv1 = (unsigned)(h0 + 1) < HSZ;
        bool wv0 = (unsigned)w0 < WSZ;
        bool wv1 = (unsigned)(w0 + 1) < WSZ;
        int r0 = (h0 * WSZ + w0) << 8;

        #define ACC8(OFF, WT) do { \
            uint4 raw = *reinterpret_cast<const uint4*>(vb + (OFF)); \
            float2 f0 = __half22float2(*reinterpret_cast<__half2*>(&raw.x)); \
            float2 f1 = __half22float2(*reinterpret_cast<__half2*>(&raw.y)); \
            float2 f2 = __half22float2(*reinterpret_cast<__half2*>(&raw.z)); \
            float2 f3 = __half22float2(*reinterpret_cast<__half2*>(&raw.w)); \
            a[0] += (WT) * f0.x; a[1] += (WT) * f0.y; \
            a[2] += (WT) * f1.x; a[3] += (WT) * f1.y; \
            a[4] += (WT) * f2.x; a[5] += (WT) * f2.y; \
            a[6] += (WT) * f3.x; a[7] += (WT) * f3.y; \
        } while (0)

        if (hv0 && wv0) ACC8(r0, w00);
        if (hv0 && wv1) ACC8(r0 + 256, w01);
        if (hv1 && wv0) ACC8(r0 + (WSZ << 8), w10);
        if (hv1 && wv1) ACC8(r0 + ((WSZ + 1) << 8), w11);
        #undef ACC8
    }
    uint4 out;
    out.x = pack2h(__float2half_rn(a[0]), __float2half_rn(a[1]));
    out.y = pack2h(__float2half_rn(a[2]), __float2half_rn(a[3]));
    out.z = pack2h(__float2half_rn(a[4]), __float2half_rn(a[5]));
    out.w = pack2h(__float2half_rn(a[6]), __float2half_rn(a[7]));
    *reinterpret_cast<uint4*>(&sh[(size_t)p * 256 + cb]) = out;
}

// ---------------------------------------------------------------------------
extern "C" void kernel_launch(void* const* d_in, const int* in_sizes, int n_in,
                              void* d_out, int out_size)
{
    const float* x        = (const float*)d_in[0];
    const float* conv_w   = (const float*)d_in[1];
    const float* bn1_g    = (const float*)d_in[2];
    const float* bn1_b    = (const float*)d_in[3];
    const float* bn1_m    = (const float*)d_in[4];
    const float* bn1_v    = (const float*)d_in[5];
    const float* value_w  = (const float*)d_in[6];
    const float* value_b  = (const float*)d_in[7];
    const float* offset_w = (const float*)d_in[8];
    const float* offset_b = (const float*)d_in[9];
    const float* out_w    = (const float*)d_in[10];
    const float* out_b    = (const float*)d_in[11];
    const float* bn2_g    = (const float*)d_in[12];
    const float* bn2_b    = (const float*)d_in[13];
    const float* bn2_m    = (const float*)d_in[14];
    const float* bn2_v    = (const float*)d_in[15];

    fp16 *xh, *yh, *sh, *vv, *whi, *wlo;
    float *omp;
    cudaGetSymbolAddress((void**)&xh,  g_xh);
    cudaGetSymbolAddress((void**)&yh,  g_yh);
    cudaGetSymbolAddress((void**)&sh,  g_sh);
    cudaGetSymbolAddress((void**)&vv,  g_v);
    cudaGetSymbolAddress((void**)&whi, g_whi);
    cudaGetSymbolAddress((void**)&wlo, g_wlo);
    cudaGetSymbolAddress((void**)&omp, g_om);

    const int smem2 = 4 * 24576;   // 96KB, NP=2
    const int smem1 = 4 * 16384;   // 64KB, NP=1
    cudaFuncSetAttribute(gemm_fp16<1,2>, cudaFuncAttributeMaxDynamicSharedMemorySize, smem2);
    cudaFuncSetAttribute(gemm_fp16<2,1>, cudaFuncAttributeMaxDynamicSharedMemorySize, smem1);
    cudaFuncSetAttribute(gemm_fp16<3,1>, cudaFuncAttributeMaxDynamicSharedMemorySize, smem1);

    // prepasses
    w_split<<<896, 256>>>(conv_w, value_w, offset_w, out_w, whi, wlo);
    x_split<<<dim3(128, 8, 4), 256>>>(x, xh);

    const int MT = MTOT / 128;   // 512 pixel tiles

    // 1) y = silu(bn1(x @ conv_w^T))           -> y fp16   (hi+lo)
    gemm_fp16<1,2><<<dim3(2, MT), 256, smem2>>>(
        xh, whi, wlo, nullptr, nullptr,
        bn1_g, bn1_b, bn1_m, bn1_v, nullptr, nullptr, yh);
    // 2) fused: v (fp16) = y@value_w^T + b ; om (fp32) = y@offset_w^T + b  (hi only)
    gemm_fp16<3,1><<<dim3(3, MT), 256, smem1>>>(
        yh, whi + 256*256, nullptr, value_b, offset_b,
        nullptr, nullptr, nullptr, nullptr, nullptr, omp, vv);
    // 3) deformable sampling (fp16 v) -> s fp16   (warp = 1 pixel)
    dcn_sample<<<MTOT / 8, 256>>>(vv, omp, sh);
    // 4) out = silu(bn2(s @ out_w^T + out_b))  -> NCHW fp32   (hi only)
    gemm_fp16<2,1><<<dim3(2, MT), 256, smem1>>>(
        sh, whi + 640*256, nullptr, out_b, nullptr,
        bn2_g, bn2_b, bn2_m, bn2_v, (float*)d_out, nullptr, nullptr);
}

// round 14
// speedup vs baseline: 2.0369x; 1.0630x over previous
#include <cuda_runtime.h>
#include <cuda_fp16.h>
#include <cstdint>
#include <math.h>

// ---------------- problem constants ----------------
#define NTOT 4
#define CHN  256
#define HSZ  128
#define WSZ  128
#define HWSZ 16384
#define MTOT 65536
#define KTAP 9
#define EPSV 1e-5f
#define OMSP 128

typedef __half fp16;

// ---------------- scratch ----------------
__device__ fp16  g_xh[MTOT*CHN];                     // x transposed, fp16
__device__ fp16  g_yh[MTOT*CHN];                     // y fp16
__device__ fp16  g_sh[MTOT*CHN];                     // sampled fp16
__device__ fp16  g_v [MTOT*CHN];                     // value proj fp16
__device__ float g_om[MTOT*OMSP];                    // offsets+masks
__device__ fp16  g_whi[896*CHN], g_wlo[896*CHN];     // weights hi/lo fp16

// ---------------- helpers ----------------
__device__ __forceinline__ uint32_t smem_u32(const void* p){
    uint32_t a;
    asm("{ .reg .u64 t; cvta.to.shared.u64 t, %1; cvt.u32.u64 %0, t; }" : "=r"(a) : "l"(p));
    return a;
}
__device__ __forceinline__ void cpasync16(uint32_t dst, const void* src){
    asm volatile("cp.async.cg.shared.global [%0], [%1], 16;"
                 :: "r"(dst), "l"(src) : "memory");
}
#define CP_COMMIT()  asm volatile("cp.async.commit_group;" ::: "memory")
#define CP_WAIT(n)   asm volatile("cp.async.wait_group %0;" :: "n"(n) : "memory")

__device__ __forceinline__ void ldsm4(uint32_t& a0, uint32_t& a1, uint32_t& a2,
                                      uint32_t& a3, uint32_t addr){
    asm volatile("ldmatrix.sync.aligned.m8n8.x4.shared.b16 {%0,%1,%2,%3}, [%4];"
                 : "=r"(a0), "=r"(a1), "=r"(a2), "=r"(a3) : "r"(addr));
}
__device__ __forceinline__ void ldsm2(uint32_t& b0, uint32_t& b1, uint32_t addr){
    asm volatile("ldmatrix.sync.aligned.m8n8.x2.shared.b16 {%0,%1}, [%2];"
                 : "=r"(b0), "=r"(b1) : "r"(addr));
}
__device__ __forceinline__ void mma16816(float* c, const uint32_t* a,
                                         const uint32_t* b){
    asm volatile(
        "mma.sync.aligned.m16n8k16.row.col.f32.f16.f16.f32 "
        "{%0,%1,%2,%3}, {%4,%5,%6,%7}, {%8,%9}, {%0,%1,%2,%3};"
        : "+f"(c[0]), "+f"(c[1]), "+f"(c[2]), "+f"(c[3])
        : "r"(a[0]), "r"(a[1]), "r"(a[2]), "r"(a[3]), "r"(b[0]), "r"(b[1]));
}
__device__ __forceinline__ uint32_t pack2h(fp16 a, fp16 b){
    __half2 h; h.x = a; h.y = b;
    return *reinterpret_cast<uint32_t*>(&h);
}
__device__ __forceinline__ uint32_t swz(int r, int c){
    return (uint32_t)(r * 64 + ((c ^ ((r >> 1) & 3)) * 16));
}
__device__ __forceinline__ float silu_f(float x){
    return x / (1.f + __expf(-x));
}

// ---------------------------------------------------------------------------
// Weight split (rows: 0-255 conv | 256-511 value | 512-639 offset | 640-895 out)
// ---------------------------------------------------------------------------
__global__ __launch_bounds__(256)
void w_split(const float* __restrict__ conv_w, const float* __restrict__ value_w,
             const float* __restrict__ offset_w, const float* __restrict__ out_w,
             fp16* __restrict__ whi, fp16* __restrict__ wlo)
{
    int idx = blockIdx.x * 256 + threadIdx.x;
    if (idx >= 896 * 256) return;
    int r = idx >> 8, c = idx & 255;
    float v = 0.f;
    if      (r < 256) v = conv_w[r * 256 + c];
    else if (r < 512) v = value_w[(r - 256) * 256 + c];
    else if (r < 640) { int rr = r - 512; if (rr < 112) v = offset_w[rr * 256 + c]; }
    else              v = out_w[(r - 640) * 256 + c];
    fp16 h = __float2half_rn(v);
    whi[idx] = h;
    wlo[idx] = __float2half_rn(v - __half2float(h));
}

// ---------------------------------------------------------------------------
// x prepass: NCHW fp32 -> NHWC fp16
// ---------------------------------------------------------------------------
__global__ __launch_bounds__(256)
void x_split(const float* __restrict__ x, fp16* __restrict__ xh)
{
    __shared__ float t[32][129];
    const int tid = threadIdx.x;
    const int n = blockIdx.z, c0 = blockIdx.y * 32, hw0 = blockIdx.x * 128;
    const float* src = x + ((size_t)n * 256 + c0) * HWSZ + hw0;
    #pragma unroll
    for (int i = 0; i < 16; i++) {
        int e = tid + i * 256;
        int c = e >> 7, p = e & 127;
        t[c][p] = src[(size_t)c * HWSZ + p];
    }
    __syncthreads();
    int p = tid >> 1, half = tid & 1;
    size_t base = ((size_t)n * HWSZ + hw0 + p) * 256 + c0 + half * 16;
    fp16 hi[16];
    #pragma unroll
    for (int j = 0; j < 16; j++)
        hi[j] = __float2half_rn(t[half * 16 + j][p]);
    *reinterpret_cast<uint4*>(&xh[base])     = *reinterpret_cast<uint4*>(&hi[0]);
    *reinterpret_cast<uint4*>(&xh[base + 8]) = *reinterpret_cast<uint4*>(&hi[8]);
}

// ---------------------------------------------------------------------------
// fp16 HMMA GEMM: A single-fp16, W hi(+lo) fp16 -> NP MMA products per k-step.
// 4-stage cp.async pipeline. Grid: x = n-block (L2 A reuse).
//   EPI 1: bn+silu -> fp16 NHWC (y)
//   EPI 2: bias+bn+silu -> fp32 NCHW (final)
//   EPI 3: fused: o<256 -> v fp16 (CoH); o>=256 -> om fp32 (Co2)
// ---------------------------------------------------------------------------
template<int EPI, int NP>
__global__ __launch_bounds__(256, 2)
void gemm_fp16(const fp16* __restrict__ Ah,
               const fp16* __restrict__ Bhi, const fp16* __restrict__ Blo,
               const float* __restrict__ bias, const float* __restrict__ bias2,
               const float* __restrict__ gamma, const float* __restrict__ beta,
               const float* __restrict__ mean,  const float* __restrict__ var,
               float* __restrict__ Co, float* __restrict__ Co2,
               fp16* __restrict__ CoH)
{
    extern __shared__ __align__(16) char dsm[];
    __shared__ float sSC[128], sSH[128];

    const int tid  = threadIdx.x;
    const int wid  = tid >> 5;
    const int lane = tid & 31;
    const int p0   = blockIdx.y * 128;
    const int n0   = blockIdx.x * 128;

    const uint32_t sb = smem_u32(dsm);
    constexpr int STG = (NP == 2) ? 24576 : 16384;
    auto AH = [&](int s){ return sb + s * STG + 0;     };
    auto BH = [&](int s){ return sb + s * STG + 8192;  };
    auto BL = [&](int s){ return sb + s * STG + 16384; };

    if (tid < 128) {
        int o = n0 + tid;
        float sc = 1.f, sh = 0.f;
        if (EPI == 1) {
            float s_ = gamma[o] * rsqrtf(var[o] + EPSV);
            sc = s_; sh = beta[o] - mean[o] * s_;
        } else if (EPI == 2) {
            float s_ = gamma[o] * rsqrtf(var[o] + EPSV);
            sc = s_; sh = (beta[o] - mean[o] * s_) + bias[o] * s_;
        } else { // EPI 3
            if (o < 256)            sh = bias[o];
            else if (o - 256 < 112) sh = bias2[o - 256];
        }
        sSC[tid] = sc; sSH[tid] = sh;
    }

    auto load_stage = [&](int kt, int s) {
        #pragma unroll
        for (int i = 0; i < 2; i++) {
            int e = tid + i * 256;
            int r = e >> 2, c = e & 3;
            size_t ao = (size_t)(p0 + r) * 256 + kt + c * 8;
            size_t bo = (size_t)(n0 + r) * 256 + kt + c * 8;
            uint32_t d = swz(r, c);
            cpasync16(AH(s) + d, Ah  + ao);
            cpasync16(BH(s) + d, Bhi + bo);
            if (NP == 2) cpasync16(BL(s) + d, Blo + bo);
        }
        CP_COMMIT();
    };

    const int wm = (wid >> 2) * 64;
    const int wn = (wid & 3) * 32;

    float acc[4][4][4];
    #pragma unroll
    for (int i = 0; i < 4; i++)
        #pragma unroll
        for (int j = 0; j < 4; j++)
            #pragma unroll
            for (int q = 0; q < 4; q++) acc[i][j][q] = 0.f;

    load_stage(0, 0);
    load_stage(32, 1);
    load_stage(64, 2);

    #pragma unroll 1
    for (int st = 0; st < 8; st++) {
        const int s = st & 3;
        if (st < 6) { CP_WAIT(2); }
        else if (st == 6) { CP_WAIT(1); }
        else { CP_WAIT(0); }
        __syncthreads();

        #pragma unroll
        for (int kk = 0; kk < 2; kk++) {
            const int c0 = kk * 2;
            uint32_t ah[4][4], bh[4][2], bl[4][2];
            #pragma unroll
            for (int mt = 0; mt < 4; mt++) {
                int rr = wm + mt * 16 + (lane & 15);
                int cc = c0 + (lane >> 4);
                ldsm4(ah[mt][0], ah[mt][1], ah[mt][2], ah[mt][3],
                      AH(s) + swz(rr, cc));
            }
            #pragma unroll
            for (int nt = 0; nt < 4; nt++) {
                int rr = wn + nt * 8 + (lane & 7);
                int cc = c0 + ((lane >> 3) & 1);
                uint32_t bd = swz(rr, cc);
                ldsm2(bh[nt][0], bh[nt][1], BH(s) + bd);
                if (NP == 2) ldsm2(bl[nt][0], bl[nt][1], BL(s) + bd);
            }
            #pragma unroll
            for (int mt = 0; mt < 4; mt++)
                #pragma unroll
                for (int nt = 0; nt < 4; nt++) {
                    mma16816(acc[mt][nt], ah[mt], bh[nt]);
                    if (NP == 2) mma16816(acc[mt][nt], ah[mt], bl[nt]);
                }
        }
        if (st < 5) load_stage((st + 3) * 32, (st + 3) & 3);
    }

    // ---------------- epilogue ----------------
    const int qr = lane >> 2;
    const int qc = (lane & 3) * 2;
    #pragma unroll
    for (int mt = 0; mt < 4; mt++) {
        #pragma unroll
        for (int nt = 0; nt < 4; nt++) {
            int ocl = wn + nt * 8 + qc;
            int o   = n0 + ocl;
            float sc0 = sSC[ocl],     sh0 = sSH[ocl];
            float sc1 = sSC[ocl + 1], sh1 = sSH[ocl + 1];
            #pragma unroll
            for (int half = 0; half < 2; half++) {
                int p  = p0 + wm + mt * 16 + qr + half * 8;
                float v0 = acc[mt][nt][half * 2 + 0] * sc0 + sh0;
                float v1 = acc[mt][nt][half * 2 + 1] * sc1 + sh1;
                if (EPI == 1 || EPI == 2) {
                    v0 = silu_f(v0);
                    v1 = silu_f(v1);
                }
                if (EPI == 1) {
                    *reinterpret_cast<uint32_t*>(&CoH[(size_t)p * 256 + o]) =
                        pack2h(__float2half_rn(v0), __float2half_rn(v1));
                } else if (EPI == 2) {
                    int n = p >> 14, hw = p & 16383;
                    Co[(((size_t)n * 256 + o)     << 14) + hw] = v0;
                    Co[(((size_t)n * 256 + o + 1) << 14) + hw] = v1;
                } else { // EPI 3
                    if (o < 256) {
                        *reinterpret_cast<uint32_t*>(&CoH[(size_t)p * 256 + o]) =
                            pack2h(__float2half_rn(v0), __float2half_rn(v1));
                    } else {
                        *reinterpret_cast<float2*>(&Co2[(size_t)p * OMSP + (o - 256)]) =
                            make_float2(v0, v1);
                    }
                }
            }
        }
    }
}

// ---------------------------------------------------------------------------
// DCNv4 sampling v4: warp = 1 pixel (all 4 groups); lane = (group = lane>>3,
// 8 channels via one 16B uint4 load per corner).
// ---------------------------------------------------------------------------
__global__ __launch_bounds__(256)
void dcn_sample(const fp16* __restrict__ v, const float* __restrict__ om,
                fp16* __restrict__ sh)
{
    const int p    = (blockIdx.x * 256 + threadIdx.x) >> 5;   // pixel
    const int lane = threadIdx.x & 31;
    const int g    = lane >> 3;
    const int c8   = (lane & 7) * 8;
    const int n  = p >> 14;
    const int hw = p & (HWSZ - 1);
    const int h = hw >> 7, w = hw & 127;

    const float* op = om + (size_t)p * OMSP + g * 27;
    const int cb = g * 64 + c8;
    const fp16* vb = v + ((size_t)n << 22) + cb;

    float a[8] = {};
    #pragma unroll
    for (int k = 0; k < KTAP; k++) {
        float ow = op[2 * k];
        float oh = op[2 * k + 1];
        float mk = op[18 + k];
        float lh = (float)(h + k / 3 - 1) + oh;
        float lw = (float)(w + k % 3 - 1) + ow;
        float fh = floorf(lh), fw = floorf(lw);
        int h0 = (int)fh, w0 = (int)fw;
        float dh = lh - fh, dw = lw - fw;
        float w00 = (1.f - dh) * (1.f - dw) * mk;
        float w01 = (1.f - dh) * dw * mk;
        float w10 = dh * (1.f - dw) * mk;
        float w11 = dh * dw * mk;
        bool hv0 = (unsigned)h0 < HSZ;
        bool hv1 = (unsigned)(h0 + 1) < HSZ;
        bool wv0 = (unsigned)w0 < WSZ;
        bool wv1 = (unsigned)(w0 + 1) < WSZ;
        int r0 = (h0 * WSZ + w0) << 8;

        #define ACC8(OFF, WT) do { \
            uint4 raw = *reinterpret_cast<const uint4*>(vb + (OFF)); \
            float2 f0 = __half22float2(*reinterpret_cast<__half2*>(&raw.x)); \
            float2 f1 = __half22float2(*reinterpret_cast<__half2*>(&raw.y)); \
            float2 f2 = __half22float2(*reinterpret_cast<__half2*>(&raw.z)); \
            float2 f3 = __half22float2(*reinterpret_cast<__half2*>(&raw.w)); \
            a[0] += (WT) * f0.x; a[1] += (WT) * f0.y; \
            a[2] += (WT) * f1.x; a[3] += (WT) * f1.y; \
            a[4] += (WT) * f2.x; a[5] += (WT) * f2.y; \
            a[6] += (WT) * f3.x; a[7] += (WT) * f3.y; \
        } while (0)

        if (hv0 && wv0) ACC8(r0, w00);
        if (hv0 && wv1) ACC8(r0 + 256, w01);
        if (hv1 && wv0) ACC8(r0 + (WSZ << 8), w10);
        if (hv1 && wv1) ACC8(r0 + ((WSZ + 1) << 8), w11);
        #undef ACC8
    }
    uint4 out;
    out.x = pack2h(__float2half_rn(a[0]), __float2half_rn(a[1]));
    out.y = pack2h(__float2half_rn(a[2]), __float2half_rn(a[3]));
    out.z = pack2h(__float2half_rn(a[4]), __float2half_rn(a[5]));
    out.w = pack2h(__float2half_rn(a[6]), __float2half_rn(a[7]));
    *reinterpret_cast<uint4*>(&sh[(size_t)p * 256 + cb]) = out;
}

// ---------------------------------------------------------------------------
extern "C" void kernel_launch(void* const* d_in, const int* in_sizes, int n_in,
                              void* d_out, int out_size)
{
    const float* x        = (const float*)d_in[0];
    const float* conv_w   = (const float*)d_in[1];
    const float* bn1_g    = (const float*)d_in[2];
    const float* bn1_b    = (const float*)d_in[3];
    const float* bn1_m    = (const float*)d_in[4];
    const float* bn1_v    = (const float*)d_in[5];
    const float* value_w  = (const float*)d_in[6];
    const float* value_b  = (const float*)d_in[7];
    const float* offset_w = (const float*)d_in[8];
    const float* offset_b = (const float*)d_in[9];
    const float* out_w    = (const float*)d_in[10];
    const float* out_b    = (const float*)d_in[11];
    const float* bn2_g    = (const float*)d_in[12];
    const float* bn2_b    = (const float*)d_in[13];
    const float* bn2_m    = (const float*)d_in[14];
    const float* bn2_v    = (const float*)d_in[15];

    fp16 *xh, *yh, *sh, *vv, *whi, *wlo;
    float *omp;
    cudaGetSymbolAddress((void**)&xh,  g_xh);
    cudaGetSymbolAddress((void**)&yh,  g_yh);
    cudaGetSymbolAddress((void**)&sh,  g_sh);
    cudaGetSymbolAddress((void**)&vv,  g_v);
    cudaGetSymbolAddress((void**)&whi, g_whi);
    cudaGetSymbolAddress((void**)&wlo, g_wlo);
    cudaGetSymbolAddress((void**)&omp, g_om);

    const int smem1 = 4 * 16384;   // 64KB, NP=1
    cudaFuncSetAttribute(gemm_fp16<1,1>, cudaFuncAttributeMaxDynamicSharedMemorySize, smem1);
    cudaFuncSetAttribute(gemm_fp16<2,1>, cudaFuncAttributeMaxDynamicSharedMemorySize, smem1);
    cudaFuncSetAttribute(gemm_fp16<3,1>, cudaFuncAttributeMaxDynamicSharedMemorySize, smem1);

    // prepasses
    w_split<<<896, 256>>>(conv_w, value_w, offset_w, out_w, whi, wlo);
    x_split<<<dim3(128, 8, 4), 256>>>(x, xh);

    const int MT = MTOT / 128;   // 512 pixel tiles

    // 1) y = silu(bn1(x @ conv_w^T))           -> y fp16   (hi only)
    gemm_fp16<1,1><<<dim3(2, MT), 256, smem1>>>(
        xh, whi, nullptr, nullptr, nullptr,
        bn1_g, bn1_b, bn1_m, bn1_v, nullptr, nullptr, yh);
    // 2) fused: v (fp16) = y@value_w^T + b ; om (fp32) = y@offset_w^T + b  (hi only)
    gemm_fp16<3,1><<<dim3(3, MT), 256, smem1>>>(
        yh, whi + 256*256, nullptr, value_b, offset_b,
        nullptr, nullptr, nullptr, nullptr, nullptr, omp, vv);
    // 3) deformable sampling (fp16 v) -> s fp16   (warp = 1 pixel)
    dcn_sample<<<MTOT / 8, 256>>>(vv, omp, sh);
    // 4) out = silu(bn2(s @ out_w^T + out_b))  -> NCHW fp32   (hi only)
    gemm_fp16<2,1><<<dim3(2, MT), 256, smem1>>>(
        sh, whi + 640*256, nullptr, out_b, nullptr,
        bn2_g, bn2_b, bn2_m, bn2_v, (float*)d_out, nullptr, nullptr);
}

// round 15
// speedup vs baseline: 2.1596x; 1.0602x over previous
#include <cuda_runtime.h>
#include <cuda_fp16.h>
#include <cstdint>
#include <math.h>

// ---------------- problem constants ----------------
#define NTOT 4
#define CHN  256
#define HSZ  128
#define WSZ  128
#define HWSZ 16384
#define MTOT 65536
#define KTAP 9
#define EPSV 1e-5f
#define OMSP 128

typedef __half fp16;

// ---------------- scratch ----------------
__device__ fp16  g_xh[MTOT*CHN];                     // x transposed, fp16
__device__ fp16  g_yh[MTOT*CHN];                     // y fp16
__device__ fp16  g_sh[MTOT*CHN];                     // sampled fp16
__device__ fp16  g_v [MTOT*CHN];                     // value proj fp16
__device__ float g_om[MTOT*OMSP];                    // offsets+masks
__device__ fp16  g_whi[896*CHN];                     // weights fp16 (hi)

// ---------------- helpers ----------------
__device__ __forceinline__ uint32_t smem_u32(const void* p){
    uint32_t a;
    asm("{ .reg .u64 t; cvta.to.shared.u64 t, %1; cvt.u32.u64 %0, t; }" : "=r"(a) : "l"(p));
    return a;
}
__device__ __forceinline__ void cpasync16(uint32_t dst, const void* src){
    asm volatile("cp.async.cg.shared.global [%0], [%1], 16;"
                 :: "r"(dst), "l"(src) : "memory");
}
#define CP_COMMIT()  asm volatile("cp.async.commit_group;" ::: "memory")
#define CP_WAIT(n)   asm volatile("cp.async.wait_group %0;" :: "n"(n) : "memory")

__device__ __forceinline__ void ldsm4(uint32_t& a0, uint32_t& a1, uint32_t& a2,
                                      uint32_t& a3, uint32_t addr){
    asm volatile("ldmatrix.sync.aligned.m8n8.x4.shared.b16 {%0,%1,%2,%3}, [%4];"
                 : "=r"(a0), "=r"(a1), "=r"(a2), "=r"(a3) : "r"(addr));
}
__device__ __forceinline__ void ldsm2(uint32_t& b0, uint32_t& b1, uint32_t addr){
    asm volatile("ldmatrix.sync.aligned.m8n8.x2.shared.b16 {%0,%1}, [%2];"
                 : "=r"(b0), "=r"(b1) : "r"(addr));
}
__device__ __forceinline__ void mma16816(float* c, const uint32_t* a,
                                         const uint32_t* b){
    asm volatile(
        "mma.sync.aligned.m16n8k16.row.col.f32.f16.f16.f32 "
        "{%0,%1,%2,%3}, {%4,%5,%6,%7}, {%8,%9}, {%0,%1,%2,%3};"
        : "+f"(c[0]), "+f"(c[1]), "+f"(c[2]), "+f"(c[3])
        : "r"(a[0]), "r"(a[1]), "r"(a[2]), "r"(a[3]), "r"(b[0]), "r"(b[1]));
}
__device__ __forceinline__ uint32_t pack2h(fp16 a, fp16 b){
    __half2 h; h.x = a; h.y = b;
    return *reinterpret_cast<uint32_t*>(&h);
}
// 128-byte-row swizzle: row r (0..127), 16B chunk c (0..7)
__device__ __forceinline__ uint32_t swzB(int r, int c){
    return (uint32_t)(r * 128 + ((c ^ (r & 7)) * 16));
}
__device__ __forceinline__ float silu_f(float x){
    return x / (1.f + __expf(-x));
}

// ---------------------------------------------------------------------------
// Merged prepass: blocks [0,4096) transpose x NCHW fp32 -> NHWC fp16;
// blocks [4096,4992) split/pad weights to fp16
// (rows: 0-255 conv | 256-511 value | 512-639 offset(112 real) | 640-895 out).
// ---------------------------------------------------------------------------
__global__ __launch_bounds__(256)
void prep(const float* __restrict__ x, fp16* __restrict__ xh,
          const float* __restrict__ conv_w, const float* __restrict__ value_w,
          const float* __restrict__ offset_w, const float* __restrict__ out_w,
          fp16* __restrict__ whi)
{
    const int tid = threadIdx.x;
    if (blockIdx.x >= 4096) {
        int idx = (blockIdx.x - 4096) * 256 + tid;
        int r = idx >> 8, c = idx & 255;
        float v = 0.f;
        if      (r < 256) v = conv_w[r * 256 + c];
        else if (r < 512) v = value_w[(r - 256) * 256 + c];
        else if (r < 640) { int rr = r - 512; if (rr < 112) v = offset_w[rr * 256 + c]; }
        else              v = out_w[(r - 640) * 256 + c];
        whi[idx] = __float2half_rn(v);
        return;
    }
    __shared__ float t[32][129];
    const int bid = blockIdx.x;
    const int n = bid >> 10, c0 = ((bid >> 7) & 7) * 32, hw0 = (bid & 127) * 128;
    const float* src = x + ((size_t)n * 256 + c0) * HWSZ + hw0;
    #pragma unroll
    for (int i = 0; i < 16; i++) {
        int e = tid + i * 256;
        int c = e >> 7, p = e & 127;
        t[c][p] = src[(size_t)c * HWSZ + p];
    }
    __syncthreads();
    int p = tid >> 1, half = tid & 1;
    size_t base = ((size_t)n * HWSZ + hw0 + p) * 256 + c0 + half * 16;
    fp16 hi[16];
    #pragma unroll
    for (int j = 0; j < 16; j++)
        hi[j] = __float2half_rn(t[half * 16 + j][p]);
    *reinterpret_cast<uint4*>(&xh[base])     = *reinterpret_cast<uint4*>(&hi[0]);
    *reinterpret_cast<uint4*>(&xh[base + 8]) = *reinterpret_cast<uint4*>(&hi[8]);
}

// ---------------------------------------------------------------------------
// fp16 HMMA GEMM, BK=64 stages (4 stages, 3 x 32KB smem buffers).
// Grid: x = n-block (fast -> L2 A reuse), y = pixel tile.
//   EPI 1: bn+silu -> fp16 NHWC (y)
//   EPI 2: bias+bn+silu -> fp32 NCHW (final)
//   EPI 3: fused: o<256 -> v fp16 (CoH); o>=256 -> om fp32 (Co2)
// Tile BM=128, BN=128, 8 warps (2x4), warp 64x32, 2 CTAs/SM.
// ---------------------------------------------------------------------------
template<int EPI>
__global__ __launch_bounds__(256, 2)
void gemm_fp16(const fp16* __restrict__ Ah, const fp16* __restrict__ Bhi,
               const float* __restrict__ bias, const float* __restrict__ bias2,
               const float* __restrict__ gamma, const float* __restrict__ beta,
               const float* __restrict__ mean,  const float* __restrict__ var,
               float* __restrict__ Co, float* __restrict__ Co2,
               fp16* __restrict__ CoH)
{
    extern __shared__ __align__(16) char dsm[];
    __shared__ float sSC[128], sSH[128];

    const int tid  = threadIdx.x;
    const int wid  = tid >> 5;
    const int lane = tid & 31;
    const int p0   = blockIdx.y * 128;
    const int n0   = blockIdx.x * 128;

    const uint32_t sb = smem_u32(dsm);
    const int STG = 32768;                 // 16KB A + 16KB B per stage
    auto AH = [&](int s){ return sb + s * STG; };
    auto BH = [&](int s){ return sb + s * STG + 16384; };

    if (tid < 128) {
        int o = n0 + tid;
        float sc = 1.f, sh = 0.f;
        if (EPI == 1) {
            float s_ = gamma[o] * rsqrtf(var[o] + EPSV);
            sc = s_; sh = beta[o] - mean[o] * s_;
        } else if (EPI == 2) {
            float s_ = gamma[o] * rsqrtf(var[o] + EPSV);
            sc = s_; sh = (beta[o] - mean[o] * s_) + bias[o] * s_;
        } else { // EPI 3
            if (o < 256)            sh = bias[o];
            else if (o - 256 < 112) sh = bias2[o - 256];
        }
        sSC[tid] = sc; sSH[tid] = sh;
    }

    auto load_stage = [&](int kt, int s) {
        #pragma unroll
        for (int i = 0; i < 4; i++) {
            int e = tid + i * 256;          // 0..1023
            int r = e >> 3, c = e & 7;
            uint32_t d = swzB(r, c);
            cpasync16(AH(s) + d, Ah  + (size_t)(p0 + r) * 256 + kt + c * 8);
            cpasync16(BH(s) + d, Bhi + (size_t)(n0 + r) * 256 + kt + c * 8);
        }
        CP_COMMIT();
    };

    const int wm = (wid >> 2) * 64;
    const int wn = (wid & 3) * 32;

    float acc[4][4][4];
    #pragma unroll
    for (int i = 0; i < 4; i++)
        #pragma unroll
        for (int j = 0; j < 4; j++)
            #pragma unroll
            for (int q = 0; q < 4; q++) acc[i][j][q] = 0.f;

    load_stage(0, 0);
    load_stage(64, 1);

    #pragma unroll 1
    for (int st = 0; st < 4; st++) {
        const int s = st % 3;
        if (st == 3) { CP_WAIT(0); } else { CP_WAIT(1); }
        __syncthreads();
        if (st < 2) load_stage((st + 2) * 64, (st + 2) % 3);

        #pragma unroll
        for (int kk = 0; kk < 4; kk++) {
            const int c0 = kk * 2;          // 16B-chunk base of this k16
            uint32_t ah[4][4], bh[4][2];
            #pragma unroll
            for (int mt = 0; mt < 4; mt++) {
                int rr = wm + mt * 16 + (lane & 15);
                int cc = c0 + (lane >> 4);
                ldsm4(ah[mt][0], ah[mt][1], ah[mt][2], ah[mt][3],
                      AH(s) + swzB(rr, cc));
            }
            #pragma unroll
            for (int nt = 0; nt < 4; nt++) {
                int rr = wn + nt * 8 + (lane & 7);
                int cc = c0 + ((lane >> 3) & 1);
                ldsm2(bh[nt][0], bh[nt][1], BH(s) + swzB(rr, cc));
            }
            #pragma unroll
            for (int mt = 0; mt < 4; mt++)
                #pragma unroll
                for (int nt = 0; nt < 4; nt++)
                    mma16816(acc[mt][nt], ah[mt], bh[nt]);
        }
    }

    // ---------------- epilogue ----------------
    const int qr = lane >> 2;
    const int qc = (lane & 3) * 2;
    #pragma unroll
    for (int mt = 0; mt < 4; mt++) {
        #pragma unroll
        for (int nt = 0; nt < 4; nt++) {
            int ocl = wn + nt * 8 + qc;
            int o   = n0 + ocl;
            float sc0 = sSC[ocl],     sh0 = sSH[ocl];
            float sc1 = sSC[ocl + 1], sh1 = sSH[ocl + 1];
            #pragma unroll
            for (int half = 0; half < 2; half++) {
                int p  = p0 + wm + mt * 16 + qr + half * 8;
                float v0 = acc[mt][nt][half * 2 + 0] * sc0 + sh0;
                float v1 = acc[mt][nt][half * 2 + 1] * sc1 + sh1;
                if (EPI == 1 || EPI == 2) {
                    v0 = silu_f(v0);
                    v1 = silu_f(v1);
                }
                if (EPI == 1) {
                    *reinterpret_cast<uint32_t*>(&CoH[(size_t)p * 256 + o]) =
                        pack2h(__float2half_rn(v0), __float2half_rn(v1));
                } else if (EPI == 2) {
                    int n = p >> 14, hw = p & 16383;
                    Co[(((size_t)n * 256 + o)     << 14) + hw] = v0;
                    Co[(((size_t)n * 256 + o + 1) << 14) + hw] = v1;
                } else { // EPI 3
                    if (o < 256) {
                        *reinterpret_cast<uint32_t*>(&CoH[(size_t)p * 256 + o]) =
                            pack2h(__float2half_rn(v0), __float2half_rn(v1));
                    } else {
                        *reinterpret_cast<float2*>(&Co2[(size_t)p * OMSP + (o - 256)]) =
                            make_float2(v0, v1);
                    }
                }
            }
        }
    }
}

// ---------------------------------------------------------------------------
// DCNv4 sampling v4 (best-measured): warp = 1 pixel (4 groups); lane =
// (group = lane>>3, 8 channels via one 16B uint4 load per corner).
// ---------------------------------------------------------------------------
__global__ __launch_bounds__(256)
void dcn_sample(const fp16* __restrict__ v, const float* __restrict__ om,
                fp16* __restrict__ sh)
{
    const int p    = (blockIdx.x * 256 + threadIdx.x) >> 5;   // pixel
    const int lane = threadIdx.x & 31;
    const int g    = lane >> 3;
    const int c8   = (lane & 7) * 8;
    const int n  = p >> 14;
    const int hw = p & (HWSZ - 1);
    const int h = hw >> 7, w = hw & 127;

    const float* op = om + (size_t)p * OMSP + g * 27;
    const int cb = g * 64 + c8;
    const fp16* vb = v + ((size_t)n << 22) + cb;

    float a[8] = {};
    #pragma unroll
    for (int k = 0; k < KTAP; k++) {
        float ow = op[2 * k];
        float oh = op[2 * k + 1];
        float mk = op[18 + k];
        float lh = (float)(h + k / 3 - 1) + oh;
        float lw = (float)(w + k % 3 - 1) + ow;
        float fh = floorf(lh), fw = floorf(lw);
        int h0 = (int)fh, w0 = (int)fw;
        float dh = lh - fh, dw = lw - fw;
        float w00 = (1.f - dh) * (1.f - dw) * mk;
        float w01 = (1.f - dh) * dw * mk;
        float w10 = dh * (1.f - dw) * mk;
        float w11 = dh * dw * mk;
        bool hv0 = (unsigned)h0 < HSZ;
        bool hv1 = (unsigned)(h0 + 1) < HSZ;
        bool wv0 = (unsigned)w0 < WSZ;
        bool wv1 = (unsigned)(w0 + 1) < WSZ;
        int r0 = (h0 * WSZ + w0) << 8;

        #define ACC8(OFF, WT) do { \
            uint4 raw = *reinterpret_cast<const uint4*>(vb + (OFF)); \
            float2 f0 = __half22float2(*reinterpret_cast<__half2*>(&raw.x)); \
            float2 f1 = __half22float2(*reinterpret_cast<__half2*>(&raw.y)); \
            float2 f2 = __half22float2(*reinterpret_cast<__half2*>(&raw.z)); \
            float2 f3 = __half22float2(*reinterpret_cast<__half2*>(&raw.w)); \
            a[0] += (WT) * f0.x; a[1] += (WT) * f0.y; \
            a[2] += (WT) * f1.x; a[3] += (WT) * f1.y; \
            a[4] += (WT) * f2.x; a[5] += (WT) * f2.y; \
            a[6] += (WT) * f3.x; a[7] += (WT) * f3.y; \
        } while (0)

        if (hv0 && wv0) ACC8(r0, w00);
        if (hv0 && wv1) ACC8(r0 + 256, w01);
        if (hv1 && wv0) ACC8(r0 + (WSZ << 8), w10);
        if (hv1 && wv1) ACC8(r0 + ((WSZ + 1) << 8), w11);
        #undef ACC8
    }
    uint4 out;
    out.x = pack2h(__float2half_rn(a[0]), __float2half_rn(a[1]));
    out.y = pack2h(__float2half_rn(a[2]), __float2half_rn(a[3]));
    out.z = pack2h(__float2half_rn(a[4]), __float2half_rn(a[5]));
    out.w = pack2h(__float2half_rn(a[6]), __float2half_rn(a[7]));
    *reinterpret_cast<uint4*>(&sh[(size_t)p * 256 + cb]) = out;
}

// ---------------------------------------------------------------------------
extern "C" void kernel_launch(void* const* d_in, const int* in_sizes, int n_in,
                              void* d_out, int out_size)
{
    const float* x        = (const float*)d_in[0];
    const float* conv_w   = (const float*)d_in[1];
    const float* bn1_g    = (const float*)d_in[2];
    const float* bn1_b    = (const float*)d_in[3];
    const float* bn1_m    = (const float*)d_in[4];
    const float* bn1_v    = (const float*)d_in[5];
    const float* value_w  = (const float*)d_in[6];
    const float* value_b  = (const float*)d_in[7];
    const float* offset_w = (const float*)d_in[8];
    const float* offset_b = (const float*)d_in[9];
    const float* out_w    = (const float*)d_in[10];
    const float* out_b    = (const float*)d_in[11];
    const float* bn2_g    = (const float*)d_in[12];
    const float* bn2_b    = (const float*)d_in[13];
    const float* bn2_m    = (const float*)d_in[14];
    const float* bn2_v    = (const float*)d_in[15];

    fp16 *xh, *yh, *sh, *vv, *whi;
    float *omp;
    cudaGetSymbolAddress((void**)&xh,  g_xh);
    cudaGetSymbolAddress((void**)&yh,  g_yh);
    cudaGetSymbolAddress((void**)&sh,  g_sh);
    cudaGetSymbolAddress((void**)&vv,  g_v);
    cudaGetSymbolAddress((void**)&whi, g_whi);
    cudaGetSymbolAddress((void**)&omp, g_om);

    const int smem = 3 * 32768;   // 96KB: 3 x (16KB A + 16KB B)
    cudaFuncSetAttribute(gemm_fp16<1>, cudaFuncAttributeMaxDynamicSharedMemorySize, smem);
    cudaFuncSetAttribute(gemm_fp16<2>, cudaFuncAttributeMaxDynamicSharedMemorySize, smem);
    cudaFuncSetAttribute(gemm_fp16<3>, cudaFuncAttributeMaxDynamicSharedMemorySize, smem);

    // merged prepass: x transpose+cvt (4096 blocks) + weight split (896 blocks)
    prep<<<4992, 256>>>(x, xh, conv_w, value_w, offset_w, out_w, whi);

    const int MT = MTOT / 128;   // 512 pixel tiles

    // 1) y = silu(bn1(x @ conv_w^T))           -> y fp16
    gemm_fp16<1><<<dim3(2, MT), 256, smem>>>(
        xh, whi, nullptr, nullptr,
        bn1_g, bn1_b, bn1_m, bn1_v, nullptr, nullptr, yh);
    // 2) fused: v (fp16) = y@value_w^T + b ; om (fp32) = y@offset_w^T + b
    gemm_fp16<3><<<dim3(3, MT), 256, smem>>>(
        yh, whi + 256*256, value_b, offset_b,
        nullptr, nullptr, nullptr, nullptr, nullptr, omp, vv);
    // 3) deformable sampling (fp16 v) -> s fp16
    dcn_sample<<<MTOT / 8, 256>>>(vv, omp, sh);
    // 4) out = silu(bn2(s @ out_w^T + out_b))  -> NCHW fp32
    gemm_fp16<2><<<dim3(2, MT), 256, smem>>>(
        sh, whi + 640*256, out_b, nullptr,
        bn2_g, bn2_b, bn2_m, bn2_v, (float*)d_out, nullptr, nullptr);
}

// round 16
// speedup vs baseline: 2.1599x; 1.0001x over previous
#include <cuda_runtime.h>
#include <cuda_fp16.h>
#include <cstdint>
#include <math.h>

// ---------------- problem constants ----------------
#define NTOT 4
#define CHN  256
#define HSZ  128
#define WSZ  128
#define HWSZ 16384
#define MTOT 65536
#define KTAP 9
#define EPSV 1e-5f
#define OMSP 128

typedef __half fp16;

// ---------------- scratch ----------------
__device__ fp16  g_xh[MTOT*CHN];                     // x transposed, fp16
__device__ fp16  g_yh[MTOT*CHN];                     // y fp16
__device__ fp16  g_sh[MTOT*CHN];                     // sampled fp16
__device__ fp16  g_v [MTOT*CHN];                     // value proj fp16
__device__ float g_om[MTOT*OMSP];                    // offsets+masks
__device__ fp16  g_whi[896*CHN];                     // weights fp16

// ---------------- helpers ----------------
__device__ __forceinline__ uint32_t smem_u32(const void* p){
    uint32_t a;
    asm("{ .reg .u64 t; cvta.to.shared.u64 t, %1; cvt.u32.u64 %0, t; }" : "=r"(a) : "l"(p));
    return a;
}
__device__ __forceinline__ void cpasync16(uint32_t dst, const void* src){
    asm volatile("cp.async.cg.shared.global [%0], [%1], 16;"
                 :: "r"(dst), "l"(src) : "memory");
}
#define CP_COMMIT()  asm volatile("cp.async.commit_group;" ::: "memory")
#define CP_WAIT(n)   asm volatile("cp.async.wait_group %0;" :: "n"(n) : "memory")

__device__ __forceinline__ void ldsm4(uint32_t& a0, uint32_t& a1, uint32_t& a2,
                                      uint32_t& a3, uint32_t addr){
    asm volatile("ldmatrix.sync.aligned.m8n8.x4.shared.b16 {%0,%1,%2,%3}, [%4];"
                 : "=r"(a0), "=r"(a1), "=r"(a2), "=r"(a3) : "r"(addr));
}
__device__ __forceinline__ void ldsm2(uint32_t& b0, uint32_t& b1, uint32_t addr){
    asm volatile("ldmatrix.sync.aligned.m8n8.x2.shared.b16 {%0,%1}, [%2];"
                 : "=r"(b0), "=r"(b1) : "r"(addr));
}
__device__ __forceinline__ void mma16816(float* c, const uint32_t* a,
                                         const uint32_t* b){
    asm volatile(
        "mma.sync.aligned.m16n8k16.row.col.f32.f16.f16.f32 "
        "{%0,%1,%2,%3}, {%4,%5,%6,%7}, {%8,%9}, {%0,%1,%2,%3};"
        : "+f"(c[0]), "+f"(c[1]), "+f"(c[2]), "+f"(c[3])
        : "r"(a[0]), "r"(a[1]), "r"(a[2]), "r"(a[3]), "r"(b[0]), "r"(b[1]));
}
__device__ __forceinline__ uint32_t pack2h(fp16 a, fp16 b){
    __half2 h; h.x = a; h.y = b;
    return *reinterpret_cast<uint32_t*>(&h);
}
// 128-byte-row swizzle: row r (0..127), 16B chunk c (0..7)
__device__ __forceinline__ uint32_t swzB(int r, int c){
    return (uint32_t)(r * 128 + ((c ^ (r & 7)) * 16));
}
__device__ __forceinline__ float silu_f(float x){
    return x / (1.f + __expf(-x));
}

// ---------------------------------------------------------------------------
// Merged prepass: blocks [0,4096) transpose x NCHW fp32 -> NHWC fp16;
// blocks [4096,4992) pad/convert weights to fp16.
// ---------------------------------------------------------------------------
__global__ __launch_bounds__(256)
void prep(const float* __restrict__ x, fp16* __restrict__ xh,
          const float* __restrict__ conv_w, const float* __restrict__ value_w,
          const float* __restrict__ offset_w, const float* __restrict__ out_w,
          fp16* __restrict__ whi)
{
    const int tid = threadIdx.x;
    if (blockIdx.x >= 4096) {
        int idx = (blockIdx.x - 4096) * 256 + tid;
        int r = idx >> 8, c = idx & 255;
        float v = 0.f;
        if      (r < 256) v = conv_w[r * 256 + c];
        else if (r < 512) v = value_w[(r - 256) * 256 + c];
        else if (r < 640) { int rr = r - 512; if (rr < 112) v = offset_w[rr * 256 + c]; }
        else              v = out_w[(r - 640) * 256 + c];
        whi[idx] = __float2half_rn(v);
        return;
    }
    __shared__ float t[32][129];
    const int bid = blockIdx.x;
    const int n = bid >> 10, c0 = ((bid >> 7) & 7) * 32, hw0 = (bid & 127) * 128;
    const float* src = x + ((size_t)n * 256 + c0) * HWSZ + hw0;
    #pragma unroll
    for (int i = 0; i < 16; i++) {
        int e = tid + i * 256;
        int c = e >> 7, p = e & 127;
        t[c][p] = src[(size_t)c * HWSZ + p];
    }
    __syncthreads();
    int p = tid >> 1, half = tid & 1;
    size_t base = ((size_t)n * HWSZ + hw0 + p) * 256 + c0 + half * 16;
    fp16 hi[16];
    #pragma unroll
    for (int j = 0; j < 16; j++)
        hi[j] = __float2half_rn(t[half * 16 + j][p]);
    *reinterpret_cast<uint4*>(&xh[base])     = *reinterpret_cast<uint4*>(&hi[0]);
    *reinterpret_cast<uint4*>(&xh[base + 8]) = *reinterpret_cast<uint4*>(&hi[8]);
}

// ---------------------------------------------------------------------------
// fp16 HMMA GEMM, BK=64 stages (4 stages, 3 x 32KB smem buffers).
// Grid: x = n-block (fast -> L2 A reuse), y = pixel tile.
// ---------------------------------------------------------------------------
template<int EPI>
__global__ __launch_bounds__(256, 2)
void gemm_fp16(const fp16* __restrict__ Ah, const fp16* __restrict__ Bhi,
               const float* __restrict__ bias, const float* __restrict__ bias2,
               const float* __restrict__ gamma, const float* __restrict__ beta,
               const float* __restrict__ mean,  const float* __restrict__ var,
               float* __restrict__ Co, float* __restrict__ Co2,
               fp16* __restrict__ CoH)
{
    extern __shared__ __align__(16) char dsm[];
    __shared__ float sSC[128], sSH[128];

    const int tid  = threadIdx.x;
    const int wid  = tid >> 5;
    const int lane = tid & 31;
    const int p0   = blockIdx.y * 128;
    const int n0   = blockIdx.x * 128;

    const uint32_t sb = smem_u32(dsm);
    const int STG = 32768;
    auto AH = [&](int s){ return sb + s * STG; };
    auto BH = [&](int s){ return sb + s * STG + 16384; };

    if (tid < 128) {
        int o = n0 + tid;
        float sc = 1.f, sh = 0.f;
        if (EPI == 1) {
            float s_ = gamma[o] * rsqrtf(var[o] + EPSV);
            sc = s_; sh = beta[o] - mean[o] * s_;
        } else if (EPI == 2) {
            float s_ = gamma[o] * rsqrtf(var[o] + EPSV);
            sc = s_; sh = (beta[o] - mean[o] * s_) + bias[o] * s_;
        } else { // EPI 3
            if (o < 256)            sh = bias[o];
            else if (o - 256 < 112) sh = bias2[o - 256];
        }
        sSC[tid] = sc; sSH[tid] = sh;
    }

    auto load_stage = [&](int kt, int s) {
        #pragma unroll
        for (int i = 0; i < 4; i++) {
            int e = tid + i * 256;
            int r = e >> 3, c = e & 7;
            uint32_t d = swzB(r, c);
            cpasync16(AH(s) + d, Ah  + (size_t)(p0 + r) * 256 + kt + c * 8);
            cpasync16(BH(s) + d, Bhi + (size_t)(n0 + r) * 256 + kt + c * 8);
        }
        CP_COMMIT();
    };

    const int wm = (wid >> 2) * 64;
    const int wn = (wid & 3) * 32;

    float acc[4][4][4];
    #pragma unroll
    for (int i = 0; i < 4; i++)
        #pragma unroll
        for (int j = 0; j < 4; j++)
            #pragma unroll
            for (int q = 0; q < 4; q++) acc[i][j][q] = 0.f;

    load_stage(0, 0);
    load_stage(64, 1);

    #pragma unroll 1
    for (int st = 0; st < 4; st++) {
        const int s = st % 3;
        if (st == 3) { CP_WAIT(0); } else { CP_WAIT(1); }
        __syncthreads();
        if (st < 2) load_stage((st + 2) * 64, (st + 2) % 3);

        #pragma unroll
        for (int kk = 0; kk < 4; kk++) {
            const int c0 = kk * 2;
            uint32_t ah[4][4], bh[4][2];
            #pragma unroll
            for (int mt = 0; mt < 4; mt++) {
                int rr = wm + mt * 16 + (lane & 15);
                int cc = c0 + (lane >> 4);
                ldsm4(ah[mt][0], ah[mt][1], ah[mt][2], ah[mt][3],
                      AH(s) + swzB(rr, cc));
            }
            #pragma unroll
            for (int nt = 0; nt < 4; nt++) {
                int rr = wn + nt * 8 + (lane & 7);
                int cc = c0 + ((lane >> 3) & 1);
                ldsm2(bh[nt][0], bh[nt][1], BH(s) + swzB(rr, cc));
            }
            #pragma unroll
            for (int mt = 0; mt < 4; mt++)
                #pragma unroll
                for (int nt = 0; nt < 4; nt++)
                    mma16816(acc[mt][nt], ah[mt], bh[nt]);
        }
    }

    // ---------------- epilogue ----------------
    const int qr = lane >> 2;
    const int qc = (lane & 3) * 2;
    #pragma unroll
    for (int mt = 0; mt < 4; mt++) {
        #pragma unroll
        for (int nt = 0; nt < 4; nt++) {
            int ocl = wn + nt * 8 + qc;
            int o   = n0 + ocl;
            float sc0 = sSC[ocl],     sh0 = sSH[ocl];
            float sc1 = sSC[ocl + 1], sh1 = sSH[ocl + 1];
            #pragma unroll
            for (int half = 0; half < 2; half++) {
                int p  = p0 + wm + mt * 16 + qr + half * 8;
                float v0 = acc[mt][nt][half * 2 + 0] * sc0 + sh0;
                float v1 = acc[mt][nt][half * 2 + 1] * sc1 + sh1;
                if (EPI == 1 || EPI == 2) {
                    v0 = silu_f(v0);
                    v1 = silu_f(v1);
                }
                if (EPI == 1) {
                    *reinterpret_cast<uint32_t*>(&CoH[(size_t)p * 256 + o]) =
                        pack2h(__float2half_rn(v0), __float2half_rn(v1));
                } else if (EPI == 2) {
                    int n = p >> 14, hw = p & 16383;
                    Co[(((size_t)n * 256 + o)     << 14) + hw] = v0;
                    Co[(((size_t)n * 256 + o + 1) << 14) + hw] = v1;
                } else { // EPI 3
                    if (o < 256) {
                        *reinterpret_cast<uint32_t*>(&CoH[(size_t)p * 256 + o]) =
                            pack2h(__float2half_rn(v0), __float2half_rn(v1));
                    } else {
                        *reinterpret_cast<float2*>(&Co2[(size_t)p * OMSP + (o - 256)]) =
                            make_float2(v0, v1);
                    }
                }
            }
        }
    }
}

// ---------------------------------------------------------------------------
// DCNv4 sampling v5: warp = 1 pixel (4 groups x 8 lanes).
// Tap-param dedup: lane j of group g computes the 8 params (4 folded weights
// + 4 clamped row offsets) for tap j; the loop broadcasts them via shfl from
// lane g*8+k. Tap 8 computed by all lanes. OOB validity folded into zeroed
// weights; clamped addresses -> unconditional gathers (no branches).
// Identical arithmetic values and order as v4 -> bit-identical output.
// ---------------------------------------------------------------------------
__device__ __forceinline__ void tap_params(
    int k, const float* __restrict__ op, int h, int w,
    float W[4], int R[4])
{
    float ow = op[2 * k];
    float oh = op[2 * k + 1];
    float mk = op[18 + k];
    float lh = (float)(h + k / 3 - 1) + oh;
    float lw = (float)(w + k % 3 - 1) + ow;
    float fh = floorf(lh), fw = floorf(lw);
    int h0 = (int)fh, w0 = (int)fw;
    float dh = lh - fh, dw = lw - fw;
    float w00 = (1.f - dh) * (1.f - dw) * mk;
    float w01 = (1.f - dh) * dw * mk;
    float w10 = dh * (1.f - dw) * mk;
    float w11 = dh * dw * mk;
    bool hv0 = (unsigned)h0 < HSZ;
    bool hv1 = (unsigned)(h0 + 1) < HSZ;
    bool wv0 = (unsigned)w0 < WSZ;
    bool wv1 = (unsigned)(w0 + 1) < WSZ;
    W[0] = (hv0 && wv0) ? w00 : 0.f;
    W[1] = (hv0 && wv1) ? w01 : 0.f;
    W[2] = (hv1 && wv0) ? w10 : 0.f;
    W[3] = (hv1 && wv1) ? w11 : 0.f;
    int h0c = min(max(h0, 0), HSZ - 1);
    int h1c = min(max(h0 + 1, 0), HSZ - 1);
    int w0c = min(max(w0, 0), WSZ - 1);
    int w1c = min(max(w0 + 1, 0), WSZ - 1);
    R[0] = (h0c * WSZ + w0c) << 8;
    R[1] = (h0c * WSZ + w1c) << 8;
    R[2] = (h1c * WSZ + w0c) << 8;
    R[3] = (h1c * WSZ + w1c) << 8;
}

__global__ __launch_bounds__(256)
void dcn_sample(const fp16* __restrict__ v, const float* __restrict__ om,
                fp16* __restrict__ sh)
{
    const int p    = (blockIdx.x * 256 + threadIdx.x) >> 5;   // pixel
    const int lane = threadIdx.x & 31;
    const int g    = lane >> 3;
    const int j    = lane & 7;       // my tap (0..7)
    const int c8   = j * 8;          // channel base within group
    const int n  = p >> 14;
    const int hw = p & (HWSZ - 1);
    const int h = hw >> 7, w = hw & 127;

    const float* op = om + (size_t)p * OMSP + g * 27;
    const int cb = g * 64 + c8;
    const fp16* vb = v + ((size_t)n << 22) + cb;

    float Wm[4]; int Rm[4];          // params for my tap j
    float W8[4]; int R8[4];          // params for tap 8 (all lanes)
    tap_params(j, op, h, w, Wm, Rm);
    tap_params(8, op, h, w, W8, R8);

    float a[8] = {};

    #define ACC8(R0, R1, R2, R3, V0, V1, V2, V3) do { \
        uint4 q0 = *reinterpret_cast<const uint4*>(vb + (R0)); \
        uint4 q1 = *reinterpret_cast<const uint4*>(vb + (R1)); \
        uint4 q2 = *reinterpret_cast<const uint4*>(vb + (R2)); \
        uint4 q3 = *reinterpret_cast<const uint4*>(vb + (R3)); \
        const uint32_t* qq[4] = {&q0.x, &q1.x, &q2.x, &q3.x}; \
        const float ww[4] = {V0, V1, V2, V3}; \
        _Pragma("unroll") \
        for (int cor = 0; cor < 4; cor++) { \
            float wt = ww[cor]; \
            _Pragma("unroll") \
            for (int u = 0; u < 4; u++) { \
                float2 f = __half22float2( \
                    *reinterpret_cast<const __half2*>(&qq[cor][u])); \
                a[2*u]   += wt * f.x; \
                a[2*u+1] += wt * f.y; \
            } \
        } \
    } while (0)

    #pragma unroll
    for (int k = 0; k < 8; k++) {
        const int src = (g << 3) + k;
        float w0 = __shfl_sync(0xffffffffu, Wm[0], src);
        float w1 = __shfl_sync(0xffffffffu, Wm[1], src);
        float w2 = __shfl_sync(0xffffffffu, Wm[2], src);
        float w3 = __shfl_sync(0xffffffffu, Wm[3], src);
        int   r0 = __shfl_sync(0xffffffffu, Rm[0], src);
        int   r1 = __shfl_sync(0xffffffffu, Rm[1], src);
        int   r2 = __shfl_sync(0xffffffffu, Rm[2], src);
        int   r3 = __shfl_sync(0xffffffffu, Rm[3], src);
        ACC8(r0, r1, r2, r3, w0, w1, w2, w3);
    }
    // tap 8 (own registers, no shuffle)
    ACC8(R8[0], R8[1], R8[2], R8[3], W8[0], W8[1], W8[2], W8[3]);
    #undef ACC8

    uint4 out;
    out.x = pack2h(__float2half_rn(a[0]), __float2half_rn(a[1]));
    out.y = pack2h(__float2half_rn(a[2]), __float2half_rn(a[3]));
    out.z = pack2h(__float2half_rn(a[4]), __float2half_rn(a[5]));
    out.w = pack2h(__float2half_rn(a[6]), __float2half_rn(a[7]));
    *reinterpret_cast<uint4*>(&sh[(size_t)p * 256 + cb]) = out;
}

// ---------------------------------------------------------------------------
extern "C" void kernel_launch(void* const* d_in, const int* in_sizes, int n_in,
                              void* d_out, int out_size)
{
    const float* x        = (const float*)d_in[0];
    const float* conv_w   = (const float*)d_in[1];
    const float* bn1_g    = (const float*)d_in[2];
    const float* bn1_b    = (const float*)d_in[3];
    const float* bn1_m    = (const float*)d_in[4];
    const float* bn1_v    = (const float*)d_in[5];
    const float* value_w  = (const float*)d_in[6];
    const float* value_b  = (const float*)d_in[7];
    const float* offset_w = (const float*)d_in[8];
    const float* offset_b = (const float*)d_in[9];
    const float* out_w    = (const float*)d_in[10];
    const float* out_b    = (const float*)d_in[11];
    const float* bn2_g    = (const float*)d_in[12];
    const float* bn2_b    = (const float*)d_in[13];
    const float* bn2_m    = (const float*)d_in[14];
    const float* bn2_v    = (const float*)d_in[15];

    fp16 *xh, *yh, *sh, *vv, *whi;
    float *omp;
    cudaGetSymbolAddress((void**)&xh,  g_xh);
    cudaGetSymbolAddress((void**)&yh,  g_yh);
    cudaGetSymbolAddress((void**)&sh,  g_sh);
    cudaGetSymbolAddress((void**)&vv,  g_v);
    cudaGetSymbolAddress((void**)&whi, g_whi);
    cudaGetSymbolAddress((void**)&omp, g_om);

    const int smem = 3 * 32768;   // 96KB: 3 x (16KB A + 16KB B)
    cudaFuncSetAttribute(gemm_fp16<1>, cudaFuncAttributeMaxDynamicSharedMemorySize, smem);
    cudaFuncSetAttribute(gemm_fp16<2>, cudaFuncAttributeMaxDynamicSharedMemorySize, smem);
    cudaFuncSetAttribute(gemm_fp16<3>, cudaFuncAttributeMaxDynamicSharedMemorySize, smem);

    // merged prepass: x transpose+cvt (4096 blocks) + weight cvt (896 blocks)
    prep<<<4992, 256>>>(x, xh, conv_w, value_w, offset_w, out_w, whi);

    const int MT = MTOT / 128;   // 512 pixel tiles

    // 1) y = silu(bn1(x @ conv_w^T))           -> y fp16
    gemm_fp16<1><<<dim3(2, MT), 256, smem>>>(
        xh, whi, nullptr, nullptr,
        bn1_g, bn1_b, bn1_m, bn1_v, nullptr, nullptr, yh);
    // 2) fused: v (fp16) = y@value_w^T + b ; om (fp32) = y@offset_w^T + b
    gemm_fp16<3><<<dim3(3, MT), 256, smem>>>(
        yh, whi + 256*256, value_b, offset_b,
        nullptr, nullptr, nullptr, nullptr, nullptr, omp, vv);
    // 3) deformable sampling (fp16 v) -> s fp16
    dcn_sample<<<MTOT / 8, 256>>>(vv, omp, sh);
    // 4) out = silu(bn2(s @ out_w^T + out_b))  -> NCHW fp32
    gemm_fp16<2><<<dim3(2, MT), 256, smem>>>(
        sh, whi + 640*256, out_b, nullptr,
        bn2_g, bn2_b, bn2_m, bn2_v, (float*)d_out, nullptr, nullptr);
}